// round 2
// baseline (speedup 1.0000x reference)
#include <cuda_runtime.h>

#define Bb 2
#define Ss 4096
#define Dd 768
#define Hh 12
#define DHd 64
#define Ww 128
#define Gg 16
#define NBb 32
#define NSPLIT 8
#define NEGF (-1.0e9f)

// ---------------- scratch (device globals; no allocation) ----------------
__device__ float g_q [Bb*Hh*Ss*DHd];
__device__ float g_k [Bb*Hh*Ss*DHd];
__device__ float g_v [Bb*Hh*Ss*DHd];
__device__ float g_kg[Bb*Hh*Ss*DHd];
__device__ float g_vg[Bb*Hh*Ss*DHd];
__device__ float g_attn[Bb*Ss*Dd];
__device__ float g_qg[Bb*Hh*Gg*DHd];
__device__ float g_pm  [Bb*Hh*NSPLIT*Gg];
__device__ float g_pl  [Bb*Hh*NSPLIT*Gg];
__device__ float g_pacc[Bb*Hh*NSPLIT*Gg*DHd];

struct ProjW {
    const float* W[5];
    const float* bias[5];
};

// ---------------- fused input projection: 5 GEMMs [8192x768]x[768x768] ----------------
// grid (6, 64, 5), 256 threads. BM=BN=128, BK=16, 8x8 per thread.
__global__ __launch_bounds__(256) void proj_gemm(const float* __restrict__ A, ProjW pw)
{
    __shared__ float As[16 * 132];
    __shared__ float Bs[16 * 132];
    int z = blockIdx.z;
    const float* Wm   = pw.W[z];
    const float* bias = pw.bias[z];
    float* dst;
    switch (z) {
        case 0: dst = g_q;  break;
        case 1: dst = g_k;  break;
        case 2: dst = g_v;  break;
        case 3: dst = g_kg; break;
        default: dst = g_vg;
    }
    float scale = (z == 0) ? 0.125f : 1.0f;

    int tid = threadIdx.x;
    int m0 = blockIdx.y * 128, n0 = blockIdx.x * 128;
    int tx = tid & 15, ty = tid >> 4;

    float acc[8][8];
#pragma unroll
    for (int i = 0; i < 8; i++)
#pragma unroll
        for (int j = 0; j < 8; j++) acc[i][j] = 0.f;

    for (int k0 = 0; k0 < 768; k0 += 16) {
#pragma unroll
        for (int it = 0; it < 2; it++) {
            int idx = tid + it * 256;          // 512 float4 of A tile
            int r = idx >> 2, cv = idx & 3;
            float4 v4 = *(const float4*)(A + (long)(m0 + r) * 768 + k0 + cv * 4);
            As[(cv * 4 + 0) * 132 + r] = v4.x;
            As[(cv * 4 + 1) * 132 + r] = v4.y;
            As[(cv * 4 + 2) * 132 + r] = v4.z;
            As[(cv * 4 + 3) * 132 + r] = v4.w;
        }
#pragma unroll
        for (int it = 0; it < 2; it++) {
            int idx = tid + it * 256;          // 512 float4 of W tile
            int r = idx >> 5, cv = idx & 31;
            *(float4*)&Bs[r * 132 + cv * 4] =
                *(const float4*)(Wm + (long)(k0 + r) * 768 + n0 + cv * 4);
        }
        __syncthreads();
#pragma unroll
        for (int kk = 0; kk < 16; kk++) {
            float a[8], bb[8];
#pragma unroll
            for (int i = 0; i < 8; i++) a[i] = As[kk * 132 + ty * 8 + i];
#pragma unroll
            for (int j = 0; j < 8; j++) bb[j] = Bs[kk * 132 + tx * 8 + j];
#pragma unroll
            for (int i = 0; i < 8; i++)
#pragma unroll
                for (int j = 0; j < 8; j++) acc[i][j] += a[i] * bb[j];
        }
        __syncthreads();
    }
    // epilogue: scatter into [B,H,S,DH]; Q gets *scale after bias
#pragma unroll
    for (int i = 0; i < 8; i++) {
        int m = m0 + ty * 8 + i;
        int b = m >> 12, s = m & 4095;
#pragma unroll
        for (int j = 0; j < 8; j++) {
            int c = n0 + tx * 8 + j;
            int h = c >> 6, d = c & 63;
            float vv = (acc[i][j] + bias[c]) * scale;
            dst[(((long)(b * Hh + h)) * Ss + s) * DHd + d] = vv;
        }
    }
}

// ---------------- output projection: [8192x768]x[768x768] + bias -> d_out ----------------
__global__ __launch_bounds__(256) void out_gemm(const float* __restrict__ Wm,
                                                const float* __restrict__ bias,
                                                float* __restrict__ C)
{
    __shared__ float As[16 * 132];
    __shared__ float Bs[16 * 132];
    int tid = threadIdx.x;
    int m0 = blockIdx.y * 128, n0 = blockIdx.x * 128;
    int tx = tid & 15, ty = tid >> 4;
    const float* A = g_attn;

    float acc[8][8];
#pragma unroll
    for (int i = 0; i < 8; i++)
#pragma unroll
        for (int j = 0; j < 8; j++) acc[i][j] = 0.f;

    for (int k0 = 0; k0 < 768; k0 += 16) {
#pragma unroll
        for (int it = 0; it < 2; it++) {
            int idx = tid + it * 256;
            int r = idx >> 2, cv = idx & 3;
            float4 v4 = *(const float4*)(A + (long)(m0 + r) * 768 + k0 + cv * 4);
            As[(cv * 4 + 0) * 132 + r] = v4.x;
            As[(cv * 4 + 1) * 132 + r] = v4.y;
            As[(cv * 4 + 2) * 132 + r] = v4.z;
            As[(cv * 4 + 3) * 132 + r] = v4.w;
        }
#pragma unroll
        for (int it = 0; it < 2; it++) {
            int idx = tid + it * 256;
            int r = idx >> 5, cv = idx & 31;
            *(float4*)&Bs[r * 132 + cv * 4] =
                *(const float4*)(Wm + (long)(k0 + r) * 768 + n0 + cv * 4);
        }
        __syncthreads();
#pragma unroll
        for (int kk = 0; kk < 16; kk++) {
            float a[8], bb[8];
#pragma unroll
            for (int i = 0; i < 8; i++) a[i] = As[kk * 132 + ty * 8 + i];
#pragma unroll
            for (int j = 0; j < 8; j++) bb[j] = Bs[kk * 132 + tx * 8 + j];
#pragma unroll
            for (int i = 0; i < 8; i++)
#pragma unroll
                for (int j = 0; j < 8; j++) acc[i][j] += a[i] * bb[j];
        }
        __syncthreads();
    }
#pragma unroll
    for (int i = 0; i < 8; i++) {
        int m = m0 + ty * 8 + i;
#pragma unroll
        for (int j = 0; j < 8; j++) {
            int c = n0 + tx * 8 + j;
            C[(long)m * 768 + c] = acc[i][j] + bias[c];
        }
    }
}

// ---------------- local banded attention + global key-columns ----------------
// grid (NB, H, B), 256 threads, dynamic smem.
// smem layout (floats): Qst[64][132] | Kts[64][132] | Vs[128][68] | Ps[128][129]
//                       | rowm[128] | rowl[128] | rowf[128] | kok[128]
__global__ __launch_bounds__(256) void local_attn(const int* __restrict__ mask)
{
    extern __shared__ float sm[];
    float* Qst  = sm;                    // [64][132] transposed Q
    float* Kts  = Qst + 64 * 132;        // [64][132] transposed K chunk
    float* Vs   = Kts + 64 * 132;        // [128][68] V chunk
    float* Ps   = Vs + 128 * 68;         // [128][129] scores/probs
    float* rowm = Ps + 128 * 129;
    float* rowl = rowm + 128;
    float* rowf = rowl + 128;
    float* kok  = rowf + 128;

    int n = blockIdx.x, h = blockIdx.y, b = blockIdx.z;
    int tid = threadIdx.x;
    const float* qb = g_q + (((long)(b * Hh + h)) * Ss + n * Ww) * DHd;
    const float* kb = g_k + ((long)(b * Hh + h)) * Ss * DHd;
    const float* vb = g_v + ((long)(b * Hh + h)) * Ss * DHd;
    const int* mk = mask + b * Ss;

    // load Q tile transposed: Qst[d][i]
#pragma unroll
    for (int it = 0; it < 8; it++) {
        int idx = tid + it * 256;        // 2048 float4
        int r = idx >> 4, cv = idx & 15;
        float4 v4 = *(const float4*)(qb + r * 64 + cv * 4);
        Qst[(cv * 4 + 0) * 132 + r] = v4.x;
        Qst[(cv * 4 + 1) * 132 + r] = v4.y;
        Qst[(cv * 4 + 2) * 132 + r] = v4.z;
        Qst[(cv * 4 + 3) * 132 + r] = v4.w;
    }
    if (tid < 128) { rowm[tid] = -3.0e38f; rowl[tid] = 0.f; }

    float oacc[8][4];
#pragma unroll
    for (int i = 0; i < 8; i++)
#pragma unroll
        for (int j = 0; j < 4; j++) oacc[i][j] = 0.f;

    int tx = tid & 15, ty = tid >> 4;
    __syncthreads();

    for (int c = 0; c < 4; c++) {
        int cw = (c == 3) ? 16 : 128;
        int p0 = (n - 1) * Ww + c * Ww;

        // key-only validity flags
        if (tid < 128) {
            bool ok;
            if (c == 3) ok = (tid < Gg) && (mk[tid] > 0);
            else { int p = p0 + tid; ok = (p >= Gg) && (p < Ss) && (mk[p] > 0); }
            kok[tid] = ok ? 1.f : 0.f;
        }
        // load K (transposed) + V chunk
#pragma unroll
        for (int it = 0; it < 8; it++) {
            int idx = tid + it * 256;
            int j = idx >> 4, cv = idx & 15;
            int p = (c == 3) ? j : (p0 + j);
            bool inr = (c == 3) ? (j < Gg) : (p >= 0 && p < Ss);
            float4 kv = make_float4(0.f, 0.f, 0.f, 0.f);
            float4 vv = make_float4(0.f, 0.f, 0.f, 0.f);
            if (inr) {
                kv = *(const float4*)(kb + (long)p * 64 + cv * 4);
                vv = *(const float4*)(vb + (long)p * 64 + cv * 4);
            }
            Kts[(cv * 4 + 0) * 132 + j] = kv.x;
            Kts[(cv * 4 + 1) * 132 + j] = kv.y;
            Kts[(cv * 4 + 2) * 132 + j] = kv.z;
            Kts[(cv * 4 + 3) * 132 + j] = kv.w;
            *(float4*)&Vs[j * 68 + cv * 4] = vv;
        }
        __syncthreads();

        // S = Q.K^T : thread handles rows ty*8+i, cols tx + 16*j
        float sc[8][8];
#pragma unroll
        for (int i = 0; i < 8; i++)
#pragma unroll
            for (int j = 0; j < 8; j++) sc[i][j] = 0.f;
#pragma unroll 8
        for (int d = 0; d < 64; d++) {
            float a[8], bb2[8];
#pragma unroll
            for (int i = 0; i < 8; i++) a[i] = Qst[d * 132 + ty * 8 + i];
#pragma unroll
            for (int j = 0; j < 8; j++) bb2[j] = Kts[d * 132 + tx + 16 * j];
#pragma unroll
            for (int i = 0; i < 8; i++)
#pragma unroll
                for (int j = 0; j < 8; j++) sc[i][j] += a[i] * bb2[j];
        }
        // mask + store scores
#pragma unroll
        for (int i = 0; i < 8; i++) {
            int row = ty * 8 + i;
            int qpos = n * Ww + row;
#pragma unroll
            for (int j = 0; j < 8; j++) {
                int col = tx + 16 * j;
                bool ok = kok[col] > 0.f;
                if (c != 3) {
                    int rel = (p0 + col) - qpos;
                    ok = ok && (rel <= Ww) && (rel >= -Ww);
                }
                Ps[row * 129 + col] = ok ? sc[i][j] : NEGF;
            }
        }
        __syncthreads();

        // online softmax per row
        if (tid < 128) {
            float mx = rowm[tid];
            float cm = -3.0e38f;
            for (int j2 = 0; j2 < cw; j2++) cm = fmaxf(cm, Ps[tid * 129 + j2]);
            float nm = fmaxf(mx, cm);
            float f = __expf(mx - nm);
            float ls = 0.f;
            for (int j2 = 0; j2 < cw; j2++) {
                float pv = __expf(Ps[tid * 129 + j2] - nm);
                Ps[tid * 129 + j2] = pv;
                ls += pv;
            }
            rowl[tid] = rowl[tid] * f + ls;
            rowm[tid] = nm;
            rowf[tid] = f;
        }
        __syncthreads();

        // O = O*f + P.V : thread rows ty*8+i, cols tx*4+j
        float fr[8];
#pragma unroll
        for (int i = 0; i < 8; i++) fr[i] = rowf[ty * 8 + i];
#pragma unroll
        for (int i = 0; i < 8; i++)
#pragma unroll
            for (int j = 0; j < 4; j++) oacc[i][j] *= fr[i];
        for (int kk = 0; kk < cw; kk++) {
            float a[8];
#pragma unroll
            for (int i = 0; i < 8; i++) a[i] = Ps[(ty * 8 + i) * 129 + kk];
            float bb2[4];
#pragma unroll
            for (int j = 0; j < 4; j++) bb2[j] = Vs[kk * 68 + tx * 4 + j];
#pragma unroll
            for (int i = 0; i < 8; i++)
#pragma unroll
                for (int j = 0; j < 4; j++) oacc[i][j] += a[i] * bb2[j];
        }
        __syncthreads();
    }
    // write merged layout [B,S,D]
#pragma unroll
    for (int i = 0; i < 8; i++) {
        int row = ty * 8 + i;
        float inv = 1.0f / rowl[row];
        float4 o4;
        o4.x = oacc[i][0] * inv;
        o4.y = oacc[i][1] * inv;
        o4.z = oacc[i][2] * inv;
        o4.w = oacc[i][3] * inv;
        *(float4*)(g_attn + ((long)b * Ss + n * Ww + row) * Dd + h * DHd + tx * 4) = o4;
    }
}

// ---------------- qg projection: 32 global query rows ----------------
__global__ __launch_bounds__(256) void qg_proj(const float* __restrict__ x,
                                               const float* __restrict__ Wqg,
                                               const float* __restrict__ bqg)
{
    __shared__ float xr[768];
    int bg = blockIdx.x;
    int b = bg >> 4, g = bg & 15;
    int tid = threadIdx.x;
    for (int i = tid; i < 768; i += 256) xr[i] = x[((long)b * Ss + g) * Dd + i];
    __syncthreads();
    float acc0 = 0.f, acc1 = 0.f, acc2 = 0.f;
    for (int k = 0; k < 768; k++) {
        float xv = xr[k];
        const float* wr = Wqg + (long)k * 768;
        acc0 += xv * wr[tid];
        acc1 += xv * wr[tid + 256];
        acc2 += xv * wr[tid + 512];
    }
    float accs[3] = {acc0, acc1, acc2};
#pragma unroll
    for (int t2 = 0; t2 < 3; t2++) {
        int cc = tid + t2 * 256;
        float vv = (accs[t2] + bqg[cc]) * 0.125f;
        g_qg[(((long)b * Hh + (cc >> 6)) * Gg + g) * DHd + (cc & 63)] = vv;
    }
}

// ---------------- global-row attention, split-K partials ----------------
// grid (NSPLIT, H, B), 256 threads, dynamic smem.
__global__ __launch_bounds__(256) void gattn_part(const int* __restrict__ mask)
{
    extern __shared__ float sm[];
    float* Qgs  = sm;                  // [16][68]
    float* Kts  = Qgs + 16 * 68;       // [64][132]
    float* Vs   = Kts + 64 * 132;      // [128][68]
    float* Ps   = Vs + 128 * 68;       // [16][129]
    float* rowm = Ps + 16 * 129;
    float* rowl = rowm + 16;
    float* rowf = rowl + 16;

    int si = blockIdx.x, h = blockIdx.y, b = blockIdx.z;
    int tid = threadIdx.x;
    const float* kgb = g_kg + ((long)(b * Hh + h)) * Ss * DHd;
    const float* vgb = g_vg + ((long)(b * Hh + h)) * Ss * DHd;
    const int* mk = mask + b * Ss;

    for (int i = tid; i < 16 * 64; i += 256) {
        int r = i >> 6, d = i & 63;
        Qgs[r * 68 + d] = g_qg[(((long)b * Hh + h) * Gg + r) * DHd + d];
    }
    if (tid < 16) { rowm[tid] = -3.0e38f; rowl[tid] = 0.f; }

    float oacc[4] = {0.f, 0.f, 0.f, 0.f};
    int r = tid >> 4, cg = tid & 15;
    __syncthreads();

    for (int c = 0; c < 4; c++) {
        int p0 = si * 512 + c * 128;
#pragma unroll
        for (int it = 0; it < 8; it++) {
            int idx = tid + it * 256;
            int j = idx >> 4, cv = idx & 15;
            int p = p0 + j;
            float4 kv = *(const float4*)(kgb + (long)p * 64 + cv * 4);
            float4 vv = *(const float4*)(vgb + (long)p * 64 + cv * 4);
            Kts[(cv * 4 + 0) * 132 + j] = kv.x;
            Kts[(cv * 4 + 1) * 132 + j] = kv.y;
            Kts[(cv * 4 + 2) * 132 + j] = kv.z;
            Kts[(cv * 4 + 3) * 132 + j] = kv.w;
            *(float4*)&Vs[j * 68 + cv * 4] = vv;
        }
        __syncthreads();

        // scores: row r, cols cg*8 .. +7
        float sc8[8] = {0.f, 0.f, 0.f, 0.f, 0.f, 0.f, 0.f, 0.f};
#pragma unroll 8
        for (int d = 0; d < 64; d++) {
            float a = Qgs[r * 68 + d];
#pragma unroll
            for (int j = 0; j < 8; j++) sc8[j] += a * Kts[d * 132 + cg * 8 + j];
        }
#pragma unroll
        for (int j = 0; j < 8; j++) {
            int p = p0 + cg * 8 + j;
            Ps[r * 129 + cg * 8 + j] = (mk[p] > 0) ? sc8[j] : NEGF;
        }
        __syncthreads();

        if (tid < 16) {
            float mx = rowm[tid], cm = -3.0e38f;
            for (int j2 = 0; j2 < 128; j2++) cm = fmaxf(cm, Ps[tid * 129 + j2]);
            float nm = fmaxf(mx, cm);
            float f = __expf(mx - nm);
            float ls = 0.f;
            for (int j2 = 0; j2 < 128; j2++) {
                float pv = __expf(Ps[tid * 129 + j2] - nm);
                Ps[tid * 129 + j2] = pv;
                ls += pv;
            }
            rowl[tid] = rowl[tid] * f + ls;
            rowm[tid] = nm;
            rowf[tid] = f;
        }
        __syncthreads();

        float f = rowf[r];
#pragma unroll
        for (int j = 0; j < 4; j++) oacc[j] *= f;
        for (int kk = 0; kk < 128; kk++) {
            float a = Ps[r * 129 + kk];
#pragma unroll
            for (int j = 0; j < 4; j++) oacc[j] += a * Vs[kk * 68 + cg * 4 + j];
        }
        __syncthreads();
    }
    int part = (b * Hh + h) * NSPLIT + si;
#pragma unroll
    for (int j = 0; j < 4; j++)
        g_pacc[((long)part * 16 + r) * 64 + cg * 4 + j] = oacc[j];
    if (cg == 0) {
        g_pm[part * 16 + r] = rowm[r];
        g_pl[part * 16 + r] = rowl[r];
    }
}

// ---------------- combine split partials, overwrite rows s < G ----------------
__global__ __launch_bounds__(64) void gattn_combine()
{
    int bh = blockIdx.x;
    int b = bh / Hh, h = bh % Hh;
    int d = threadIdx.x;  // 64
    for (int r = 0; r < Gg; r++) {
        float M = -3.0e38f;
        for (int si = 0; si < NSPLIT; si++)
            M = fmaxf(M, g_pm[((b * Hh + h) * NSPLIT + si) * 16 + r]);
        float L = 0.f, a = 0.f;
        for (int si = 0; si < NSPLIT; si++) {
            int part = (b * Hh + h) * NSPLIT + si;
            float w = __expf(g_pm[part * 16 + r] - M);
            L += w * g_pl[part * 16 + r];
            a += w * g_pacc[((long)part * 16 + r) * 64 + d];
        }
        g_attn[((long)b * Ss + r) * Dd + h * DHd + d] = a / L;
    }
}

// ---------------- launch ----------------
extern "C" void kernel_launch(void* const* d_in, const int* in_sizes, int n_in,
                              void* d_out, int out_size)
{
    (void)in_sizes; (void)n_in; (void)out_size;
    const float* x    = (const float*)d_in[0];
    const int*   mask = (const int*)d_in[1];
    ProjW pw;
    pw.W[0] = (const float*)d_in[2];  pw.bias[0] = (const float*)d_in[3];   // Wq, bq
    pw.W[1] = (const float*)d_in[4];  pw.bias[1] = (const float*)d_in[5];   // Wk, bk
    pw.W[2] = (const float*)d_in[6];  pw.bias[2] = (const float*)d_in[7];   // Wv, bv
    pw.W[3] = (const float*)d_in[10]; pw.bias[3] = (const float*)d_in[11];  // Wkg, bkg
    pw.W[4] = (const float*)d_in[12]; pw.bias[4] = (const float*)d_in[13];  // Wvg, bvg
    const float* Wqg = (const float*)d_in[8];
    const float* bqg = (const float*)d_in[9];
    const float* Wo  = (const float*)d_in[14];
    const float* bo  = (const float*)d_in[15];
    float* out = (float*)d_out;

    int lsm = (64 * 132 + 64 * 132 + 128 * 68 + 128 * 129 + 3 * 128 + 128) * 4;
    cudaFuncSetAttribute(local_attn, cudaFuncAttributeMaxDynamicSharedMemorySize, lsm);
    int gsm = (16 * 68 + 64 * 132 + 128 * 68 + 16 * 129 + 3 * 16) * 4;
    cudaFuncSetAttribute(gattn_part, cudaFuncAttributeMaxDynamicSharedMemorySize, gsm);

    proj_gemm<<<dim3(6, 64, 5), 256>>>(x, pw);
    local_attn<<<dim3(NBb, Hh, Bb), 256, lsm>>>(mask);
    qg_proj<<<Bb * Gg, 256>>>(x, Wqg, bqg);
    gattn_part<<<dim3(NSPLIT, Hh, Bb), 256, gsm>>>(mask);
    gattn_combine<<<Bb * Hh, 64>>>();
    out_gemm<<<dim3(6, 64), 256>>>(Wo, bo, out);
}

// round 5
// speedup vs baseline: 1.5921x; 1.5921x over previous
#include <cuda_runtime.h>
#include <cuda_bf16.h>
#include <cstdint>

#define Bb 2
#define Ss 4096
#define Dd 768
#define Hh 12
#define DHd 64
#define Ww 128
#define Gg 16
#define NBb 32
#define NSPLIT 8
#define NEGF (-1.0e9f)

// ---------------- scratch (device globals; no allocation) ----------------
__device__ float g_q [Bb*Hh*Ss*DHd];
__device__ float g_k [Bb*Hh*Ss*DHd];
__device__ float g_v [Bb*Hh*Ss*DHd];
__device__ float g_kg[Bb*Hh*Ss*DHd];
__device__ float g_vg[Bb*Hh*Ss*DHd];
__device__ float g_attn[Bb*Ss*Dd];
__device__ float g_qg[Bb*Hh*Gg*DHd];
__device__ float g_pm  [Bb*Hh*NSPLIT*Gg];
__device__ float g_pl  [Bb*Hh*NSPLIT*Gg];
__device__ float g_pacc[Bb*Hh*NSPLIT*Gg*DHd];

// bf16 split operands
__device__ __nv_bfloat16 g_xhi[Bb*Ss*Dd];
__device__ __nv_bfloat16 g_xlo[Bb*Ss*Dd];
__device__ __nv_bfloat16 g_ahi[Bb*Ss*Dd];
__device__ __nv_bfloat16 g_alo[Bb*Ss*Dd];
__device__ __nv_bfloat16 g_wthi[6*Dd*Dd];   // transposed [N][K], 6 weights
__device__ __nv_bfloat16 g_wtlo[6*Dd*Dd];

struct W6   { const float* w[6]; };
struct Bia5 { const float* b[5]; };

// ================= warp-MMA helpers (sm_80+ PTX, compiles for compute_100) =====
#define SWZ(o) ((o) ^ (((o) >> 3) & 0x70))

__device__ __forceinline__ uint32_t smem_u32(const void* p) {
    uint32_t a;
    asm("{ .reg .u64 t; cvta.to.shared.u64 t, %1; cvt.u32.u64 %0, t; }" : "=r"(a) : "l"(p));
    return a;
}
__device__ __forceinline__ void ldsm4(uint32_t* r, uint32_t addr) {
    asm volatile("ldmatrix.sync.aligned.m8n8.x4.shared.b16 {%0,%1,%2,%3}, [%4];"
                 : "=r"(r[0]), "=r"(r[1]), "=r"(r[2]), "=r"(r[3]) : "r"(addr));
}
__device__ __forceinline__ void mma16816(float* d, const uint32_t* a, uint32_t b0, uint32_t b1) {
    asm volatile(
        "mma.sync.aligned.m16n8k16.row.col.f32.bf16.bf16.f32 "
        "{%0,%1,%2,%3}, {%4,%5,%6,%7}, {%8,%9}, {%0,%1,%2,%3};"
        : "+f"(d[0]), "+f"(d[1]), "+f"(d[2]), "+f"(d[3])
        : "r"(a[0]), "r"(a[1]), "r"(a[2]), "r"(a[3]), "r"(b0), "r"(b1));
}

// ================= prep kernels =================
__global__ __launch_bounds__(256) void to_bf16_split(const float* __restrict__ in,
                                                     __nv_bfloat16* __restrict__ hi,
                                                     __nv_bfloat16* __restrict__ lo, int n4)
{
    int i = blockIdx.x * 256 + threadIdx.x;
    if (i >= n4) return;
    float4 v = ((const float4*)in)[i];
    float vv[4] = {v.x, v.y, v.z, v.w};
    union { __nv_bfloat16 h[4]; uint2 u; } uh, ul;
#pragma unroll
    for (int j = 0; j < 4; j++) {
        __nv_bfloat16 h = __float2bfloat16(vv[j]);
        uh.h[j] = h;
        ul.h[j] = __float2bfloat16(vv[j] - __bfloat162float(h));
    }
    *(uint2*)(hi + (size_t)i * 4) = uh.u;
    *(uint2*)(lo + (size_t)i * 4) = ul.u;
}

// transpose W [K=768][N=768] -> Wt [N][K], bf16 hi/lo. grid (24,24,6), block (32,8)
__global__ __launch_bounds__(256) void prep_w(W6 ws)
{
    __shared__ float t[32][33];
    int z = blockIdx.z;
    const float* W = ws.w[z];
    __nv_bfloat16* oh = g_wthi + (size_t)z * Dd * Dd;
    __nv_bfloat16* ol = g_wtlo + (size_t)z * Dd * Dd;
    int k0 = blockIdx.x * 32, n0 = blockIdx.y * 32;
    int tx = threadIdx.x, ty = threadIdx.y;
#pragma unroll
    for (int r = 0; r < 4; r++)
        t[ty + r * 8][tx] = W[(size_t)(k0 + ty + r * 8) * Dd + n0 + tx];
    __syncthreads();
#pragma unroll
    for (int r = 0; r < 4; r++) {
        float v = t[tx][ty + r * 8];
        __nv_bfloat16 h = __float2bfloat16(v);
        size_t o = (size_t)(n0 + ty + r * 8) * Dd + k0 + tx;
        oh[o] = h;
        ol[o] = __float2bfloat16(v - __bfloat162float(h));
    }
}

// ================= bf16 mma.sync GEMM: C[128x128] = A[128x768] * Wt^T ============
// smem 64KB: Ahi[128][64], Alo, Bhi, Blo (bf16, SW128 swizzled 16B units)
#define GEMM_SMEM 65536

template<bool OUT>
__global__ __launch_bounds__(256)
void mma_gemm(const __nv_bfloat16* __restrict__ Ahi, const __nv_bfloat16* __restrict__ Alo,
              Bia5 bp, const float* __restrict__ bias_o, float* __restrict__ outp)
{
    extern __shared__ char smem[];
    uint32_t sb = smem_u32(smem);
    int tid = threadIdx.x;
    int wid = tid >> 5, lane = tid & 31;
    int wm = wid >> 2, wn = wid & 3;          // warp tile: rows wm*64, cols wn*32
    int z = OUT ? 5 : blockIdx.z;
    int n0 = blockIdx.x * 128, m0 = blockIdx.y * 128;

    const __nv_bfloat16* Bhi = g_wthi + (size_t)z * Dd * Dd;
    const __nv_bfloat16* Blo = g_wtlo + (size_t)z * Dd * Dd;
    const __nv_bfloat16* srcs[4] = {
        Ahi + (size_t)m0 * Dd, Alo + (size_t)m0 * Dd,
        Bhi + (size_t)n0 * Dd, Blo + (size_t)n0 * Dd };

    float acc[4][4][4];
#pragma unroll
    for (int i = 0; i < 4; i++)
#pragma unroll
        for (int j = 0; j < 4; j++)
#pragma unroll
            for (int q = 0; q < 4; q++) acc[i][j][q] = 0.f;

    // per-lane ldmatrix address components
    int alr = lane & 15, alc = lane >> 4, arx = alr & 7;      // A: row-in-16, chunk half
    uint32_t aoff[4];
#pragma unroll
    for (int mi = 0; mi < 4; mi++) aoff[mi] = (wm * 64 + mi * 16 + alr) * 128;
    int blr = (lane & 7) + ((lane >> 4) & 1) * 8;             // B: n row
    int blc = (lane >> 3) & 1, brx = lane & 7;
    uint32_t boff[2];
#pragma unroll
    for (int ni = 0; ni < 2; ni++) boff[ni] = (wn * 32 + ni * 16 + blr) * 128;

    uint32_t sA = sb, sAl = sb + 16384, sB = sb + 32768, sBl = sb + 49152;

    for (int c = 0; c < 12; c++) {
        int k0 = c * 64;
        // load 4 tiles: 128 rows x 8 x 16B each
#pragma unroll
        for (int t = 0; t < 4; t++) {
            const __nv_bfloat16* sp = srcs[t] + k0;
            char* tp = smem + t * 16384;
#pragma unroll
            for (int it = 0; it < 4; it++) {
                int idx = tid + it * 256;
                int row = idx >> 3, cu = idx & 7;
                uint4 v = *(const uint4*)(sp + (size_t)row * Dd + cu * 8);
                *(uint4*)(tp + SWZ(row * 128 + cu * 16)) = v;
            }
        }
        __syncthreads();
#pragma unroll
        for (int ks = 0; ks < 4; ks++) {
            uint32_t ah[4][4], al[4][4], bh[2][4], bl[2][4];
            uint32_t ac = ((uint32_t)(ks * 2 + alc) ^ arx) << 4;
            uint32_t bc = ((uint32_t)(ks * 2 + blc) ^ brx) << 4;
#pragma unroll
            for (int mi = 0; mi < 4; mi++) {
                ldsm4(ah[mi], sA  + aoff[mi] + ac);
                ldsm4(al[mi], sAl + aoff[mi] + ac);
            }
#pragma unroll
            for (int ni = 0; ni < 2; ni++) {
                ldsm4(bh[ni], sB  + boff[ni] + bc);
                ldsm4(bl[ni], sBl + boff[ni] + bc);
            }
#pragma unroll
            for (int mi = 0; mi < 4; mi++)
#pragma unroll
                for (int nj = 0; nj < 4; nj++) {
                    int ni = nj >> 1, hf = (nj & 1) * 2;
                    mma16816(acc[mi][nj], ah[mi], bh[ni][hf], bh[ni][hf + 1]);
                    mma16816(acc[mi][nj], al[mi], bh[ni][hf], bh[ni][hf + 1]);
                    mma16816(acc[mi][nj], ah[mi], bl[ni][hf], bl[ni][hf + 1]);
                }
        }
        __syncthreads();
    }

    // epilogue: d0,d1 -> (row g, col t*2..), d2,d3 -> (row g+8)
    int g = lane >> 2, t4 = lane & 3;
#pragma unroll
    for (int mi = 0; mi < 4; mi++) {
        int r0 = m0 + wm * 64 + mi * 16 + g;
#pragma unroll
        for (int nj = 0; nj < 4; nj++) {
            int cc = n0 + wn * 32 + nj * 8 + t4 * 2;
#pragma unroll
            for (int half = 0; half < 2; half++) {
                int m = r0 + half * 8;
                float v0 = acc[mi][nj][half * 2 + 0];
                float v1 = acc[mi][nj][half * 2 + 1];
                if (OUT) {
                    float2 o = make_float2(v0 + bias_o[cc], v1 + bias_o[cc + 1]);
                    *(float2*)(outp + (size_t)m * Dd + cc) = o;
                } else {
                    const float* bias = bp.b[z];
                    float scale = (z == 0) ? 0.125f : 1.0f;
                    float* dstz;
                    switch (z) {
                        case 0: dstz = g_q;  break;
                        case 1: dstz = g_k;  break;
                        case 2: dstz = g_v;  break;
                        case 3: dstz = g_kg; break;
                        default: dstz = g_vg;
                    }
                    int b = m >> 12, s = m & 4095;
                    int h = cc >> 6, d0 = cc & 63;
                    float2 o = make_float2((v0 + bias[cc]) * scale, (v1 + bias[cc + 1]) * scale);
                    *(float2*)(dstz + (((size_t)(b * Hh + h)) * Ss + s) * DHd + d0) = o;
                }
            }
        }
    }
}

// ---------------- local banded attention + global key-columns (R2, passing) ------
__global__ __launch_bounds__(256) void local_attn(const int* __restrict__ mask)
{
    extern __shared__ float sm[];
    float* Qst  = sm;
    float* Kts  = Qst + 64 * 132;
    float* Vs   = Kts + 64 * 132;
    float* Ps   = Vs + 128 * 68;
    float* rowm = Ps + 128 * 129;
    float* rowl = rowm + 128;
    float* rowf = rowl + 128;
    float* kok  = rowf + 128;

    int n = blockIdx.x, h = blockIdx.y, b = blockIdx.z;
    int tid = threadIdx.x;
    const float* qb = g_q + (((long)(b * Hh + h)) * Ss + n * Ww) * DHd;
    const float* kb = g_k + ((long)(b * Hh + h)) * Ss * DHd;
    const float* vb = g_v + ((long)(b * Hh + h)) * Ss * DHd;
    const int* mk = mask + b * Ss;

#pragma unroll
    for (int it = 0; it < 8; it++) {
        int idx = tid + it * 256;
        int r = idx >> 4, cv = idx & 15;
        float4 v4 = *(const float4*)(qb + r * 64 + cv * 4);
        Qst[(cv * 4 + 0) * 132 + r] = v4.x;
        Qst[(cv * 4 + 1) * 132 + r] = v4.y;
        Qst[(cv * 4 + 2) * 132 + r] = v4.z;
        Qst[(cv * 4 + 3) * 132 + r] = v4.w;
    }
    if (tid < 128) { rowm[tid] = -3.0e38f; rowl[tid] = 0.f; }

    float oacc[8][4];
#pragma unroll
    for (int i = 0; i < 8; i++)
#pragma unroll
        for (int j = 0; j < 4; j++) oacc[i][j] = 0.f;

    int tx = tid & 15, ty = tid >> 4;
    __syncthreads();

    for (int c = 0; c < 4; c++) {
        int cw = (c == 3) ? 16 : 128;
        int p0 = (n - 1) * Ww + c * Ww;

        if (tid < 128) {
            bool ok;
            if (c == 3) ok = (tid < Gg) && (mk[tid] > 0);
            else { int p = p0 + tid; ok = (p >= Gg) && (p < Ss) && (mk[p] > 0); }
            kok[tid] = ok ? 1.f : 0.f;
        }
#pragma unroll
        for (int it = 0; it < 8; it++) {
            int idx = tid + it * 256;
            int j = idx >> 4, cv = idx & 15;
            int p = (c == 3) ? j : (p0 + j);
            bool inr = (c == 3) ? (j < Gg) : (p >= 0 && p < Ss);
            float4 kv = make_float4(0.f, 0.f, 0.f, 0.f);
            float4 vv = make_float4(0.f, 0.f, 0.f, 0.f);
            if (inr) {
                kv = *(const float4*)(kb + (long)p * 64 + cv * 4);
                vv = *(const float4*)(vb + (long)p * 64 + cv * 4);
            }
            Kts[(cv * 4 + 0) * 132 + j] = kv.x;
            Kts[(cv * 4 + 1) * 132 + j] = kv.y;
            Kts[(cv * 4 + 2) * 132 + j] = kv.z;
            Kts[(cv * 4 + 3) * 132 + j] = kv.w;
            *(float4*)&Vs[j * 68 + cv * 4] = vv;
        }
        __syncthreads();

        float sc[8][8];
#pragma unroll
        for (int i = 0; i < 8; i++)
#pragma unroll
            for (int j = 0; j < 8; j++) sc[i][j] = 0.f;
#pragma unroll 8
        for (int d = 0; d < 64; d++) {
            float a[8], bb2[8];
#pragma unroll
            for (int i = 0; i < 8; i++) a[i] = Qst[d * 132 + ty * 8 + i];
#pragma unroll
            for (int j = 0; j < 8; j++) bb2[j] = Kts[d * 132 + tx + 16 * j];
#pragma unroll
            for (int i = 0; i < 8; i++)
#pragma unroll
                for (int j = 0; j < 8; j++) sc[i][j] += a[i] * bb2[j];
        }
#pragma unroll
        for (int i = 0; i < 8; i++) {
            int row = ty * 8 + i;
            int qpos = n * Ww + row;
#pragma unroll
            for (int j = 0; j < 8; j++) {
                int col = tx + 16 * j;
                bool ok = kok[col] > 0.f;
                if (c != 3) {
                    int rel = (p0 + col) - qpos;
                    ok = ok && (rel <= Ww) && (rel >= -Ww);
                }
                Ps[row * 129 + col] = ok ? sc[i][j] : NEGF;
            }
        }
        __syncthreads();

        if (tid < 128) {
            float mx = rowm[tid];
            float cm = -3.0e38f;
            for (int j2 = 0; j2 < cw; j2++) cm = fmaxf(cm, Ps[tid * 129 + j2]);
            float nm = fmaxf(mx, cm);
            float f = __expf(mx - nm);
            float ls = 0.f;
            for (int j2 = 0; j2 < cw; j2++) {
                float pv = __expf(Ps[tid * 129 + j2] - nm);
                Ps[tid * 129 + j2] = pv;
                ls += pv;
            }
            rowl[tid] = rowl[tid] * f + ls;
            rowm[tid] = nm;
            rowf[tid] = f;
        }
        __syncthreads();

        float fr[8];
#pragma unroll
        for (int i = 0; i < 8; i++) fr[i] = rowf[ty * 8 + i];
#pragma unroll
        for (int i = 0; i < 8; i++)
#pragma unroll
            for (int j = 0; j < 4; j++) oacc[i][j] *= fr[i];
        for (int kk = 0; kk < cw; kk++) {
            float a[8];
#pragma unroll
            for (int i = 0; i < 8; i++) a[i] = Ps[(ty * 8 + i) * 129 + kk];
            float bb2[4];
#pragma unroll
            for (int j = 0; j < 4; j++) bb2[j] = Vs[kk * 68 + tx * 4 + j];
#pragma unroll
            for (int i = 0; i < 8; i++)
#pragma unroll
                for (int j = 0; j < 4; j++) oacc[i][j] += a[i] * bb2[j];
        }
        __syncthreads();
    }
#pragma unroll
    for (int i = 0; i < 8; i++) {
        int row = ty * 8 + i;
        float inv = 1.0f / rowl[row];
        float4 o4;
        o4.x = oacc[i][0] * inv;
        o4.y = oacc[i][1] * inv;
        o4.z = oacc[i][2] * inv;
        o4.w = oacc[i][3] * inv;
        *(float4*)(g_attn + ((long)b * Ss + n * Ww + row) * Dd + h * DHd + tx * 4) = o4;
    }
}

// ---------------- qg projection ----------------
__global__ __launch_bounds__(256) void qg_proj(const float* __restrict__ x,
                                               const float* __restrict__ Wqg,
                                               const float* __restrict__ bqg)
{
    __shared__ float xr[768];
    int bg = blockIdx.x;
    int b = bg >> 4, g = bg & 15;
    int tid = threadIdx.x;
    for (int i = tid; i < 768; i += 256) xr[i] = x[((long)b * Ss + g) * Dd + i];
    __syncthreads();
    float acc0 = 0.f, acc1 = 0.f, acc2 = 0.f;
    for (int k = 0; k < 768; k++) {
        float xv = xr[k];
        const float* wr = Wqg + (long)k * 768;
        acc0 += xv * wr[tid];
        acc1 += xv * wr[tid + 256];
        acc2 += xv * wr[tid + 512];
    }
    float accs[3] = {acc0, acc1, acc2};
#pragma unroll
    for (int t2 = 0; t2 < 3; t2++) {
        int cc = tid + t2 * 256;
        float vv = (accs[t2] + bqg[cc]) * 0.125f;
        g_qg[(((long)b * Hh + (cc >> 6)) * Gg + g) * DHd + (cc & 63)] = vv;
    }
}

// ---------------- global-row attention, split-K partials ----------------
__global__ __launch_bounds__(256) void gattn_part(const int* __restrict__ mask)
{
    extern __shared__ float sm[];
    float* Qgs  = sm;
    float* Kts  = Qgs + 16 * 68;
    float* Vs   = Kts + 64 * 132;
    float* Ps   = Vs + 128 * 68;
    float* rowm = Ps + 16 * 129;
    float* rowl = rowm + 16;
    float* rowf = rowl + 16;

    int si = blockIdx.x, h = blockIdx.y, b = blockIdx.z;
    int tid = threadIdx.x;
    const float* kgb = g_kg + ((long)(b * Hh + h)) * Ss * DHd;
    const float* vgb = g_vg + ((long)(b * Hh + h)) * Ss * DHd;
    const int* mk = mask + b * Ss;

    for (int i = tid; i < 16 * 64; i += 256) {
        int r = i >> 6, d = i & 63;
        Qgs[r * 68 + d] = g_qg[(((long)b * Hh + h) * Gg + r) * DHd + d];
    }
    if (tid < 16) { rowm[tid] = -3.0e38f; rowl[tid] = 0.f; }

    float oacc[4] = {0.f, 0.f, 0.f, 0.f};
    int r = tid >> 4, cg = tid & 15;
    __syncthreads();

    for (int c = 0; c < 4; c++) {
        int p0 = si * 512 + c * 128;
#pragma unroll
        for (int it = 0; it < 8; it++) {
            int idx = tid + it * 256;
            int j = idx >> 4, cv = idx & 15;
            int p = p0 + j;
            float4 kv = *(const float4*)(kgb + (long)p * 64 + cv * 4);
            float4 vv = *(const float4*)(vgb + (long)p * 64 + cv * 4);
            Kts[(cv * 4 + 0) * 132 + j] = kv.x;
            Kts[(cv * 4 + 1) * 132 + j] = kv.y;
            Kts[(cv * 4 + 2) * 132 + j] = kv.z;
            Kts[(cv * 4 + 3) * 132 + j] = kv.w;
            *(float4*)&Vs[j * 68 + cv * 4] = vv;
        }
        __syncthreads();

        float sc8[8] = {0.f, 0.f, 0.f, 0.f, 0.f, 0.f, 0.f, 0.f};
#pragma unroll 8
        for (int d = 0; d < 64; d++) {
            float a = Qgs[r * 68 + d];
#pragma unroll
            for (int j = 0; j < 8; j++) sc8[j] += a * Kts[d * 132 + cg * 8 + j];
        }
#pragma unroll
        for (int j = 0; j < 8; j++) {
            int p = p0 + cg * 8 + j;
            Ps[r * 129 + cg * 8 + j] = (mk[p] > 0) ? sc8[j] : NEGF;
        }
        __syncthreads();

        if (tid < 16) {
            float mx = rowm[tid], cm = -3.0e38f;
            for (int j2 = 0; j2 < 128; j2++) cm = fmaxf(cm, Ps[tid * 129 + j2]);
            float nm = fmaxf(mx, cm);
            float f = __expf(mx - nm);
            float ls = 0.f;
            for (int j2 = 0; j2 < 128; j2++) {
                float pv = __expf(Ps[tid * 129 + j2] - nm);
                Ps[tid * 129 + j2] = pv;
                ls += pv;
            }
            rowl[tid] = rowl[tid] * f + ls;
            rowm[tid] = nm;
            rowf[tid] = f;
        }
        __syncthreads();

        float f = rowf[r];
#pragma unroll
        for (int j = 0; j < 4; j++) oacc[j] *= f;
        for (int kk = 0; kk < 128; kk++) {
            float a = Ps[r * 129 + kk];
#pragma unroll
            for (int j = 0; j < 4; j++) oacc[j] += a * Vs[kk * 68 + cg * 4 + j];
        }
        __syncthreads();
    }
    int part = (b * Hh + h) * NSPLIT + si;
#pragma unroll
    for (int j = 0; j < 4; j++)
        g_pacc[((long)part * 16 + r) * 64 + cg * 4 + j] = oacc[j];
    if (cg == 0) {
        g_pm[part * 16 + r] = rowm[r];
        g_pl[part * 16 + r] = rowl[r];
    }
}

__global__ __launch_bounds__(64) void gattn_combine()
{
    int bh = blockIdx.x;
    int b = bh / Hh, h = bh % Hh;
    int d = threadIdx.x;
    for (int r = 0; r < Gg; r++) {
        float M = -3.0e38f;
        for (int si = 0; si < NSPLIT; si++)
            M = fmaxf(M, g_pm[((b * Hh + h) * NSPLIT + si) * 16 + r]);
        float L = 0.f, a = 0.f;
        for (int si = 0; si < NSPLIT; si++) {
            int part = (b * Hh + h) * NSPLIT + si;
            float w = __expf(g_pm[part * 16 + r] - M);
            L += w * g_pl[part * 16 + r];
            a += w * g_pacc[((long)part * 16 + r) * 64 + d];
        }
        g_attn[((long)b * Ss + r) * Dd + h * DHd + d] = a / L;
    }
}

// ---------------- launch ----------------
extern "C" void kernel_launch(void* const* d_in, const int* in_sizes, int n_in,
                              void* d_out, int out_size)
{
    (void)in_sizes; (void)n_in; (void)out_size;
    const float* x    = (const float*)d_in[0];
    const int*   mask = (const int*)d_in[1];
    W6 w6;
    w6.w[0] = (const float*)d_in[2];   // Wq
    w6.w[1] = (const float*)d_in[4];   // Wk
    w6.w[2] = (const float*)d_in[6];   // Wv
    w6.w[3] = (const float*)d_in[10];  // Wkg
    w6.w[4] = (const float*)d_in[12];  // Wvg
    w6.w[5] = (const float*)d_in[14];  // Wo
    Bia5 b5;
    b5.b[0] = (const float*)d_in[3];   // bq
    b5.b[1] = (const float*)d_in[5];   // bk
    b5.b[2] = (const float*)d_in[7];   // bv
    b5.b[3] = (const float*)d_in[11];  // bkg
    b5.b[4] = (const float*)d_in[13];  // bvg
    const float* Wqg = (const float*)d_in[8];
    const float* bqg = (const float*)d_in[9];
    const float* bo  = (const float*)d_in[15];
    float* out = (float*)d_out;

    int lsm = (64 * 132 + 64 * 132 + 128 * 68 + 128 * 129 + 3 * 128 + 128) * 4;
    cudaFuncSetAttribute(local_attn, cudaFuncAttributeMaxDynamicSharedMemorySize, lsm);
    int gsm = (16 * 68 + 64 * 132 + 128 * 68 + 16 * 129 + 3 * 16) * 4;
    cudaFuncSetAttribute(gattn_part, cudaFuncAttributeMaxDynamicSharedMemorySize, gsm);
    cudaFuncSetAttribute(mma_gemm<false>, cudaFuncAttributeMaxDynamicSharedMemorySize, GEMM_SMEM);
    cudaFuncSetAttribute(mma_gemm<true>,  cudaFuncAttributeMaxDynamicSharedMemorySize, GEMM_SMEM);

    __nv_bfloat16 *xhi, *xlo, *ahi, *alo;
    cudaGetSymbolAddress((void**)&xhi, g_xhi);
    cudaGetSymbolAddress((void**)&xlo, g_xlo);
    cudaGetSymbolAddress((void**)&ahi, g_ahi);
    cudaGetSymbolAddress((void**)&alo, g_alo);
    float* attn;
    cudaGetSymbolAddress((void**)&attn, g_attn);

    int n4 = Bb * Ss * Dd / 4;
    to_bf16_split<<<(n4 + 255) / 256, 256>>>(x, xhi, xlo, n4);           // 1
    prep_w<<<dim3(24, 24, 6), dim3(32, 8)>>>(w6);                        // 2
    mma_gemm<false><<<dim3(6, 64, 5), 256, GEMM_SMEM>>>(xhi, xlo, b5, nullptr, nullptr); // 3
    qg_proj<<<Bb * Gg, 256>>>(x, Wqg, bqg);                              // 4
    gattn_part<<<dim3(NSPLIT, Hh, Bb), 256, gsm>>>(mask);                // 5
    local_attn<<<dim3(NBb, Hh, Bb), 256, lsm>>>(mask);                   // 6 (profiled)
    gattn_combine<<<Bb * Hh, 64>>>();                                    // 7
    to_bf16_split<<<(n4 + 255) / 256, 256>>>(attn, ahi, alo, n4);        // 8
    mma_gemm<true><<<dim3(6, 64), 256, GEMM_SMEM>>>(ahi, alo, b5, bo, out); // 9
}

// round 6
// speedup vs baseline: 2.0113x; 1.2633x over previous
#include <cuda_runtime.h>
#include <cuda_bf16.h>
#include <cstdint>

#define Bb 2
#define Ss 4096
#define Dd 768
#define Hh 12
#define DHd 64
#define Ww 128
#define Gg 16
#define NBb 32
#define NSPLIT 8
#define NEGF (-1.0e9f)

// ---------------- scratch (device globals; no allocation) ----------------
__device__ float g_kg[Bb*Hh*Ss*DHd];
__device__ float g_vg[Bb*Hh*Ss*DHd];
__device__ float g_attn[Bb*Ss*Dd];
__device__ float g_qg[Bb*Hh*Gg*DHd];
__device__ float g_pm  [Bb*Hh*NSPLIT*Gg];
__device__ float g_pl  [Bb*Hh*NSPLIT*Gg];
__device__ float g_pacc[Bb*Hh*NSPLIT*Gg*DHd];

// bf16 split operands
__device__ __nv_bfloat16 g_xhi[Bb*Ss*Dd];
__device__ __nv_bfloat16 g_xlo[Bb*Ss*Dd];
__device__ __nv_bfloat16 g_ahi[Bb*Ss*Dd];
__device__ __nv_bfloat16 g_alo[Bb*Ss*Dd];
__device__ __nv_bfloat16 g_wthi[6*Dd*Dd];   // transposed [N][K], 6 weights
__device__ __nv_bfloat16 g_wtlo[6*Dd*Dd];
// q/k/v in bf16 hi/lo, layout [B,H,S,DH]
__device__ __nv_bfloat16 g_qhi[Bb*Hh*Ss*DHd];
__device__ __nv_bfloat16 g_qlo[Bb*Hh*Ss*DHd];
__device__ __nv_bfloat16 g_khi[Bb*Hh*Ss*DHd];
__device__ __nv_bfloat16 g_klo[Bb*Hh*Ss*DHd];
__device__ __nv_bfloat16 g_vhi[Bb*Hh*Ss*DHd];
__device__ __nv_bfloat16 g_vlo[Bb*Hh*Ss*DHd];

struct W6   { const float* w[6]; };
struct Bia5 { const float* b[5]; };

// ================= warp-MMA helpers =================
#define SWZ(o) ((o) ^ (((o) >> 3) & 0x70))

__device__ __forceinline__ uint32_t smem_u32(const void* p) {
    uint32_t a;
    asm("{ .reg .u64 t; cvta.to.shared.u64 t, %1; cvt.u32.u64 %0, t; }" : "=r"(a) : "l"(p));
    return a;
}
__device__ __forceinline__ void ldsm4(uint32_t* r, uint32_t addr) {
    asm volatile("ldmatrix.sync.aligned.m8n8.x4.shared.b16 {%0,%1,%2,%3}, [%4];"
                 : "=r"(r[0]), "=r"(r[1]), "=r"(r[2]), "=r"(r[3]) : "r"(addr));
}
__device__ __forceinline__ void mma16816(float* d, const uint32_t* a, uint32_t b0, uint32_t b1) {
    asm volatile(
        "mma.sync.aligned.m16n8k16.row.col.f32.bf16.bf16.f32 "
        "{%0,%1,%2,%3}, {%4,%5,%6,%7}, {%8,%9}, {%0,%1,%2,%3};"
        : "+f"(d[0]), "+f"(d[1]), "+f"(d[2]), "+f"(d[3])
        : "r"(a[0]), "r"(a[1]), "r"(a[2]), "r"(a[3]), "r"(b0), "r"(b1));
}
__device__ __forceinline__ void pack_hilo(float e0, float e1, uint32_t& hi, uint32_t& lo) {
    __nv_bfloat162 h = __floats2bfloat162_rn(e0, e1);
    float r0 = e0 - __bfloat162float(h.x);
    float r1 = e1 - __bfloat162float(h.y);
    __nv_bfloat162 l2 = __floats2bfloat162_rn(r0, r1);
    hi = *(uint32_t*)&h;
    lo = *(uint32_t*)&l2;
}

// ================= prep kernels =================
__global__ __launch_bounds__(256) void to_bf16_split(const float* __restrict__ in,
                                                     __nv_bfloat16* __restrict__ hi,
                                                     __nv_bfloat16* __restrict__ lo, int n4)
{
    int i = blockIdx.x * 256 + threadIdx.x;
    if (i >= n4) return;
    float4 v = ((const float4*)in)[i];
    float vv[4] = {v.x, v.y, v.z, v.w};
    union { __nv_bfloat16 h[4]; uint2 u; } uh, ul;
#pragma unroll
    for (int j = 0; j < 4; j++) {
        __nv_bfloat16 h = __float2bfloat16(vv[j]);
        uh.h[j] = h;
        ul.h[j] = __float2bfloat16(vv[j] - __bfloat162float(h));
    }
    *(uint2*)(hi + (size_t)i * 4) = uh.u;
    *(uint2*)(lo + (size_t)i * 4) = ul.u;
}

__global__ __launch_bounds__(256) void prep_w(W6 ws)
{
    __shared__ float t[32][33];
    int z = blockIdx.z;
    const float* W = ws.w[z];
    __nv_bfloat16* oh = g_wthi + (size_t)z * Dd * Dd;
    __nv_bfloat16* ol = g_wtlo + (size_t)z * Dd * Dd;
    int k0 = blockIdx.x * 32, n0 = blockIdx.y * 32;
    int tx = threadIdx.x, ty = threadIdx.y;
#pragma unroll
    for (int r = 0; r < 4; r++)
        t[ty + r * 8][tx] = W[(size_t)(k0 + ty + r * 8) * Dd + n0 + tx];
    __syncthreads();
#pragma unroll
    for (int r = 0; r < 4; r++) {
        float v = t[tx][ty + r * 8];
        __nv_bfloat16 h = __float2bfloat16(v);
        size_t o = (size_t)(n0 + ty + r * 8) * Dd + k0 + tx;
        oh[o] = h;
        ol[o] = __float2bfloat16(v - __bfloat162float(h));
    }
}

// ================= bf16 mma.sync GEMM =================
#define GEMM_SMEM 65536

template<bool OUT>
__global__ __launch_bounds__(256)
void mma_gemm(const __nv_bfloat16* __restrict__ Ahi, const __nv_bfloat16* __restrict__ Alo,
              Bia5 bp, const float* __restrict__ bias_o, float* __restrict__ outp)
{
    extern __shared__ char smem[];
    uint32_t sb = smem_u32(smem);
    int tid = threadIdx.x;
    int wid = tid >> 5, lane = tid & 31;
    int wm = wid >> 2, wn = wid & 3;
    int z = OUT ? 5 : blockIdx.z;
    int n0 = blockIdx.x * 128, m0 = blockIdx.y * 128;

    const __nv_bfloat16* Bhi = g_wthi + (size_t)z * Dd * Dd;
    const __nv_bfloat16* Blo = g_wtlo + (size_t)z * Dd * Dd;
    const __nv_bfloat16* srcs[4] = {
        Ahi + (size_t)m0 * Dd, Alo + (size_t)m0 * Dd,
        Bhi + (size_t)n0 * Dd, Blo + (size_t)n0 * Dd };

    float acc[4][4][4];
#pragma unroll
    for (int i = 0; i < 4; i++)
#pragma unroll
        for (int j = 0; j < 4; j++)
#pragma unroll
            for (int q = 0; q < 4; q++) acc[i][j][q] = 0.f;

    int alr = lane & 15, alc = lane >> 4, arx = alr & 7;
    uint32_t aoff[4];
#pragma unroll
    for (int mi = 0; mi < 4; mi++) aoff[mi] = (wm * 64 + mi * 16 + alr) * 128;
    int blr = (lane & 7) + ((lane >> 4) & 1) * 8;
    int blc = (lane >> 3) & 1, brx = lane & 7;
    uint32_t boff[2];
#pragma unroll
    for (int ni = 0; ni < 2; ni++) boff[ni] = (wn * 32 + ni * 16 + blr) * 128;

    uint32_t sA = sb, sAl = sb + 16384, sB = sb + 32768, sBl = sb + 49152;

    for (int c = 0; c < 12; c++) {
        int k0 = c * 64;
#pragma unroll
        for (int t = 0; t < 4; t++) {
            const __nv_bfloat16* sp = srcs[t] + k0;
            char* tp = smem + t * 16384;
#pragma unroll
            for (int it = 0; it < 4; it++) {
                int idx = tid + it * 256;
                int row = idx >> 3, cu = idx & 7;
                uint4 v = *(const uint4*)(sp + (size_t)row * Dd + cu * 8);
                *(uint4*)(tp + SWZ(row * 128 + cu * 16)) = v;
            }
        }
        __syncthreads();
#pragma unroll
        for (int ks = 0; ks < 4; ks++) {
            uint32_t ah[4][4], al[4][4], bh[2][4], bl[2][4];
            uint32_t ac = ((uint32_t)(ks * 2 + alc) ^ arx) << 4;
            uint32_t bc = ((uint32_t)(ks * 2 + blc) ^ brx) << 4;
#pragma unroll
            for (int mi = 0; mi < 4; mi++) {
                ldsm4(ah[mi], sA  + aoff[mi] + ac);
                ldsm4(al[mi], sAl + aoff[mi] + ac);
            }
#pragma unroll
            for (int ni = 0; ni < 2; ni++) {
                ldsm4(bh[ni], sB  + boff[ni] + bc);
                ldsm4(bl[ni], sBl + boff[ni] + bc);
            }
#pragma unroll
            for (int mi = 0; mi < 4; mi++)
#pragma unroll
                for (int nj = 0; nj < 4; nj++) {
                    int ni = nj >> 1, hf = (nj & 1) * 2;
                    mma16816(acc[mi][nj], ah[mi], bh[ni][hf], bh[ni][hf + 1]);
                    mma16816(acc[mi][nj], al[mi], bh[ni][hf], bh[ni][hf + 1]);
                    mma16816(acc[mi][nj], ah[mi], bl[ni][hf], bl[ni][hf + 1]);
                }
        }
        __syncthreads();
    }

    int g = lane >> 2, t4 = lane & 3;
#pragma unroll
    for (int mi = 0; mi < 4; mi++) {
        int r0 = m0 + wm * 64 + mi * 16 + g;
#pragma unroll
        for (int nj = 0; nj < 4; nj++) {
            int cc = n0 + wn * 32 + nj * 8 + t4 * 2;
#pragma unroll
            for (int half = 0; half < 2; half++) {
                int m = r0 + half * 8;
                float v0 = acc[mi][nj][half * 2 + 0];
                float v1 = acc[mi][nj][half * 2 + 1];
                if (OUT) {
                    float2 o = make_float2(v0 + bias_o[cc], v1 + bias_o[cc + 1]);
                    *(float2*)(outp + (size_t)m * Dd + cc) = o;
                } else {
                    const float* bias = bp.b[z];
                    float scale = (z == 0) ? 0.125f : 1.0f;
                    v0 = (v0 + bias[cc]) * scale;
                    v1 = (v1 + bias[cc + 1]) * scale;
                    int b = m >> 12, s = m & 4095;
                    int h = cc >> 6, d0 = cc & 63;
                    size_t base = (((size_t)(b * Hh + h)) * Ss + s) * DHd + d0;
                    if (z >= 3) {
                        float* dstz = (z == 3) ? g_kg : g_vg;
                        *(float2*)(dstz + base) = make_float2(v0, v1);
                    } else {
                        uint32_t hi, lo;
                        pack_hilo(v0, v1, hi, lo);
                        __nv_bfloat16 *dh, *dl;
                        if (z == 0)      { dh = g_qhi; dl = g_qlo; }
                        else if (z == 1) { dh = g_khi; dl = g_klo; }
                        else             { dh = g_vhi; dl = g_vlo; }
                        *(uint32_t*)(dh + base) = hi;
                        *(uint32_t*)(dl + base) = lo;
                    }
                }
            }
        }
    }
}

// ================= local attention: register FA2 on mma.sync =================
// smem: kok[128]f @0 (pad to 1024) | Qhi 16K | Qlo | Khi | Klo | Vthi | Vtlo
#define LA_KOK   0
#define LA_Q     1024
#define LA_QL    (LA_Q  + 16384)
#define LA_K     (LA_QL + 16384)
#define LA_KL    (LA_K  + 16384)
#define LA_VT    (LA_KL + 16384)
#define LA_VTL   (LA_VT + 16384)
#define LA_SMEM  (LA_VTL + 16384)

__global__ __launch_bounds__(256) void local_attn(const int* __restrict__ mask)
{
    extern __shared__ char smem[];
    uint32_t sb = smem_u32(smem);
    float* kok = (float*)(smem + LA_KOK);

    int n = blockIdx.x, h = blockIdx.y, b = blockIdx.z;
    int tid = threadIdx.x;
    int wid = tid >> 5, lane = tid & 31;
    int g = lane >> 2, t4 = lane & 3;
    int qr = wid * 16;

    size_t bhbase = ((size_t)(b * Hh + h)) * Ss * DHd;
    const __nv_bfloat16* qh_g = g_qhi + bhbase + (size_t)n * Ww * DHd;
    const __nv_bfloat16* ql_g = g_qlo + bhbase + (size_t)n * Ww * DHd;
    const __nv_bfloat16* kh_g = g_khi + bhbase;
    const __nv_bfloat16* kl_g = g_klo + bhbase;
    const __nv_bfloat16* vh_g = g_vhi + bhbase;
    const __nv_bfloat16* vl_g = g_vlo + bhbase;
    const int* mk = mask + b * Ss;

    // load Q (once): 1024 uint4 per buffer
#pragma unroll
    for (int it = 0; it < 4; it++) {
        int idx = tid + it * 256;
        int row = idx >> 3, cu = idx & 7;
        uint32_t sw = row * 128 + ((cu ^ (row & 7)) << 4);
        *(uint4*)(smem + LA_Q  + sw) = *(const uint4*)(qh_g + (size_t)row * DHd + cu * 8);
        *(uint4*)(smem + LA_QL + sw) = *(const uint4*)(ql_g + (size_t)row * DHd + cu * 8);
    }

    float sacc[16][4];
    float O[8][4];
#pragma unroll
    for (int j = 0; j < 8; j++)
#pragma unroll
        for (int q = 0; q < 4; q++) O[j][q] = 0.f;
    float m0 = -3.0e38f, m1 = -3.0e38f, l0 = 0.f, l1 = 0.f;

    int arow = qr + (lane & 15);
    uint32_t aboff = arow * 128;
    int arx = lane & 7;
    int alc = lane >> 4;
    int krow_in = (lane & 7) + 8 * ((lane >> 4) & 1);
    int kcc = (lane >> 3) & 1;

    for (int c = 0; c < 4; c++) {
        int p0 = (n - 1) * Ww + c * Ww;
        __syncthreads();   // previous chunk fully consumed
        // kok flags
        if (tid < 128) {
            bool ok;
            if (c == 3) ok = (tid < Gg) && (mk[tid] > 0);
            else { int p = p0 + tid; ok = (p >= Gg) && (p < Ss) && (mk[p] > 0); }
            kok[tid] = ok ? 1.f : 0.f;
        }
        // load K hi/lo (swizzled) and V^T hi/lo
#pragma unroll
        for (int it = 0; it < 4; it++) {
            int idx = tid + it * 256;
            int j = idx >> 3, cu = idx & 7;
            int p = (c == 3) ? j : (p0 + j);
            bool inr = (c == 3) ? (j < Gg) : (p >= 0 && p < Ss);
            uint4 kv = make_uint4(0, 0, 0, 0), kv2 = make_uint4(0, 0, 0, 0);
            uint4 vv = make_uint4(0, 0, 0, 0), vv2 = make_uint4(0, 0, 0, 0);
            if (inr) {
                size_t gb = (size_t)p * DHd + cu * 8;
                kv  = *(const uint4*)(kh_g + gb);
                kv2 = *(const uint4*)(kl_g + gb);
                vv  = *(const uint4*)(vh_g + gb);
                vv2 = *(const uint4*)(vl_g + gb);
            }
            uint32_t sw = j * 128 + ((cu ^ (j & 7)) << 4);
            *(uint4*)(smem + LA_K  + sw) = kv;
            *(uint4*)(smem + LA_KL + sw) = kv2;
            // scatter V^T: element (d = cu*8+i, key j)
            union { uint4 u; __nv_bfloat16 hfv[8]; } uv, uv2;
            uv.u = vv; uv2.u = vv2;
#pragma unroll
            for (int i = 0; i < 8; i++) {
                int d = cu * 8 + i;
                uint32_t vo = d * 256 + (((j >> 3) ^ (d & 7)) << 4) + (j & 7) * 2;
                *(__nv_bfloat16*)(smem + LA_VT  + vo) = uv.hfv[i];
                *(__nv_bfloat16*)(smem + LA_VTL + vo) = uv2.hfv[i];
            }
        }
        __syncthreads();

        // ---- S = Q.K^T ----
#pragma unroll
        for (int j = 0; j < 16; j++)
#pragma unroll
            for (int q = 0; q < 4; q++) sacc[j][q] = 0.f;
#pragma unroll
        for (int ks = 0; ks < 4; ks++) {
            uint32_t qh4[4], ql4[4];
            uint32_t ac = ((uint32_t)(ks * 2 + alc) ^ arx) << 4;
            ldsm4(qh4, sb + LA_Q  + aboff + ac);
            ldsm4(ql4, sb + LA_QL + aboff + ac);
#pragma unroll
            for (int jj = 0; jj < 8; jj++) {
                uint32_t kh4[4], kl4[4];
                uint32_t kb = (16 * jj + krow_in) * 128 + (((uint32_t)(ks * 2 + kcc) ^ arx) << 4);
                ldsm4(kh4, sb + LA_K  + kb);
                ldsm4(kl4, sb + LA_KL + kb);
                mma16816(sacc[2 * jj],     qh4, kh4[0], kh4[1]);
                mma16816(sacc[2 * jj],     ql4, kh4[0], kh4[1]);
                mma16816(sacc[2 * jj],     qh4, kl4[0], kl4[1]);
                mma16816(sacc[2 * jj + 1], qh4, kh4[2], kh4[3]);
                mma16816(sacc[2 * jj + 1], ql4, kh4[2], kh4[3]);
                mma16816(sacc[2 * jj + 1], qh4, kl4[2], kl4[3]);
            }
        }

        // ---- mask ----
        int row0 = n * Ww + qr + g;
        int row1 = row0 + 8;
#pragma unroll
        for (int j = 0; j < 16; j++) {
#pragma unroll
            for (int q = 0; q < 4; q++) {
                int col = 8 * j + t4 * 2 + (q & 1);
                int row = (q >= 2) ? row1 : row0;
                bool ok = kok[col] > 0.f;
                if (c != 3) {
                    int rel = (p0 + col) - row;
                    ok = ok && (rel <= Ww) && (rel >= -Ww);
                }
                if (!ok) sacc[j][q] = NEGF;
            }
        }

        // ---- online softmax (registers) ----
        float mx0 = -3.0e38f, mx1 = -3.0e38f;
#pragma unroll
        for (int j = 0; j < 16; j++) {
            mx0 = fmaxf(mx0, fmaxf(sacc[j][0], sacc[j][1]));
            mx1 = fmaxf(mx1, fmaxf(sacc[j][2], sacc[j][3]));
        }
        mx0 = fmaxf(mx0, __shfl_xor_sync(0xffffffff, mx0, 1));
        mx0 = fmaxf(mx0, __shfl_xor_sync(0xffffffff, mx0, 2));
        mx1 = fmaxf(mx1, __shfl_xor_sync(0xffffffff, mx1, 1));
        mx1 = fmaxf(mx1, __shfl_xor_sync(0xffffffff, mx1, 2));
        float mn0 = fmaxf(m0, mx0), mn1 = fmaxf(m1, mx1);
        float f0 = __expf(m0 - mn0), f1 = __expf(m1 - mn1);
        float s0 = 0.f, s1 = 0.f;
#pragma unroll
        for (int j = 0; j < 16; j++) {
            float p0v = __expf(sacc[j][0] - mn0);
            float p1v = __expf(sacc[j][1] - mn0);
            float p2v = __expf(sacc[j][2] - mn1);
            float p3v = __expf(sacc[j][3] - mn1);
            sacc[j][0] = p0v; sacc[j][1] = p1v; sacc[j][2] = p2v; sacc[j][3] = p3v;
            s0 += p0v + p1v; s1 += p2v + p3v;
        }
        s0 += __shfl_xor_sync(0xffffffff, s0, 1);
        s0 += __shfl_xor_sync(0xffffffff, s0, 2);
        s1 += __shfl_xor_sync(0xffffffff, s1, 1);
        s1 += __shfl_xor_sync(0xffffffff, s1, 2);
        l0 = l0 * f0 + s0; l1 = l1 * f1 + s1;
        m0 = mn0; m1 = mn1;
#pragma unroll
        for (int j = 0; j < 8; j++) {
            O[j][0] *= f0; O[j][1] *= f0; O[j][2] *= f1; O[j][3] *= f1;
        }

        // ---- O += P.V ----
#pragma unroll
        for (int ks = 0; ks < 8; ks++) {
            uint32_t pah[4], pal[4];
            pack_hilo(sacc[2 * ks][0],     sacc[2 * ks][1],     pah[0], pal[0]);
            pack_hilo(sacc[2 * ks][2],     sacc[2 * ks][3],     pah[1], pal[1]);
            pack_hilo(sacc[2 * ks + 1][0], sacc[2 * ks + 1][1], pah[2], pal[2]);
            pack_hilo(sacc[2 * ks + 1][2], sacc[2 * ks + 1][3], pah[3], pal[3]);
#pragma unroll
            for (int jd = 0; jd < 4; jd++) {
                uint32_t vh4[4], vl4[4];
                int drow = 16 * jd + krow_in;
                uint32_t vb = drow * 256 + (((uint32_t)(ks * 2 + kcc) ^ (uint32_t)(drow & 7)) << 4);
                ldsm4(vh4, sb + LA_VT  + vb);
                ldsm4(vl4, sb + LA_VTL + vb);
                mma16816(O[2 * jd],     pah, vh4[0], vh4[1]);
                mma16816(O[2 * jd],     pal, vh4[0], vh4[1]);
                mma16816(O[2 * jd],     pah, vl4[0], vl4[1]);
                mma16816(O[2 * jd + 1], pah, vh4[2], vh4[3]);
                mma16816(O[2 * jd + 1], pal, vh4[2], vh4[3]);
                mma16816(O[2 * jd + 1], pah, vl4[2], vl4[3]);
            }
        }
    }

    // ---- write out: g_attn[b][s][h*64+d] ----
    float inv0 = 1.0f / l0, inv1 = 1.0f / l1;
    int s0r = n * Ww + qr + g;
    int s1r = s0r + 8;
    float* o0 = g_attn + ((size_t)b * Ss + s0r) * Dd + h * DHd;
    float* o1 = g_attn + ((size_t)b * Ss + s1r) * Dd + h * DHd;
#pragma unroll
    for (int jd = 0; jd < 8; jd++) {
        int cc = 8 * jd + t4 * 2;
        *(float2*)(o0 + cc) = make_float2(O[jd][0] * inv0, O[jd][1] * inv0);
        *(float2*)(o1 + cc) = make_float2(O[jd][2] * inv1, O[jd][3] * inv1);
    }
}

// ---------------- qg projection: parallelized split-K ----------------
__global__ __launch_bounds__(256) void qg_proj(const float* __restrict__ x,
                                               const float* __restrict__ Wqg,
                                               const float* __restrict__ bqg)
{
    __shared__ float xr[768];
    __shared__ float sred[256];
    int bg = blockIdx.x, cc = blockIdx.y;
    int b = bg >> 4, g = bg & 15;
    int tid = threadIdx.x;
    for (int i = tid; i < 768; i += 256) xr[i] = x[((size_t)b * Ss + g) * Dd + i];
    __syncthreads();
    int col = cc * 128 + (tid & 127);
    int kh = tid >> 7;
    float acc = 0.f;
    int kbase = kh * 384;
#pragma unroll 8
    for (int k = 0; k < 384; k++)
        acc += xr[kbase + k] * Wqg[(size_t)(kbase + k) * 768 + col];
    sred[tid] = acc;
    __syncthreads();
    if (tid < 128) {
        float tot = sred[tid] + sred[tid + 128];
        int c = cc * 128 + tid;
        float vv = (tot + bqg[c]) * 0.125f;
        g_qg[(((size_t)b * Hh + (c >> 6)) * Gg + g) * DHd + (c & 63)] = vv;
    }
}

// ---------------- global-row attention, split-K partials ----------------
__global__ __launch_bounds__(256) void gattn_part(const int* __restrict__ mask)
{
    extern __shared__ float sm[];
    float* Qgs  = sm;
    float* Kts  = Qgs + 16 * 68;
    float* Vs   = Kts + 64 * 132;
    float* Ps   = Vs + 128 * 68;
    float* rowm = Ps + 16 * 129;
    float* rowl = rowm + 16;
    float* rowf = rowl + 16;

    int si = blockIdx.x, h = blockIdx.y, b = blockIdx.z;
    int tid = threadIdx.x;
    const float* kgb = g_kg + ((size_t)(b * Hh + h)) * Ss * DHd;
    const float* vgb = g_vg + ((size_t)(b * Hh + h)) * Ss * DHd;
    const int* mk = mask + b * Ss;

    for (int i = tid; i < 16 * 64; i += 256) {
        int r = i >> 6, d = i & 63;
        Qgs[r * 68 + d] = g_qg[(((size_t)b * Hh + h) * Gg + r) * DHd + d];
    }
    if (tid < 16) { rowm[tid] = -3.0e38f; rowl[tid] = 0.f; }

    float oacc[4] = {0.f, 0.f, 0.f, 0.f};
    int r = tid >> 4, cg = tid & 15;
    __syncthreads();

    for (int c = 0; c < 4; c++) {
        int p0 = si * 512 + c * 128;
#pragma unroll
        for (int it = 0; it < 8; it++) {
            int idx = tid + it * 256;
            int j = idx >> 4, cv = idx & 15;
            int p = p0 + j;
            float4 kv = *(const float4*)(kgb + (size_t)p * 64 + cv * 4);
            float4 vv = *(const float4*)(vgb + (size_t)p * 64 + cv * 4);
            Kts[(cv * 4 + 0) * 132 + j] = kv.x;
            Kts[(cv * 4 + 1) * 132 + j] = kv.y;
            Kts[(cv * 4 + 2) * 132 + j] = kv.z;
            Kts[(cv * 4 + 3) * 132 + j] = kv.w;
            *(float4*)&Vs[j * 68 + cv * 4] = vv;
        }
        __syncthreads();

        float sc8[8] = {0.f, 0.f, 0.f, 0.f, 0.f, 0.f, 0.f, 0.f};
#pragma unroll 8
        for (int d = 0; d < 64; d++) {
            float a = Qgs[r * 68 + d];
#pragma unroll
            for (int j = 0; j < 8; j++) sc8[j] += a * Kts[d * 132 + cg * 8 + j];
        }
#pragma unroll
        for (int j = 0; j < 8; j++) {
            int p = p0 + cg * 8 + j;
            Ps[r * 129 + cg * 8 + j] = (mk[p] > 0) ? sc8[j] : NEGF;
        }
        __syncthreads();

        if (tid < 16) {
            float mx = rowm[tid], cm = -3.0e38f;
            for (int j2 = 0; j2 < 128; j2++) cm = fmaxf(cm, Ps[tid * 129 + j2]);
            float nm = fmaxf(mx, cm);
            float f = __expf(mx - nm);
            float ls = 0.f;
            for (int j2 = 0; j2 < 128; j2++) {
                float pv = __expf(Ps[tid * 129 + j2] - nm);
                Ps[tid * 129 + j2] = pv;
                ls += pv;
            }
            rowl[tid] = rowl[tid] * f + ls;
            rowm[tid] = nm;
            rowf[tid] = f;
        }
        __syncthreads();

        float f = rowf[r];
#pragma unroll
        for (int j = 0; j < 4; j++) oacc[j] *= f;
        for (int kk = 0; kk < 128; kk++) {
            float a = Ps[r * 129 + kk];
#pragma unroll
            for (int j = 0; j < 4; j++) oacc[j] += a * Vs[kk * 68 + cg * 4 + j];
        }
        __syncthreads();
    }
    int part = (b * Hh + h) * NSPLIT + si;
#pragma unroll
    for (int j = 0; j < 4; j++)
        g_pacc[((size_t)part * 16 + r) * 64 + cg * 4 + j] = oacc[j];
    if (cg == 0) {
        g_pm[part * 16 + r] = rowm[r];
        g_pl[part * 16 + r] = rowl[r];
    }
}

__global__ __launch_bounds__(64) void gattn_combine()
{
    int bh = blockIdx.x;
    int b = bh / Hh, h = bh % Hh;
    int d = threadIdx.x;
    for (int r = 0; r < Gg; r++) {
        float M = -3.0e38f;
        for (int si = 0; si < NSPLIT; si++)
            M = fmaxf(M, g_pm[((b * Hh + h) * NSPLIT + si) * 16 + r]);
        float L = 0.f, a = 0.f;
        for (int si = 0; si < NSPLIT; si++) {
            int part = (b * Hh + h) * NSPLIT + si;
            float w = __expf(g_pm[part * 16 + r] - M);
            L += w * g_pl[part * 16 + r];
            a += w * g_pacc[((size_t)part * 16 + r) * 64 + d];
        }
        g_attn[((size_t)b * Ss + r) * Dd + h * DHd + d] = a / L;
    }
}

// ---------------- launch ----------------
extern "C" void kernel_launch(void* const* d_in, const int* in_sizes, int n_in,
                              void* d_out, int out_size)
{
    (void)in_sizes; (void)n_in; (void)out_size;
    const float* x    = (const float*)d_in[0];
    const int*   mask = (const int*)d_in[1];
    W6 w6;
    w6.w[0] = (const float*)d_in[2];   // Wq
    w6.w[1] = (const float*)d_in[4];   // Wk
    w6.w[2] = (const float*)d_in[6];   // Wv
    w6.w[3] = (const float*)d_in[10];  // Wkg
    w6.w[4] = (const float*)d_in[12];  // Wvg
    w6.w[5] = (const float*)d_in[14];  // Wo
    Bia5 b5;
    b5.b[0] = (const float*)d_in[3];
    b5.b[1] = (const float*)d_in[5];
    b5.b[2] = (const float*)d_in[7];
    b5.b[3] = (const float*)d_in[11];
    b5.b[4] = (const float*)d_in[13];
    const float* Wqg = (const float*)d_in[8];
    const float* bqg = (const float*)d_in[9];
    const float* bo  = (const float*)d_in[15];
    float* out = (float*)d_out;

    int gsm = (16 * 68 + 64 * 132 + 128 * 68 + 16 * 129 + 3 * 16) * 4;
    cudaFuncSetAttribute(gattn_part, cudaFuncAttributeMaxDynamicSharedMemorySize, gsm);
    cudaFuncSetAttribute(mma_gemm<false>, cudaFuncAttributeMaxDynamicSharedMemorySize, GEMM_SMEM);
    cudaFuncSetAttribute(mma_gemm<true>,  cudaFuncAttributeMaxDynamicSharedMemorySize, GEMM_SMEM);
    cudaFuncSetAttribute(local_attn, cudaFuncAttributeMaxDynamicSharedMemorySize, LA_SMEM);

    __nv_bfloat16 *xhi, *xlo, *ahi, *alo;
    cudaGetSymbolAddress((void**)&xhi, g_xhi);
    cudaGetSymbolAddress((void**)&xlo, g_xlo);
    cudaGetSymbolAddress((void**)&ahi, g_ahi);
    cudaGetSymbolAddress((void**)&alo, g_alo);
    float* attn;
    cudaGetSymbolAddress((void**)&attn, g_attn);

    int n4 = Bb * Ss * Dd / 4;
    to_bf16_split<<<(n4 + 255) / 256, 256>>>(x, xhi, xlo, n4);           // 1
    prep_w<<<dim3(24, 24, 6), dim3(32, 8)>>>(w6);                        // 2
    mma_gemm<false><<<dim3(6, 64, 5), 256, GEMM_SMEM>>>(xhi, xlo, b5, nullptr, nullptr); // 3
    qg_proj<<<dim3(Bb * Gg, 6), 256>>>(x, Wqg, bqg);                     // 4
    gattn_part<<<dim3(NSPLIT, Hh, Bb), 256, gsm>>>(mask);                // 5
    local_attn<<<dim3(NBb, Hh, Bb), 256, LA_SMEM>>>(mask);               // 6 (profiled)
    gattn_combine<<<Bb * Hh, 64>>>();                                    // 7
    to_bf16_split<<<(n4 + 255) / 256, 256>>>(attn, ahi, alo, n4);        // 8
    mma_gemm<true><<<dim3(6, 64), 256, GEMM_SMEM>>>(ahi, alo, b5, bo, out); // 9
}

// round 7
// speedup vs baseline: 2.0893x; 1.0388x over previous
#include <cuda_runtime.h>
#include <cuda_bf16.h>
#include <cstdint>

#define Bb 2
#define Ss 4096
#define Dd 768
#define Hh 12
#define DHd 64
#define Ww 128
#define Gg 16
#define NBb 32
#define NSPLIT 32
#define NEGF (-1.0e9f)

// ---------------- scratch (device globals; no allocation) ----------------
__device__ float g_kg[Bb*Hh*Ss*DHd];
__device__ float g_vg[Bb*Hh*Ss*DHd];
__device__ float g_attn[Bb*Ss*Dd];
__device__ float g_qg[Bb*Hh*Gg*DHd];
__device__ float g_pm  [Bb*Hh*NSPLIT*Gg];
__device__ float g_pl  [Bb*Hh*NSPLIT*Gg];
__device__ float g_pacc[Bb*Hh*NSPLIT*Gg*DHd];

// bf16 split operands
__device__ __nv_bfloat16 g_xhi[Bb*Ss*Dd];
__device__ __nv_bfloat16 g_xlo[Bb*Ss*Dd];
__device__ __nv_bfloat16 g_ahi[Bb*Ss*Dd];
__device__ __nv_bfloat16 g_alo[Bb*Ss*Dd];
__device__ __nv_bfloat16 g_wthi[6*Dd*Dd];   // transposed [N][K], 6 weights
__device__ __nv_bfloat16 g_wtlo[6*Dd*Dd];
// q/k/v in bf16 hi/lo, layout [B,H,S,DH]
__device__ __nv_bfloat16 g_qhi[Bb*Hh*Ss*DHd];
__device__ __nv_bfloat16 g_qlo[Bb*Hh*Ss*DHd];
__device__ __nv_bfloat16 g_khi[Bb*Hh*Ss*DHd];
__device__ __nv_bfloat16 g_klo[Bb*Hh*Ss*DHd];
__device__ __nv_bfloat16 g_vhi[Bb*Hh*Ss*DHd];
__device__ __nv_bfloat16 g_vlo[Bb*Hh*Ss*DHd];

struct W6   { const float* w[6]; };
struct Bia5 { const float* b[5]; };

// ================= warp-MMA helpers =================
#define SWZ(o) ((o) ^ (((o) >> 3) & 0x70))

__device__ __forceinline__ uint32_t smem_u32(const void* p) {
    uint32_t a;
    asm("{ .reg .u64 t; cvta.to.shared.u64 t, %1; cvt.u32.u64 %0, t; }" : "=r"(a) : "l"(p));
    return a;
}
__device__ __forceinline__ void ldsm4(uint32_t* r, uint32_t addr) {
    asm volatile("ldmatrix.sync.aligned.m8n8.x4.shared.b16 {%0,%1,%2,%3}, [%4];"
                 : "=r"(r[0]), "=r"(r[1]), "=r"(r[2]), "=r"(r[3]) : "r"(addr));
}
__device__ __forceinline__ void ldsm4t(uint32_t* r, uint32_t addr) {
    asm volatile("ldmatrix.sync.aligned.m8n8.x4.trans.shared.b16 {%0,%1,%2,%3}, [%4];"
                 : "=r"(r[0]), "=r"(r[1]), "=r"(r[2]), "=r"(r[3]) : "r"(addr));
}
__device__ __forceinline__ void mma16816(float* d, const uint32_t* a, uint32_t b0, uint32_t b1) {
    asm volatile(
        "mma.sync.aligned.m16n8k16.row.col.f32.bf16.bf16.f32 "
        "{%0,%1,%2,%3}, {%4,%5,%6,%7}, {%8,%9}, {%0,%1,%2,%3};"
        : "+f"(d[0]), "+f"(d[1]), "+f"(d[2]), "+f"(d[3])
        : "r"(a[0]), "r"(a[1]), "r"(a[2]), "r"(a[3]), "r"(b0), "r"(b1));
}
__device__ __forceinline__ void pack_hilo(float e0, float e1, uint32_t& hi, uint32_t& lo) {
    __nv_bfloat162 h = __floats2bfloat162_rn(e0, e1);
    float r0 = e0 - __bfloat162float(h.x);
    float r1 = e1 - __bfloat162float(h.y);
    __nv_bfloat162 l2 = __floats2bfloat162_rn(r0, r1);
    hi = *(uint32_t*)&h;
    lo = *(uint32_t*)&l2;
}

// ================= prep kernels =================
__global__ __launch_bounds__(256) void to_bf16_split(const float* __restrict__ in,
                                                     __nv_bfloat16* __restrict__ hi,
                                                     __nv_bfloat16* __restrict__ lo, int n4)
{
    int i = blockIdx.x * 256 + threadIdx.x;
    if (i >= n4) return;
    float4 v = ((const float4*)in)[i];
    float vv[4] = {v.x, v.y, v.z, v.w};
    union { __nv_bfloat16 h[4]; uint2 u; } uh, ul;
#pragma unroll
    for (int j = 0; j < 4; j++) {
        __nv_bfloat16 h = __float2bfloat16(vv[j]);
        uh.h[j] = h;
        ul.h[j] = __float2bfloat16(vv[j] - __bfloat162float(h));
    }
    *(uint2*)(hi + (size_t)i * 4) = uh.u;
    *(uint2*)(lo + (size_t)i * 4) = ul.u;
}

__global__ __launch_bounds__(256) void prep_w(W6 ws)
{
    __shared__ float t[32][33];
    int z = blockIdx.z;
    const float* W = ws.w[z];
    __nv_bfloat16* oh = g_wthi + (size_t)z * Dd * Dd;
    __nv_bfloat16* ol = g_wtlo + (size_t)z * Dd * Dd;
    int k0 = blockIdx.x * 32, n0 = blockIdx.y * 32;
    int tx = threadIdx.x, ty = threadIdx.y;
#pragma unroll
    for (int r = 0; r < 4; r++)
        t[ty + r * 8][tx] = W[(size_t)(k0 + ty + r * 8) * Dd + n0 + tx];
    __syncthreads();
#pragma unroll
    for (int r = 0; r < 4; r++) {
        float v = t[tx][ty + r * 8];
        __nv_bfloat16 h = __float2bfloat16(v);
        size_t o = (size_t)(n0 + ty + r * 8) * Dd + k0 + tx;
        oh[o] = h;
        ol[o] = __float2bfloat16(v - __bfloat162float(h));
    }
}

// ================= bf16 mma.sync GEMM =================
#define GEMM_SMEM 65536

template<bool OUT>
__global__ __launch_bounds__(256)
void mma_gemm(const __nv_bfloat16* __restrict__ Ahi, const __nv_bfloat16* __restrict__ Alo,
              Bia5 bp, const float* __restrict__ bias_o, float* __restrict__ outp)
{
    extern __shared__ char smem[];
    uint32_t sb = smem_u32(smem);
    int tid = threadIdx.x;
    int wid = tid >> 5, lane = tid & 31;
    int wm = wid >> 2, wn = wid & 3;
    int z = OUT ? 5 : blockIdx.z;
    int n0 = blockIdx.x * 128, m0 = blockIdx.y * 128;

    const __nv_bfloat16* Bhi = g_wthi + (size_t)z * Dd * Dd;
    const __nv_bfloat16* Blo = g_wtlo + (size_t)z * Dd * Dd;
    const __nv_bfloat16* srcs[4] = {
        Ahi + (size_t)m0 * Dd, Alo + (size_t)m0 * Dd,
        Bhi + (size_t)n0 * Dd, Blo + (size_t)n0 * Dd };

    float acc[4][4][4];
#pragma unroll
    for (int i = 0; i < 4; i++)
#pragma unroll
        for (int j = 0; j < 4; j++)
#pragma unroll
            for (int q = 0; q < 4; q++) acc[i][j][q] = 0.f;

    int alr = lane & 15, alc = lane >> 4, arx = alr & 7;
    uint32_t aoff[4];
#pragma unroll
    for (int mi = 0; mi < 4; mi++) aoff[mi] = (wm * 64 + mi * 16 + alr) * 128;
    int blr = (lane & 7) + ((lane >> 4) & 1) * 8;
    int blc = (lane >> 3) & 1, brx = lane & 7;
    uint32_t boff[2];
#pragma unroll
    for (int ni = 0; ni < 2; ni++) boff[ni] = (wn * 32 + ni * 16 + blr) * 128;

    uint32_t sA = sb, sAl = sb + 16384, sB = sb + 32768, sBl = sb + 49152;

    for (int c = 0; c < 12; c++) {
        int k0 = c * 64;
#pragma unroll
        for (int t = 0; t < 4; t++) {
            const __nv_bfloat16* sp = srcs[t] + k0;
            char* tp = smem + t * 16384;
#pragma unroll
            for (int it = 0; it < 4; it++) {
                int idx = tid + it * 256;
                int row = idx >> 3, cu = idx & 7;
                uint4 v = *(const uint4*)(sp + (size_t)row * Dd + cu * 8);
                *(uint4*)(tp + SWZ(row * 128 + cu * 16)) = v;
            }
        }
        __syncthreads();
#pragma unroll
        for (int ks = 0; ks < 4; ks++) {
            uint32_t ah[4][4], al[4][4], bh[2][4], bl[2][4];
            uint32_t ac = ((uint32_t)(ks * 2 + alc) ^ arx) << 4;
            uint32_t bc = ((uint32_t)(ks * 2 + blc) ^ brx) << 4;
#pragma unroll
            for (int mi = 0; mi < 4; mi++) {
                ldsm4(ah[mi], sA  + aoff[mi] + ac);
                ldsm4(al[mi], sAl + aoff[mi] + ac);
            }
#pragma unroll
            for (int ni = 0; ni < 2; ni++) {
                ldsm4(bh[ni], sB  + boff[ni] + bc);
                ldsm4(bl[ni], sBl + boff[ni] + bc);
            }
#pragma unroll
            for (int mi = 0; mi < 4; mi++)
#pragma unroll
                for (int nj = 0; nj < 4; nj++) {
                    int ni = nj >> 1, hf = (nj & 1) * 2;
                    mma16816(acc[mi][nj], ah[mi], bh[ni][hf], bh[ni][hf + 1]);
                    mma16816(acc[mi][nj], al[mi], bh[ni][hf], bh[ni][hf + 1]);
                    mma16816(acc[mi][nj], ah[mi], bl[ni][hf], bl[ni][hf + 1]);
                }
        }
        __syncthreads();
    }

    int g = lane >> 2, t4 = lane & 3;
#pragma unroll
    for (int mi = 0; mi < 4; mi++) {
        int r0 = m0 + wm * 64 + mi * 16 + g;
#pragma unroll
        for (int nj = 0; nj < 4; nj++) {
            int cc = n0 + wn * 32 + nj * 8 + t4 * 2;
#pragma unroll
            for (int half = 0; half < 2; half++) {
                int m = r0 + half * 8;
                float v0 = acc[mi][nj][half * 2 + 0];
                float v1 = acc[mi][nj][half * 2 + 1];
                if (OUT) {
                    float2 o = make_float2(v0 + bias_o[cc], v1 + bias_o[cc + 1]);
                    *(float2*)(outp + (size_t)m * Dd + cc) = o;
                } else {
                    const float* bias = bp.b[z];
                    float scale = (z == 0) ? 0.125f : 1.0f;
                    v0 = (v0 + bias[cc]) * scale;
                    v1 = (v1 + bias[cc + 1]) * scale;
                    int b = m >> 12, s = m & 4095;
                    int h = cc >> 6, d0 = cc & 63;
                    size_t base = (((size_t)(b * Hh + h)) * Ss + s) * DHd + d0;
                    if (z >= 3) {
                        float* dstz = (z == 3) ? g_kg : g_vg;
                        *(float2*)(dstz + base) = make_float2(v0, v1);
                    } else {
                        uint32_t hi, lo;
                        pack_hilo(v0, v1, hi, lo);
                        __nv_bfloat16 *dh, *dl;
                        if (z == 0)      { dh = g_qhi; dl = g_qlo; }
                        else if (z == 1) { dh = g_khi; dl = g_klo; }
                        else             { dh = g_vhi; dl = g_vlo; }
                        *(uint32_t*)(dh + base) = hi;
                        *(uint32_t*)(dl + base) = lo;
                    }
                }
            }
        }
    }
}

// ================= local attention: register FA2 on mma.sync =================
// smem: kok[128]f @0 (pad to 1024) | Qhi 16K | Qlo | Khi | Klo | Vhi | Vlo
#define LA_KOK   0
#define LA_Q     1024
#define LA_QL    (LA_Q  + 16384)
#define LA_K     (LA_QL + 16384)
#define LA_KL    (LA_K  + 16384)
#define LA_VT    (LA_KL + 16384)
#define LA_VTL   (LA_VT + 16384)
#define LA_SMEM  (LA_VTL + 16384)

__global__ __launch_bounds__(256) void local_attn(const int* __restrict__ mask)
{
    extern __shared__ char smem[];
    uint32_t sb = smem_u32(smem);
    float* kok = (float*)(smem + LA_KOK);

    int n = blockIdx.x, h = blockIdx.y, b = blockIdx.z;
    int tid = threadIdx.x;
    int wid = tid >> 5, lane = tid & 31;
    int g = lane >> 2, t4 = lane & 3;
    int qr = wid * 16;

    size_t bhbase = ((size_t)(b * Hh + h)) * Ss * DHd;
    const __nv_bfloat16* qh_g = g_qhi + bhbase + (size_t)n * Ww * DHd;
    const __nv_bfloat16* ql_g = g_qlo + bhbase + (size_t)n * Ww * DHd;
    const __nv_bfloat16* kh_g = g_khi + bhbase;
    const __nv_bfloat16* kl_g = g_klo + bhbase;
    const __nv_bfloat16* vh_g = g_vhi + bhbase;
    const __nv_bfloat16* vl_g = g_vlo + bhbase;
    const int* mk = mask + b * Ss;

    // load Q (once)
#pragma unroll
    for (int it = 0; it < 4; it++) {
        int idx = tid + it * 256;
        int row = idx >> 3, cu = idx & 7;
        uint32_t sw = row * 128 + ((cu ^ (row & 7)) << 4);
        *(uint4*)(smem + LA_Q  + sw) = *(const uint4*)(qh_g + (size_t)row * DHd + cu * 8);
        *(uint4*)(smem + LA_QL + sw) = *(const uint4*)(ql_g + (size_t)row * DHd + cu * 8);
    }

    float sacc[16][4];
    float O[8][4];
#pragma unroll
    for (int j = 0; j < 8; j++)
#pragma unroll
        for (int q = 0; q < 4; q++) O[j][q] = 0.f;
    float m0 = -3.0e38f, m1 = -3.0e38f, l0 = 0.f, l1 = 0.f;

    int arow = qr + (lane & 15);
    uint32_t aboff = arow * 128;
    int arx = lane & 7;
    int alc = lane >> 4;
    int krow_in = (lane & 7) + 8 * ((lane >> 4) & 1);
    int kcc = (lane >> 3) & 1;
    // trans-B lane mapping for P.V
    int tkrow = (lane & 7) + 8 * ((lane >> 3) & 1);
    int tdu = lane >> 4;

    for (int c = 0; c < 4; c++) {
        int p0 = (n - 1) * Ww + c * Ww;
        __syncthreads();   // previous chunk fully consumed
        if (tid < 128) {
            bool ok;
            if (c == 3) ok = (tid < Gg) && (mk[tid] > 0);
            else { int p = p0 + tid; ok = (p >= Gg) && (p < Ss) && (mk[p] > 0); }
            kok[tid] = ok ? 1.f : 0.f;
        }
        // load K hi/lo and V hi/lo (both row-major swizzled)
#pragma unroll
        for (int it = 0; it < 4; it++) {
            int idx = tid + it * 256;
            int j = idx >> 3, cu = idx & 7;
            int p = (c == 3) ? j : (p0 + j);
            bool inr = (c == 3) ? (j < Gg) : (p >= 0 && p < Ss);
            uint4 kv = make_uint4(0, 0, 0, 0), kv2 = make_uint4(0, 0, 0, 0);
            uint4 vv = make_uint4(0, 0, 0, 0), vv2 = make_uint4(0, 0, 0, 0);
            if (inr) {
                size_t gb = (size_t)p * DHd + cu * 8;
                kv  = *(const uint4*)(kh_g + gb);
                kv2 = *(const uint4*)(kl_g + gb);
                vv  = *(const uint4*)(vh_g + gb);
                vv2 = *(const uint4*)(vl_g + gb);
            }
            uint32_t sw = j * 128 + ((cu ^ (j & 7)) << 4);
            *(uint4*)(smem + LA_K   + sw) = kv;
            *(uint4*)(smem + LA_KL  + sw) = kv2;
            *(uint4*)(smem + LA_VT  + sw) = vv;
            *(uint4*)(smem + LA_VTL + sw) = vv2;
        }
        __syncthreads();

        // ---- S = Q.K^T ----
#pragma unroll
        for (int j = 0; j < 16; j++)
#pragma unroll
            for (int q = 0; q < 4; q++) sacc[j][q] = 0.f;
#pragma unroll
        for (int ks = 0; ks < 4; ks++) {
            uint32_t qh4[4], ql4[4];
            uint32_t ac = ((uint32_t)(ks * 2 + alc) ^ arx) << 4;
            ldsm4(qh4, sb + LA_Q  + aboff + ac);
            ldsm4(ql4, sb + LA_QL + aboff + ac);
#pragma unroll
            for (int jj = 0; jj < 8; jj++) {
                uint32_t kh4[4], kl4[4];
                uint32_t kb = (16 * jj + krow_in) * 128 + (((uint32_t)(ks * 2 + kcc) ^ arx) << 4);
                ldsm4(kh4, sb + LA_K  + kb);
                ldsm4(kl4, sb + LA_KL + kb);
                mma16816(sacc[2 * jj],     qh4, kh4[0], kh4[1]);
                mma16816(sacc[2 * jj],     ql4, kh4[0], kh4[1]);
                mma16816(sacc[2 * jj],     qh4, kl4[0], kl4[1]);
                mma16816(sacc[2 * jj + 1], qh4, kh4[2], kh4[3]);
                mma16816(sacc[2 * jj + 1], ql4, kh4[2], kh4[3]);
                mma16816(sacc[2 * jj + 1], qh4, kl4[2], kl4[3]);
            }
        }

        // ---- mask ----
        int row0 = n * Ww + qr + g;
        int row1 = row0 + 8;
#pragma unroll
        for (int j = 0; j < 16; j++) {
#pragma unroll
            for (int q = 0; q < 4; q++) {
                int col = 8 * j + t4 * 2 + (q & 1);
                int row = (q >= 2) ? row1 : row0;
                bool ok = kok[col] > 0.f;
                if (c != 3) {
                    int rel = (p0 + col) - row;
                    ok = ok && (rel <= Ww) && (rel >= -Ww);
                }
                if (!ok) sacc[j][q] = NEGF;
            }
        }

        // ---- online softmax (registers) ----
        float mx0 = -3.0e38f, mx1 = -3.0e38f;
#pragma unroll
        for (int j = 0; j < 16; j++) {
            mx0 = fmaxf(mx0, fmaxf(sacc[j][0], sacc[j][1]));
            mx1 = fmaxf(mx1, fmaxf(sacc[j][2], sacc[j][3]));
        }
        mx0 = fmaxf(mx0, __shfl_xor_sync(0xffffffff, mx0, 1));
        mx0 = fmaxf(mx0, __shfl_xor_sync(0xffffffff, mx0, 2));
        mx1 = fmaxf(mx1, __shfl_xor_sync(0xffffffff, mx1, 1));
        mx1 = fmaxf(mx1, __shfl_xor_sync(0xffffffff, mx1, 2));
        float mn0 = fmaxf(m0, mx0), mn1 = fmaxf(m1, mx1);
        float f0 = __expf(m0 - mn0), f1 = __expf(m1 - mn1);
        float s0 = 0.f, s1 = 0.f;
#pragma unroll
        for (int j = 0; j < 16; j++) {
            float p0v = __expf(sacc[j][0] - mn0);
            float p1v = __expf(sacc[j][1] - mn0);
            float p2v = __expf(sacc[j][2] - mn1);
            float p3v = __expf(sacc[j][3] - mn1);
            sacc[j][0] = p0v; sacc[j][1] = p1v; sacc[j][2] = p2v; sacc[j][3] = p3v;
            s0 += p0v + p1v; s1 += p2v + p3v;
        }
        s0 += __shfl_xor_sync(0xffffffff, s0, 1);
        s0 += __shfl_xor_sync(0xffffffff, s0, 2);
        s1 += __shfl_xor_sync(0xffffffff, s1, 1);
        s1 += __shfl_xor_sync(0xffffffff, s1, 2);
        l0 = l0 * f0 + s0; l1 = l1 * f1 + s1;
        m0 = mn0; m1 = mn1;
#pragma unroll
        for (int j = 0; j < 8; j++) {
            O[j][0] *= f0; O[j][1] *= f0; O[j][2] *= f1; O[j][3] *= f1;
        }

        // ---- O += P.V (trans-loaded B from row-major V) ----
#pragma unroll
        for (int ks = 0; ks < 8; ks++) {
            uint32_t pah[4], pal[4];
            pack_hilo(sacc[2 * ks][0],     sacc[2 * ks][1],     pah[0], pal[0]);
            pack_hilo(sacc[2 * ks][2],     sacc[2 * ks][3],     pah[1], pal[1]);
            pack_hilo(sacc[2 * ks + 1][0], sacc[2 * ks + 1][1], pah[2], pal[2]);
            pack_hilo(sacc[2 * ks + 1][2], sacc[2 * ks + 1][3], pah[3], pal[3]);
#pragma unroll
            for (int jd = 0; jd < 4; jd++) {
                uint32_t vh4[4], vl4[4];
                uint32_t vb = (uint32_t)(16 * ks + tkrow) * 128 +
                              (((uint32_t)(jd * 2 + tdu) ^ (uint32_t)(lane & 7)) << 4);
                ldsm4t(vh4, sb + LA_VT  + vb);
                ldsm4t(vl4, sb + LA_VTL + vb);
                mma16816(O[2 * jd],     pah, vh4[0], vh4[1]);
                mma16816(O[2 * jd],     pal, vh4[0], vh4[1]);
                mma16816(O[2 * jd],     pah, vl4[0], vl4[1]);
                mma16816(O[2 * jd + 1], pah, vh4[2], vh4[3]);
                mma16816(O[2 * jd + 1], pal, vh4[2], vh4[3]);
                mma16816(O[2 * jd + 1], pah, vl4[2], vl4[3]);
            }
        }
    }

    // ---- write out ----
    float inv0 = 1.0f / l0, inv1 = 1.0f / l1;
    int s0r = n * Ww + qr + g;
    int s1r = s0r + 8;
    float* o0 = g_attn + ((size_t)b * Ss + s0r) * Dd + h * DHd;
    float* o1 = g_attn + ((size_t)b * Ss + s1r) * Dd + h * DHd;
#pragma unroll
    for (int jd = 0; jd < 8; jd++) {
        int cc = 8 * jd + t4 * 2;
        *(float2*)(o0 + cc) = make_float2(O[jd][0] * inv0, O[jd][1] * inv0);
        *(float2*)(o1 + cc) = make_float2(O[jd][2] * inv1, O[jd][3] * inv1);
    }
}

// ---------------- qg projection: intra-block split-K ----------------
// grid (32, 24): bg=(b,g), cc = 32-col group. tid = ks*32 + col32.
__global__ __launch_bounds__(256) void qg_proj(const float* __restrict__ x,
                                               const float* __restrict__ Wqg,
                                               const float* __restrict__ bqg)
{
    __shared__ float xr[768];
    __shared__ float sred[256];
    int bg = blockIdx.x, cc = blockIdx.y;
    int b = bg >> 4, g = bg & 15;
    int tid = threadIdx.x;
    for (int i = tid; i < 768; i += 256) xr[i] = x[((size_t)b * Ss + g) * Dd + i];
    __syncthreads();
    int col = cc * 32 + (tid & 31);
    int ks = tid >> 5;                 // 0..7, 96 k's each
    int k0 = ks * 96;
    float acc = 0.f;
#pragma unroll 8
    for (int k = 0; k < 96; k++)
        acc += xr[k0 + k] * Wqg[(size_t)(k0 + k) * 768 + col];
    sred[tid] = acc;
    __syncthreads();
    if (tid < 32) {
        float tot = 0.f;
#pragma unroll
        for (int j = 0; j < 8; j++) tot += sred[tid + 32 * j];
        int c = cc * 32 + tid;
        float vv = (tot + bqg[c]) * 0.125f;
        g_qg[(((size_t)b * Hh + (c >> 6)) * Gg + g) * DHd + (c & 63)] = vv;
    }
}

// ---------------- global-row attention: 32-way split, one chunk each ----------
__global__ __launch_bounds__(256) void gattn_part(const int* __restrict__ mask)
{
    extern __shared__ float sm[];
    float* Qgs  = sm;
    float* Kts  = Qgs + 16 * 68;
    float* Vs   = Kts + 64 * 132;
    float* Ps   = Vs + 128 * 68;
    float* rowm = Ps + 16 * 129;
    float* rowl = rowm + 16;

    int si = blockIdx.x, h = blockIdx.y, b = blockIdx.z;
    int tid = threadIdx.x;
    const float* kgb = g_kg + ((size_t)(b * Hh + h)) * Ss * DHd;
    const float* vgb = g_vg + ((size_t)(b * Hh + h)) * Ss * DHd;
    const int* mk = mask + b * Ss;

    for (int i = tid; i < 16 * 64; i += 256) {
        int r = i >> 6, d = i & 63;
        Qgs[r * 68 + d] = g_qg[(((size_t)b * Hh + h) * Gg + r) * DHd + d];
    }

    int p0 = si * 128;
    int r = tid >> 4, cg = tid & 15;
#pragma unroll
    for (int it = 0; it < 8; it++) {
        int idx = tid + it * 256;
        int j = idx >> 4, cv = idx & 15;
        int p = p0 + j;
        float4 kv = *(const float4*)(kgb + (size_t)p * 64 + cv * 4);
        float4 vv = *(const float4*)(vgb + (size_t)p * 64 + cv * 4);
        Kts[(cv * 4 + 0) * 132 + j] = kv.x;
        Kts[(cv * 4 + 1) * 132 + j] = kv.y;
        Kts[(cv * 4 + 2) * 132 + j] = kv.z;
        Kts[(cv * 4 + 3) * 132 + j] = kv.w;
        *(float4*)&Vs[j * 68 + cv * 4] = vv;
    }
    __syncthreads();

    float sc8[8] = {0.f, 0.f, 0.f, 0.f, 0.f, 0.f, 0.f, 0.f};
#pragma unroll 8
    for (int d = 0; d < 64; d++) {
        float a = Qgs[r * 68 + d];
#pragma unroll
        for (int j = 0; j < 8; j++) sc8[j] += a * Kts[d * 132 + cg * 8 + j];
    }
#pragma unroll
    for (int j = 0; j < 8; j++) {
        int p = p0 + cg * 8 + j;
        Ps[r * 129 + cg * 8 + j] = (mk[p] > 0) ? sc8[j] : NEGF;
    }
    __syncthreads();

    if (tid < 16) {
        float cm = -3.0e38f;
        for (int j2 = 0; j2 < 128; j2++) cm = fmaxf(cm, Ps[tid * 129 + j2]);
        float ls = 0.f;
        for (int j2 = 0; j2 < 128; j2++) {
            float pv = __expf(Ps[tid * 129 + j2] - cm);
            Ps[tid * 129 + j2] = pv;
            ls += pv;
        }
        rowm[tid] = cm;
        rowl[tid] = ls;
    }
    __syncthreads();

    float oacc[4] = {0.f, 0.f, 0.f, 0.f};
    for (int kk = 0; kk < 128; kk++) {
        float a = Ps[r * 129 + kk];
#pragma unroll
        for (int j = 0; j < 4; j++) oacc[j] += a * Vs[kk * 68 + cg * 4 + j];
    }
    int part = (b * Hh + h) * NSPLIT + si;
#pragma unroll
    for (int j = 0; j < 4; j++)
        g_pacc[((size_t)part * 16 + r) * 64 + cg * 4 + j] = oacc[j];
    if (cg == 0) {
        g_pm[part * 16 + r] = rowm[r];
        g_pl[part * 16 + r] = rowl[r];
    }
}

__global__ __launch_bounds__(64) void gattn_combine()
{
    int bh = blockIdx.x;
    int b = bh / Hh, h = bh % Hh;
    int d = threadIdx.x;
    for (int r = 0; r < Gg; r++) {
        float M = -3.0e38f;
        for (int si = 0; si < NSPLIT; si++)
            M = fmaxf(M, g_pm[((b * Hh + h) * NSPLIT + si) * 16 + r]);
        float L = 0.f, a = 0.f;
        for (int si = 0; si < NSPLIT; si++) {
            int part = (b * Hh + h) * NSPLIT + si;
            float w = __expf(g_pm[part * 16 + r] - M);
            L += w * g_pl[part * 16 + r];
            a += w * g_pacc[((size_t)part * 16 + r) * 64 + d];
        }
        g_attn[((size_t)b * Ss + r) * Dd + h * DHd + d] = a / L;
    }
}

// ---------------- launch ----------------
extern "C" void kernel_launch(void* const* d_in, const int* in_sizes, int n_in,
                              void* d_out, int out_size)
{
    (void)in_sizes; (void)n_in; (void)out_size;
    const float* x    = (const float*)d_in[0];
    const int*   mask = (const int*)d_in[1];
    W6 w6;
    w6.w[0] = (const float*)d_in[2];   // Wq
    w6.w[1] = (const float*)d_in[4];   // Wk
    w6.w[2] = (const float*)d_in[6];   // Wv
    w6.w[3] = (const float*)d_in[10];  // Wkg
    w6.w[4] = (const float*)d_in[12];  // Wvg
    w6.w[5] = (const float*)d_in[14];  // Wo
    Bia5 b5;
    b5.b[0] = (const float*)d_in[3];
    b5.b[1] = (const float*)d_in[5];
    b5.b[2] = (const float*)d_in[7];
    b5.b[3] = (const float*)d_in[11];
    b5.b[4] = (const float*)d_in[13];
    const float* Wqg = (const float*)d_in[8];
    const float* bqg = (const float*)d_in[9];
    const float* bo  = (const float*)d_in[15];
    float* out = (float*)d_out;

    int gsm = (16 * 68 + 64 * 132 + 128 * 68 + 16 * 129 + 2 * 16) * 4;
    cudaFuncSetAttribute(gattn_part, cudaFuncAttributeMaxDynamicSharedMemorySize, gsm);
    cudaFuncSetAttribute(mma_gemm<false>, cudaFuncAttributeMaxDynamicSharedMemorySize, GEMM_SMEM);
    cudaFuncSetAttribute(mma_gemm<true>,  cudaFuncAttributeMaxDynamicSharedMemorySize, GEMM_SMEM);
    cudaFuncSetAttribute(local_attn, cudaFuncAttributeMaxDynamicSharedMemorySize, LA_SMEM);

    __nv_bfloat16 *xhi, *xlo, *ahi, *alo;
    cudaGetSymbolAddress((void**)&xhi, g_xhi);
    cudaGetSymbolAddress((void**)&xlo, g_xlo);
    cudaGetSymbolAddress((void**)&ahi, g_ahi);
    cudaGetSymbolAddress((void**)&alo, g_alo);
    float* attn;
    cudaGetSymbolAddress((void**)&attn, g_attn);

    int n4 = Bb * Ss * Dd / 4;
    to_bf16_split<<<(n4 + 255) / 256, 256>>>(x, xhi, xlo, n4);           // 1
    prep_w<<<dim3(24, 24, 6), dim3(32, 8)>>>(w6);                        // 2
    mma_gemm<false><<<dim3(6, 64, 5), 256, GEMM_SMEM>>>(xhi, xlo, b5, nullptr, nullptr); // 3
    local_attn<<<dim3(NBb, Hh, Bb), 256, LA_SMEM>>>(mask);               // 4 (profiled)
    qg_proj<<<dim3(Bb * Gg, 24), 256>>>(x, Wqg, bqg);                    // 5
    gattn_part<<<dim3(NSPLIT, Hh, Bb), 256, gsm>>>(mask);                // 6
    gattn_combine<<<Bb * Hh, 64>>>();                                    // 7
    to_bf16_split<<<(n4 + 255) / 256, 256>>>(attn, ahi, alo, n4);        // 8
    mma_gemm<true><<<dim3(6, 64), 256, GEMM_SMEM>>>(ahi, alo, b5, bo, out); // 9
}

// round 8
// speedup vs baseline: 2.4318x; 1.1639x over previous
#include <cuda_runtime.h>
#include <cuda_bf16.h>
#include <cstdint>

#define Bb 2
#define Ss 4096
#define Dd 768
#define Hh 12
#define DHd 64
#define Ww 128
#define Gg 16
#define NBb 32
#define NSPLIT 32
#define NEGF (-1.0e9f)

// ---------------- scratch (device globals; no allocation) ----------------
__device__ float g_kg[Bb*Hh*Ss*DHd];
__device__ float g_vg[Bb*Hh*Ss*DHd];
__device__ float g_qg[Bb*Hh*Gg*DHd];
__device__ float g_pm  [Bb*Hh*NSPLIT*Gg];
__device__ float g_pl  [Bb*Hh*NSPLIT*Gg];
__device__ float g_pacc[Bb*Hh*NSPLIT*Gg*DHd];

__device__ __nv_bfloat16 g_xhi[Bb*Ss*Dd];
__device__ __nv_bfloat16 g_xlo[Bb*Ss*Dd];
__device__ __nv_bfloat16 g_ahi[Bb*Ss*Dd];
__device__ __nv_bfloat16 g_alo[Bb*Ss*Dd];
__device__ __nv_bfloat16 g_wthi[6*Dd*Dd];
__device__ __nv_bfloat16 g_wtlo[6*Dd*Dd];
__device__ __nv_bfloat16 g_qhi[Bb*Hh*Ss*DHd];
__device__ __nv_bfloat16 g_qlo[Bb*Hh*Ss*DHd];
__device__ __nv_bfloat16 g_khi[Bb*Hh*Ss*DHd];
__device__ __nv_bfloat16 g_klo[Bb*Hh*Ss*DHd];
__device__ __nv_bfloat16 g_vhi[Bb*Hh*Ss*DHd];
__device__ __nv_bfloat16 g_vlo[Bb*Hh*Ss*DHd];

struct W6   { const float* w[6]; };
struct Bia5 { const float* b[5]; };

// ================= warp-MMA helpers =================
#define SWZ(o) ((o) ^ (((o) >> 3) & 0x70))

__device__ __forceinline__ uint32_t smem_u32(const void* p) {
    uint32_t a;
    asm("{ .reg .u64 t; cvta.to.shared.u64 t, %1; cvt.u32.u64 %0, t; }" : "=r"(a) : "l"(p));
    return a;
}
__device__ __forceinline__ void ldsm4(uint32_t* r, uint32_t addr) {
    asm volatile("ldmatrix.sync.aligned.m8n8.x4.shared.b16 {%0,%1,%2,%3}, [%4];"
                 : "=r"(r[0]), "=r"(r[1]), "=r"(r[2]), "=r"(r[3]) : "r"(addr));
}
__device__ __forceinline__ void ldsm4t(uint32_t* r, uint32_t addr) {
    asm volatile("ldmatrix.sync.aligned.m8n8.x4.trans.shared.b16 {%0,%1,%2,%3}, [%4];"
                 : "=r"(r[0]), "=r"(r[1]), "=r"(r[2]), "=r"(r[3]) : "r"(addr));
}
__device__ __forceinline__ void mma16816(float* d, const uint32_t* a, uint32_t b0, uint32_t b1) {
    asm volatile(
        "mma.sync.aligned.m16n8k16.row.col.f32.bf16.bf16.f32 "
        "{%0,%1,%2,%3}, {%4,%5,%6,%7}, {%8,%9}, {%0,%1,%2,%3};"
        : "+f"(d[0]), "+f"(d[1]), "+f"(d[2]), "+f"(d[3])
        : "r"(a[0]), "r"(a[1]), "r"(a[2]), "r"(a[3]), "r"(b0), "r"(b1));
}
__device__ __forceinline__ void pack_hilo(float e0, float e1, uint32_t& hi, uint32_t& lo) {
    __nv_bfloat162 h = __floats2bfloat162_rn(e0, e1);
    float r0 = e0 - __bfloat162float(h.x);
    float r1 = e1 - __bfloat162float(h.y);
    __nv_bfloat162 l2 = __floats2bfloat162_rn(r0, r1);
    hi = *(uint32_t*)&h;
    lo = *(uint32_t*)&l2;
}
__device__ __forceinline__ void cpasync16(uint32_t dst, const void* src) {
    asm volatile("cp.async.cg.shared.global [%0], [%1], 16;" :: "r"(dst), "l"(src) : "memory");
}

// ================= prep kernels =================
__global__ __launch_bounds__(256) void to_bf16_split(const float* __restrict__ in,
                                                     __nv_bfloat16* __restrict__ hi,
                                                     __nv_bfloat16* __restrict__ lo, int n4)
{
    int i = blockIdx.x * 256 + threadIdx.x;
    if (i >= n4) return;
    float4 v = ((const float4*)in)[i];
    float vv[4] = {v.x, v.y, v.z, v.w};
    union { __nv_bfloat16 h[4]; uint2 u; } uh, ul;
#pragma unroll
    for (int j = 0; j < 4; j++) {
        __nv_bfloat16 h = __float2bfloat16(vv[j]);
        uh.h[j] = h;
        ul.h[j] = __float2bfloat16(vv[j] - __bfloat162float(h));
    }
    *(uint2*)(hi + (size_t)i * 4) = uh.u;
    *(uint2*)(lo + (size_t)i * 4) = ul.u;
}

__global__ __launch_bounds__(256) void prep_w(W6 ws)
{
    __shared__ float t[32][33];
    int z = blockIdx.z;
    const float* W = ws.w[z];
    __nv_bfloat16* oh = g_wthi + (size_t)z * Dd * Dd;
    __nv_bfloat16* ol = g_wtlo + (size_t)z * Dd * Dd;
    int k0 = blockIdx.x * 32, n0 = blockIdx.y * 32;
    int tx = threadIdx.x, ty = threadIdx.y;
#pragma unroll
    for (int r = 0; r < 4; r++)
        t[ty + r * 8][tx] = W[(size_t)(k0 + ty + r * 8) * Dd + n0 + tx];
    __syncthreads();
#pragma unroll
    for (int r = 0; r < 4; r++) {
        float v = t[tx][ty + r * 8];
        __nv_bfloat16 h = __float2bfloat16(v);
        size_t o = (size_t)(n0 + ty + r * 8) * Dd + k0 + tx;
        oh[o] = h;
        ol[o] = __float2bfloat16(v - __bfloat162float(h));
    }
}

// ===== bf16 mma.sync GEMM v2: 512 thr, 32x32 warp tiles, cp.async 2-stage =====
#define GEMM_SMEM 131072

template<bool OUT>
__global__ __launch_bounds__(512)
void mma_gemm(const __nv_bfloat16* __restrict__ Ahi, const __nv_bfloat16* __restrict__ Alo,
              Bia5 bp, const float* __restrict__ bias_o, float* __restrict__ outp)
{
    extern __shared__ char smem[];
    uint32_t sb = smem_u32(smem);
    int tid = threadIdx.x;
    int wid = tid >> 5, lane = tid & 31;
    int wm = wid >> 2, wn = wid & 3;          // 4x4 warps, 32x32 tile each
    int z = OUT ? 5 : blockIdx.z;
    int n0 = blockIdx.x * 128, m0 = blockIdx.y * 128;

    const __nv_bfloat16* Bhi = g_wthi + (size_t)z * Dd * Dd;
    const __nv_bfloat16* Blo = g_wtlo + (size_t)z * Dd * Dd;
    const __nv_bfloat16* srcs[4] = {
        Ahi + (size_t)m0 * Dd, Alo + (size_t)m0 * Dd,
        Bhi + (size_t)n0 * Dd, Blo + (size_t)n0 * Dd };

    float acc[2][4][4];
#pragma unroll
    for (int i = 0; i < 2; i++)
#pragma unroll
        for (int j = 0; j < 4; j++)
#pragma unroll
            for (int q = 0; q < 4; q++) acc[i][j][q] = 0.f;

    int alr = lane & 15, alc = lane >> 4, arx = lane & 7;
    uint32_t aoff[2];
#pragma unroll
    for (int mi = 0; mi < 2; mi++) aoff[mi] = (wm * 32 + mi * 16 + alr) * 128;
    int blr = (lane & 7) + ((lane >> 4) & 1) * 8;
    int blc = (lane >> 3) & 1, brx = lane & 7;
    uint32_t boff[2];
#pragma unroll
    for (int ni = 0; ni < 2; ni++) boff[ni] = (wn * 32 + ni * 16 + blr) * 128;

    // stage loader: 4 tiles x 16KB, 4096 x 16B, 512 threads -> 8 each
    auto load_stage = [&](int c, int s) {
        int k0 = c * 64;
        uint32_t base = sb + s * 65536;
#pragma unroll
        for (int t = 0; t < 4; t++) {
            const __nv_bfloat16* sp = srcs[t] + k0;
            uint32_t tp = base + t * 16384;
#pragma unroll
            for (int it = 0; it < 2; it++) {
                int idx = tid + it * 512;
                int row = idx >> 3, cu = idx & 7;
                cpasync16(tp + SWZ(row * 128 + cu * 16), sp + (size_t)row * Dd + cu * 8);
            }
        }
    };

    load_stage(0, 0);
    asm volatile("cp.async.commit_group;" ::: "memory");

    for (int c = 0; c < 12; c++) {
        if (c < 11) {
            load_stage(c + 1, (c + 1) & 1);
            asm volatile("cp.async.commit_group;" ::: "memory");
            asm volatile("cp.async.wait_group 1;" ::: "memory");
        } else {
            asm volatile("cp.async.wait_group 0;" ::: "memory");
        }
        __syncthreads();
        uint32_t sA = sb + (c & 1) * 65536;
        uint32_t sAl = sA + 16384, sB = sA + 32768, sBl = sA + 49152;
#pragma unroll
        for (int ks = 0; ks < 4; ks++) {
            uint32_t ah[2][4], al[2][4], bh[2][4], bl[2][4];
            uint32_t ac = ((uint32_t)(ks * 2 + alc) ^ arx) << 4;
            uint32_t bc = ((uint32_t)(ks * 2 + blc) ^ brx) << 4;
#pragma unroll
            for (int mi = 0; mi < 2; mi++) {
                ldsm4(ah[mi], sA  + aoff[mi] + ac);
                ldsm4(al[mi], sAl + aoff[mi] + ac);
            }
#pragma unroll
            for (int ni = 0; ni < 2; ni++) {
                ldsm4(bh[ni], sB  + boff[ni] + bc);
                ldsm4(bl[ni], sBl + boff[ni] + bc);
            }
#pragma unroll
            for (int mi = 0; mi < 2; mi++)
#pragma unroll
                for (int nj = 0; nj < 4; nj++) {
                    int ni = nj >> 1, hf = (nj & 1) * 2;
                    mma16816(acc[mi][nj], ah[mi], bh[ni][hf], bh[ni][hf + 1]);
                    mma16816(acc[mi][nj], al[mi], bh[ni][hf], bh[ni][hf + 1]);
                    mma16816(acc[mi][nj], ah[mi], bl[ni][hf], bl[ni][hf + 1]);
                }
        }
        __syncthreads();
    }

    int g = lane >> 2, t4 = lane & 3;
#pragma unroll
    for (int mi = 0; mi < 2; mi++) {
        int r0 = m0 + wm * 32 + mi * 16 + g;
#pragma unroll
        for (int nj = 0; nj < 4; nj++) {
            int cc = n0 + wn * 32 + nj * 8 + t4 * 2;
#pragma unroll
            for (int half = 0; half < 2; half++) {
                int m = r0 + half * 8;
                float v0 = acc[mi][nj][half * 2 + 0];
                float v1 = acc[mi][nj][half * 2 + 1];
                if (OUT) {
                    float2 o = make_float2(v0 + bias_o[cc], v1 + bias_o[cc + 1]);
                    *(float2*)(outp + (size_t)m * Dd + cc) = o;
                } else {
                    const float* bias = bp.b[z];
                    float scale = (z == 0) ? 0.125f : 1.0f;
                    v0 = (v0 + bias[cc]) * scale;
                    v1 = (v1 + bias[cc + 1]) * scale;
                    int b = m >> 12, s = m & 4095;
                    int h = cc >> 6, d0 = cc & 63;
                    size_t base = (((size_t)(b * Hh + h)) * Ss + s) * DHd + d0;
                    if (z >= 3) {
                        float* dstz = (z == 3) ? g_kg : g_vg;
                        *(float2*)(dstz + base) = make_float2(v0, v1);
                    } else {
                        uint32_t hi, lo;
                        pack_hilo(v0, v1, hi, lo);
                        __nv_bfloat16 *dh, *dl;
                        if (z == 0)      { dh = g_qhi; dl = g_qlo; }
                        else if (z == 1) { dh = g_khi; dl = g_klo; }
                        else             { dh = g_vhi; dl = g_vlo; }
                        *(uint32_t*)(dh + base) = hi;
                        *(uint32_t*)(dl + base) = lo;
                    }
                }
            }
        }
    }
}

// ================= local attention: register FA2 on mma.sync =================
#define LA_KOK   0
#define LA_Q     1024
#define LA_QL    (LA_Q  + 16384)
#define LA_K     (LA_QL + 16384)
#define LA_KL    (LA_K  + 16384)
#define LA_VT    (LA_KL + 16384)
#define LA_VTL   (LA_VT + 16384)
#define LA_SMEM  (LA_VTL + 16384)

__global__ __launch_bounds__(256) void local_attn(const int* __restrict__ mask)
{
    extern __shared__ char smem[];
    uint32_t sb = smem_u32(smem);
    float* kok = (float*)(smem + LA_KOK);

    int n = blockIdx.x, h = blockIdx.y, b = blockIdx.z;
    int tid = threadIdx.x;
    int wid = tid >> 5, lane = tid & 31;
    int g = lane >> 2, t4 = lane & 3;
    int qr = wid * 16;

    size_t bhbase = ((size_t)(b * Hh + h)) * Ss * DHd;
    const __nv_bfloat16* qh_g = g_qhi + bhbase + (size_t)n * Ww * DHd;
    const __nv_bfloat16* ql_g = g_qlo + bhbase + (size_t)n * Ww * DHd;
    const __nv_bfloat16* kh_g = g_khi + bhbase;
    const __nv_bfloat16* kl_g = g_klo + bhbase;
    const __nv_bfloat16* vh_g = g_vhi + bhbase;
    const __nv_bfloat16* vl_g = g_vlo + bhbase;
    const int* mk = mask + b * Ss;

#pragma unroll
    for (int it = 0; it < 4; it++) {
        int idx = tid + it * 256;
        int row = idx >> 3, cu = idx & 7;
        uint32_t sw = row * 128 + ((cu ^ (row & 7)) << 4);
        *(uint4*)(smem + LA_Q  + sw) = *(const uint4*)(qh_g + (size_t)row * DHd + cu * 8);
        *(uint4*)(smem + LA_QL + sw) = *(const uint4*)(ql_g + (size_t)row * DHd + cu * 8);
    }

    float sacc[16][4];
    float O[8][4];
#pragma unroll
    for (int j = 0; j < 8; j++)
#pragma unroll
        for (int q = 0; q < 4; q++) O[j][q] = 0.f;
    float m0 = -3.0e38f, m1 = -3.0e38f, l0 = 0.f, l1 = 0.f;

    int arow = qr + (lane & 15);
    uint32_t aboff = arow * 128;
    int arx = lane & 7;
    int alc = lane >> 4;
    int krow_in = (lane & 7) + 8 * ((lane >> 4) & 1);
    int kcc = (lane >> 3) & 1;
    int tkrow = (lane & 7) + 8 * ((lane >> 3) & 1);
    int tdu = lane >> 4;

    for (int c = 0; c < 4; c++) {
        int p0 = (n - 1) * Ww + c * Ww;
        __syncthreads();
        if (tid < 128) {
            bool ok;
            if (c == 3) ok = (tid < Gg) && (mk[tid] > 0);
            else { int p = p0 + tid; ok = (p >= Gg) && (p < Ss) && (mk[p] > 0); }
            kok[tid] = ok ? 1.f : 0.f;
        }
#pragma unroll
        for (int it = 0; it < 4; it++) {
            int idx = tid + it * 256;
            int j = idx >> 3, cu = idx & 7;
            int p = (c == 3) ? j : (p0 + j);
            bool inr = (c == 3) ? (j < Gg) : (p >= 0 && p < Ss);
            uint4 kv = make_uint4(0, 0, 0, 0), kv2 = make_uint4(0, 0, 0, 0);
            uint4 vv = make_uint4(0, 0, 0, 0), vv2 = make_uint4(0, 0, 0, 0);
            if (inr) {
                size_t gb = (size_t)p * DHd + cu * 8;
                kv  = *(const uint4*)(kh_g + gb);
                kv2 = *(const uint4*)(kl_g + gb);
                vv  = *(const uint4*)(vh_g + gb);
                vv2 = *(const uint4*)(vl_g + gb);
            }
            uint32_t sw = j * 128 + ((cu ^ (j & 7)) << 4);
            *(uint4*)(smem + LA_K   + sw) = kv;
            *(uint4*)(smem + LA_KL  + sw) = kv2;
            *(uint4*)(smem + LA_VT  + sw) = vv;
            *(uint4*)(smem + LA_VTL + sw) = vv2;
        }
        __syncthreads();

#pragma unroll
        for (int j = 0; j < 16; j++)
#pragma unroll
            for (int q = 0; q < 4; q++) sacc[j][q] = 0.f;
#pragma unroll
        for (int ks = 0; ks < 4; ks++) {
            uint32_t qh4[4], ql4[4];
            uint32_t ac = ((uint32_t)(ks * 2 + alc) ^ arx) << 4;
            ldsm4(qh4, sb + LA_Q  + aboff + ac);
            ldsm4(ql4, sb + LA_QL + aboff + ac);
#pragma unroll
            for (int jj = 0; jj < 8; jj++) {
                uint32_t kh4[4], kl4[4];
                uint32_t kb = (16 * jj + krow_in) * 128 + (((uint32_t)(ks * 2 + kcc) ^ arx) << 4);
                ldsm4(kh4, sb + LA_K  + kb);
                ldsm4(kl4, sb + LA_KL + kb);
                mma16816(sacc[2 * jj],     qh4, kh4[0], kh4[1]);
                mma16816(sacc[2 * jj],     ql4, kh4[0], kh4[1]);
                mma16816(sacc[2 * jj],     qh4, kl4[0], kl4[1]);
                mma16816(sacc[2 * jj + 1], qh4, kh4[2], kh4[3]);
                mma16816(sacc[2 * jj + 1], ql4, kh4[2], kh4[3]);
                mma16816(sacc[2 * jj + 1], qh4, kl4[2], kl4[3]);
            }
        }

        int row0 = n * Ww + qr + g;
        int row1 = row0 + 8;
#pragma unroll
        for (int j = 0; j < 16; j++) {
#pragma unroll
            for (int q = 0; q < 4; q++) {
                int col = 8 * j + t4 * 2 + (q & 1);
                int row = (q >= 2) ? row1 : row0;
                bool ok = kok[col] > 0.f;
                if (c != 3) {
                    int rel = (p0 + col) - row;
                    ok = ok && (rel <= Ww) && (rel >= -Ww);
                }
                if (!ok) sacc[j][q] = NEGF;
            }
        }

        float mx0 = -3.0e38f, mx1 = -3.0e38f;
#pragma unroll
        for (int j = 0; j < 16; j++) {
            mx0 = fmaxf(mx0, fmaxf(sacc[j][0], sacc[j][1]));
            mx1 = fmaxf(mx1, fmaxf(sacc[j][2], sacc[j][3]));
        }
        mx0 = fmaxf(mx0, __shfl_xor_sync(0xffffffff, mx0, 1));
        mx0 = fmaxf(mx0, __shfl_xor_sync(0xffffffff, mx0, 2));
        mx1 = fmaxf(mx1, __shfl_xor_sync(0xffffffff, mx1, 1));
        mx1 = fmaxf(mx1, __shfl_xor_sync(0xffffffff, mx1, 2));
        float mn0 = fmaxf(m0, mx0), mn1 = fmaxf(m1, mx1);
        float f0 = __expf(m0 - mn0), f1 = __expf(m1 - mn1);
        float s0 = 0.f, s1 = 0.f;
#pragma unroll
        for (int j = 0; j < 16; j++) {
            float p0v = __expf(sacc[j][0] - mn0);
            float p1v = __expf(sacc[j][1] - mn0);
            float p2v = __expf(sacc[j][2] - mn1);
            float p3v = __expf(sacc[j][3] - mn1);
            sacc[j][0] = p0v; sacc[j][1] = p1v; sacc[j][2] = p2v; sacc[j][3] = p3v;
            s0 += p0v + p1v; s1 += p2v + p3v;
        }
        s0 += __shfl_xor_sync(0xffffffff, s0, 1);
        s0 += __shfl_xor_sync(0xffffffff, s0, 2);
        s1 += __shfl_xor_sync(0xffffffff, s1, 1);
        s1 += __shfl_xor_sync(0xffffffff, s1, 2);
        l0 = l0 * f0 + s0; l1 = l1 * f1 + s1;
        m0 = mn0; m1 = mn1;
#pragma unroll
        for (int j = 0; j < 8; j++) {
            O[j][0] *= f0; O[j][1] *= f0; O[j][2] *= f1; O[j][3] *= f1;
        }

#pragma unroll
        for (int ks = 0; ks < 8; ks++) {
            uint32_t pah[4], pal[4];
            pack_hilo(sacc[2 * ks][0],     sacc[2 * ks][1],     pah[0], pal[0]);
            pack_hilo(sacc[2 * ks][2],     sacc[2 * ks][3],     pah[1], pal[1]);
            pack_hilo(sacc[2 * ks + 1][0], sacc[2 * ks + 1][1], pah[2], pal[2]);
            pack_hilo(sacc[2 * ks + 1][2], sacc[2 * ks + 1][3], pah[3], pal[3]);
#pragma unroll
            for (int jd = 0; jd < 4; jd++) {
                uint32_t vh4[4], vl4[4];
                uint32_t vb = (uint32_t)(16 * ks + tkrow) * 128 +
                              (((uint32_t)(jd * 2 + tdu) ^ (uint32_t)(lane & 7)) << 4);
                ldsm4t(vh4, sb + LA_VT  + vb);
                ldsm4t(vl4, sb + LA_VTL + vb);
                mma16816(O[2 * jd],     pah, vh4[0], vh4[1]);
                mma16816(O[2 * jd],     pal, vh4[0], vh4[1]);
                mma16816(O[2 * jd],     pah, vl4[0], vl4[1]);
                mma16816(O[2 * jd + 1], pah, vh4[2], vh4[3]);
                mma16816(O[2 * jd + 1], pal, vh4[2], vh4[3]);
                mma16816(O[2 * jd + 1], pah, vl4[2], vl4[3]);
            }
        }
    }

    // ---- write out directly as bf16 hi/lo (feeds out-proj GEMM) ----
    float inv0 = 1.0f / l0, inv1 = 1.0f / l1;
    int s0r = n * Ww + qr + g;
    int s1r = s0r + 8;
    size_t b0 = ((size_t)b * Ss + s0r) * Dd + h * DHd;
    size_t b1 = ((size_t)b * Ss + s1r) * Dd + h * DHd;
#pragma unroll
    for (int jd = 0; jd < 8; jd++) {
        int cc = 8 * jd + t4 * 2;
        uint32_t hi, lo;
        pack_hilo(O[jd][0] * inv0, O[jd][1] * inv0, hi, lo);
        *(uint32_t*)(g_ahi + b0 + cc) = hi;
        *(uint32_t*)(g_alo + b0 + cc) = lo;
        pack_hilo(O[jd][2] * inv1, O[jd][3] * inv1, hi, lo);
        *(uint32_t*)(g_ahi + b1 + cc) = hi;
        *(uint32_t*)(g_alo + b1 + cc) = lo;
    }
}

// ---------------- qg projection: intra-block split-K ----------------
__global__ __launch_bounds__(256) void qg_proj(const float* __restrict__ x,
                                               const float* __restrict__ Wqg,
                                               const float* __restrict__ bqg)
{
    __shared__ float xr[768];
    __shared__ float sred[256];
    int bg = blockIdx.x, cc = blockIdx.y;
    int b = bg >> 4, g = bg & 15;
    int tid = threadIdx.x;
    for (int i = tid; i < 768; i += 256) xr[i] = x[((size_t)b * Ss + g) * Dd + i];
    __syncthreads();
    int col = cc * 32 + (tid & 31);
    int ks = tid >> 5;
    int k0 = ks * 96;
    float acc = 0.f;
#pragma unroll 8
    for (int k = 0; k < 96; k++)
        acc += xr[k0 + k] * Wqg[(size_t)(k0 + k) * 768 + col];
    sred[tid] = acc;
    __syncthreads();
    if (tid < 32) {
        float tot = 0.f;
#pragma unroll
        for (int j = 0; j < 8; j++) tot += sred[tid + 32 * j];
        int c = cc * 32 + tid;
        float vv = (tot + bqg[c]) * 0.125f;
        g_qg[(((size_t)b * Hh + (c >> 6)) * Gg + g) * DHd + (c & 63)] = vv;
    }
}

// ---------------- global-row attention: 32-way split ----------------
__global__ __launch_bounds__(256) void gattn_part(const int* __restrict__ mask)
{
    extern __shared__ float sm[];
    float* Qgs  = sm;
    float* Kts  = Qgs + 16 * 68;
    float* Vs   = Kts + 64 * 132;
    float* Ps   = Vs + 128 * 68;
    float* rowm = Ps + 16 * 129;
    float* rowl = rowm + 16;

    int si = blockIdx.x, h = blockIdx.y, b = blockIdx.z;
    int tid = threadIdx.x;
    const float* kgb = g_kg + ((size_t)(b * Hh + h)) * Ss * DHd;
    const float* vgb = g_vg + ((size_t)(b * Hh + h)) * Ss * DHd;
    const int* mk = mask + b * Ss;

    for (int i = tid; i < 16 * 64; i += 256) {
        int r = i >> 6, d = i & 63;
        Qgs[r * 68 + d] = g_qg[(((size_t)b * Hh + h) * Gg + r) * DHd + d];
    }

    int p0 = si * 128;
    int r = tid >> 4, cg = tid & 15;
#pragma unroll
    for (int it = 0; it < 8; it++) {
        int idx = tid + it * 256;
        int j = idx >> 4, cv = idx & 15;
        int p = p0 + j;
        float4 kv = *(const float4*)(kgb + (size_t)p * 64 + cv * 4);
        float4 vv = *(const float4*)(vgb + (size_t)p * 64 + cv * 4);
        Kts[(cv * 4 + 0) * 132 + j] = kv.x;
        Kts[(cv * 4 + 1) * 132 + j] = kv.y;
        Kts[(cv * 4 + 2) * 132 + j] = kv.z;
        Kts[(cv * 4 + 3) * 132 + j] = kv.w;
        *(float4*)&Vs[j * 68 + cv * 4] = vv;
    }
    __syncthreads();

    float sc8[8] = {0.f, 0.f, 0.f, 0.f, 0.f, 0.f, 0.f, 0.f};
#pragma unroll 8
    for (int d = 0; d < 64; d++) {
        float a = Qgs[r * 68 + d];
#pragma unroll
        for (int j = 0; j < 8; j++) sc8[j] += a * Kts[d * 132 + cg * 8 + j];
    }
#pragma unroll
    for (int j = 0; j < 8; j++) {
        int p = p0 + cg * 8 + j;
        Ps[r * 129 + cg * 8 + j] = (mk[p] > 0) ? sc8[j] : NEGF;
    }
    __syncthreads();

    if (tid < 16) {
        float cm = -3.0e38f;
        for (int j2 = 0; j2 < 128; j2++) cm = fmaxf(cm, Ps[tid * 129 + j2]);
        float ls = 0.f;
        for (int j2 = 0; j2 < 128; j2++) {
            float pv = __expf(Ps[tid * 129 + j2] - cm);
            Ps[tid * 129 + j2] = pv;
            ls += pv;
        }
        rowm[tid] = cm;
        rowl[tid] = ls;
    }
    __syncthreads();

    float oacc[4] = {0.f, 0.f, 0.f, 0.f};
    for (int kk = 0; kk < 128; kk++) {
        float a = Ps[r * 129 + kk];
#pragma unroll
        for (int j = 0; j < 4; j++) oacc[j] += a * Vs[kk * 68 + cg * 4 + j];
    }
    int part = (b * Hh + h) * NSPLIT + si;
#pragma unroll
    for (int j = 0; j < 4; j++)
        g_pacc[((size_t)part * 16 + r) * 64 + cg * 4 + j] = oacc[j];
    if (cg == 0) {
        g_pm[part * 16 + r] = rowm[r];
        g_pl[part * 16 + r] = rowl[r];
    }
}

__global__ __launch_bounds__(32) void gattn_combine()
{
    int bh = blockIdx.x;
    int b = bh / Hh, h = bh % Hh;
    int t = threadIdx.x;   // 0..31, handles cols 2t, 2t+1
    for (int r = 0; r < Gg; r++) {
        float M = -3.0e38f;
        for (int si = 0; si < NSPLIT; si++)
            M = fmaxf(M, g_pm[((b * Hh + h) * NSPLIT + si) * 16 + r]);
        float L = 0.f, a0 = 0.f, a1 = 0.f;
        for (int si = 0; si < NSPLIT; si++) {
            int part = (b * Hh + h) * NSPLIT + si;
            float w = __expf(g_pm[part * 16 + r] - M);
            L += w * g_pl[part * 16 + r];
            a0 += w * g_pacc[((size_t)part * 16 + r) * 64 + 2 * t];
            a1 += w * g_pacc[((size_t)part * 16 + r) * 64 + 2 * t + 1];
        }
        uint32_t hi, lo;
        pack_hilo(a0 / L, a1 / L, hi, lo);
        size_t base = ((size_t)b * Ss + r) * Dd + h * DHd + 2 * t;
        *(uint32_t*)(g_ahi + base) = hi;
        *(uint32_t*)(g_alo + base) = lo;
    }
}

// ---------------- launch ----------------
extern "C" void kernel_launch(void* const* d_in, const int* in_sizes, int n_in,
                              void* d_out, int out_size)
{
    (void)in_sizes; (void)n_in; (void)out_size;
    const float* x    = (const float*)d_in[0];
    const int*   mask = (const int*)d_in[1];
    W6 w6;
    w6.w[0] = (const float*)d_in[2];
    w6.w[1] = (const float*)d_in[4];
    w6.w[2] = (const float*)d_in[6];
    w6.w[3] = (const float*)d_in[10];
    w6.w[4] = (const float*)d_in[12];
    w6.w[5] = (const float*)d_in[14];
    Bia5 b5;
    b5.b[0] = (const float*)d_in[3];
    b5.b[1] = (const float*)d_in[5];
    b5.b[2] = (const float*)d_in[7];
    b5.b[3] = (const float*)d_in[11];
    b5.b[4] = (const float*)d_in[13];
    const float* Wqg = (const float*)d_in[8];
    const float* bqg = (const float*)d_in[9];
    const float* bo  = (const float*)d_in[15];
    float* out = (float*)d_out;

    int gsm = (16 * 68 + 64 * 132 + 128 * 68 + 16 * 129 + 2 * 16) * 4;
    cudaFuncSetAttribute(gattn_part, cudaFuncAttributeMaxDynamicSharedMemorySize, gsm);
    cudaFuncSetAttribute(mma_gemm<false>, cudaFuncAttributeMaxDynamicSharedMemorySize, GEMM_SMEM);
    cudaFuncSetAttribute(mma_gemm<true>,  cudaFuncAttributeMaxDynamicSharedMemorySize, GEMM_SMEM);
    cudaFuncSetAttribute(local_attn, cudaFuncAttributeMaxDynamicSharedMemorySize, LA_SMEM);

    __nv_bfloat16 *xhi, *xlo, *ahi, *alo;
    cudaGetSymbolAddress((void**)&xhi, g_xhi);
    cudaGetSymbolAddress((void**)&xlo, g_xlo);
    cudaGetSymbolAddress((void**)&ahi, g_ahi);
    cudaGetSymbolAddress((void**)&alo, g_alo);

    int n4 = Bb * Ss * Dd / 4;
    to_bf16_split<<<(n4 + 255) / 256, 256>>>(x, xhi, xlo, n4);             // 1
    prep_w<<<dim3(24, 24, 6), dim3(32, 8)>>>(w6);                          // 2
    qg_proj<<<dim3(Bb * Gg, 24), 256>>>(x, Wqg, bqg);                      // 3
    mma_gemm<false><<<dim3(6, 64, 5), 512, GEMM_SMEM>>>(xhi, xlo, b5, nullptr, nullptr); // 4 (profiled)
    local_attn<<<dim3(NBb, Hh, Bb), 256, LA_SMEM>>>(mask);                 // 5
    gattn_part<<<dim3(NSPLIT, Hh, Bb), 256, gsm>>>(mask);                  // 6
    gattn_combine<<<Bb * Hh, 32>>>();                                      // 7
    mma_gemm<true><<<dim3(6, 64), 512, GEMM_SMEM>>>(ahi, alo, b5, bo, out); // 8
}

// round 9
// speedup vs baseline: 3.2500x; 1.3365x over previous
#include <cuda_runtime.h>
#include <cuda_fp16.h>
#include <cstdint>

#define Bb 2
#define Ss 4096
#define Dd 768
#define Hh 12
#define DHd 64
#define Ww 128
#define Gg 16
#define NBb 32
#define NSPLIT 32
#define NEGF (-1.0e9f)

// ---------------- scratch (device globals; no allocation) ----------------
__device__ float g_kg[Bb*Hh*Ss*DHd];
__device__ float g_vg[Bb*Hh*Ss*DHd];
__device__ float g_qg[Bb*Hh*Gg*DHd];
__device__ float g_pm  [Bb*Hh*NSPLIT*Gg];
__device__ float g_pl  [Bb*Hh*NSPLIT*Gg];
__device__ float g_pacc[Bb*Hh*NSPLIT*Gg*DHd];

__device__ __half g_xhi[Bb*Ss*Dd];
__device__ __half g_xlo[Bb*Ss*Dd];
__device__ __half g_ahi[Bb*Ss*Dd];
__device__ __half g_alo[Bb*Ss*Dd];
__device__ __half g_wt [6*Dd*Dd];       // transposed [N][K], single fp16
__device__ __half g_qhi[Bb*Hh*Ss*DHd];
__device__ __half g_qlo[Bb*Hh*Ss*DHd];
__device__ __half g_kf [Bb*Hh*Ss*DHd];  // single fp16
__device__ __half g_vf [Bb*Hh*Ss*DHd];  // single fp16

struct W6   { const float* w[6]; };
struct Bia5 { const float* b[5]; };

// ================= warp-MMA helpers =================
#define SWZ(o) ((o) ^ (((o) >> 3) & 0x70))

__device__ __forceinline__ uint32_t smem_u32(const void* p) {
    uint32_t a;
    asm("{ .reg .u64 t; cvta.to.shared.u64 t, %1; cvt.u32.u64 %0, t; }" : "=r"(a) : "l"(p));
    return a;
}
__device__ __forceinline__ void ldsm4(uint32_t* r, uint32_t addr) {
    asm volatile("ldmatrix.sync.aligned.m8n8.x4.shared.b16 {%0,%1,%2,%3}, [%4];"
                 : "=r"(r[0]), "=r"(r[1]), "=r"(r[2]), "=r"(r[3]) : "r"(addr));
}
__device__ __forceinline__ void ldsm4t(uint32_t* r, uint32_t addr) {
    asm volatile("ldmatrix.sync.aligned.m8n8.x4.trans.shared.b16 {%0,%1,%2,%3}, [%4];"
                 : "=r"(r[0]), "=r"(r[1]), "=r"(r[2]), "=r"(r[3]) : "r"(addr));
}
__device__ __forceinline__ void mma16816(float* d, const uint32_t* a, uint32_t b0, uint32_t b1) {
    asm volatile(
        "mma.sync.aligned.m16n8k16.row.col.f32.f16.f16.f32 "
        "{%0,%1,%2,%3}, {%4,%5,%6,%7}, {%8,%9}, {%0,%1,%2,%3};"
        : "+f"(d[0]), "+f"(d[1]), "+f"(d[2]), "+f"(d[3])
        : "r"(a[0]), "r"(a[1]), "r"(a[2]), "r"(a[3]), "r"(b0), "r"(b1));
}
__device__ __forceinline__ void pack_hilo_h(float e0, float e1, uint32_t& hi, uint32_t& lo) {
    __half2 h = __floats2half2_rn(e0, e1);
    float r0 = e0 - __half2float(h.x);
    float r1 = e1 - __half2float(h.y);
    __half2 l2 = __floats2half2_rn(r0, r1);
    hi = *(uint32_t*)&h;
    lo = *(uint32_t*)&l2;
}
__device__ __forceinline__ uint32_t pack_h2(float e0, float e1) {
    __half2 h = __floats2half2_rn(e0, e1);
    return *(uint32_t*)&h;
}
__device__ __forceinline__ void cpasync16(uint32_t dst, const void* src) {
    asm volatile("cp.async.cg.shared.global [%0], [%1], 16;" :: "r"(dst), "l"(src) : "memory");
}

// ================= prep kernels =================
__global__ __launch_bounds__(256) void to_f16_split(const float* __restrict__ in,
                                                    __half* __restrict__ hi,
                                                    __half* __restrict__ lo, int n4)
{
    int i = blockIdx.x * 256 + threadIdx.x;
    if (i >= n4) return;
    float4 v = ((const float4*)in)[i];
    float vv[4] = {v.x, v.y, v.z, v.w};
    union { __half h[4]; uint2 u; } uh, ul;
#pragma unroll
    for (int j = 0; j < 4; j++) {
        __half h = __float2half_rn(vv[j]);
        uh.h[j] = h;
        ul.h[j] = __float2half_rn(vv[j] - __half2float(h));
    }
    *(uint2*)(hi + (size_t)i * 4) = uh.u;
    *(uint2*)(lo + (size_t)i * 4) = ul.u;
}

// transpose W [K][N] -> Wt [N][K], single fp16
__global__ __launch_bounds__(256) void prep_w(W6 ws)
{
    __shared__ float t[32][33];
    int z = blockIdx.z;
    const float* W = ws.w[z];
    __half* oh = g_wt + (size_t)z * Dd * Dd;
    int k0 = blockIdx.x * 32, n0 = blockIdx.y * 32;
    int tx = threadIdx.x, ty = threadIdx.y;
#pragma unroll
    for (int r = 0; r < 4; r++)
        t[ty + r * 8][tx] = W[(size_t)(k0 + ty + r * 8) * Dd + n0 + tx];
    __syncthreads();
#pragma unroll
    for (int r = 0; r < 4; r++)
        oh[(size_t)(n0 + ty + r * 8) * Dd + k0 + tx] = __float2half_rn(t[tx][ty + r * 8]);
}

// ===== fp16 2-product GEMM: 512 thr, 32x32 warp tiles, cp.async 3-stage =====
#define STAGE_SZ 49152
#define GEMM_SMEM (3 * STAGE_SZ)

template<bool OUT>
__global__ __launch_bounds__(512)
void mma_gemm(const __half* __restrict__ Ahi, const __half* __restrict__ Alo,
              Bia5 bp, const float* __restrict__ bias_o, float* __restrict__ outp)
{
    extern __shared__ char smem[];
    uint32_t sb = smem_u32(smem);
    int tid = threadIdx.x;
    int wid = tid >> 5, lane = tid & 31;
    int wm = wid >> 2, wn = wid & 3;
    int z = OUT ? 5 : blockIdx.z;
    int n0 = blockIdx.x * 128, m0 = blockIdx.y * 128;

    const __half* Bw = g_wt + (size_t)z * Dd * Dd;
    const __half* srcs[3] = {
        Ahi + (size_t)m0 * Dd, Alo + (size_t)m0 * Dd, Bw + (size_t)n0 * Dd };

    float acc[2][4][4];
#pragma unroll
    for (int i = 0; i < 2; i++)
#pragma unroll
        for (int j = 0; j < 4; j++)
#pragma unroll
            for (int q = 0; q < 4; q++) acc[i][j][q] = 0.f;

    int alr = lane & 15, alc = lane >> 4, arx = lane & 7;
    uint32_t aoff[2];
#pragma unroll
    for (int mi = 0; mi < 2; mi++) aoff[mi] = (wm * 32 + mi * 16 + alr) * 128;
    int blr = (lane & 7) + ((lane >> 4) & 1) * 8;
    int blc = (lane >> 3) & 1, brx = lane & 7;
    uint32_t boff[2];
#pragma unroll
    for (int ni = 0; ni < 2; ni++) boff[ni] = (wn * 32 + ni * 16 + blr) * 128;

    // stage: Ah @0, Al @16384, B @32768 (each 128 rows x 128B)
    auto load_stage = [&](int c, int s) {
        int k0 = c * 64;
        uint32_t base = sb + s * STAGE_SZ;
#pragma unroll
        for (int t = 0; t < 3; t++) {
            const __half* sp = srcs[t] + k0;
            uint32_t tp = base + t * 16384;
#pragma unroll
            for (int it = 0; it < 2; it++) {
                int idx = tid + it * 512;
                int row = idx >> 3, cu = idx & 7;
                cpasync16(tp + SWZ(row * 128 + cu * 16), sp + (size_t)row * Dd + cu * 8);
            }
        }
    };

    load_stage(0, 0);
    asm volatile("cp.async.commit_group;" ::: "memory");
    load_stage(1, 1);
    asm volatile("cp.async.commit_group;" ::: "memory");

    for (int c = 0; c < 12; c++) {
        asm volatile("cp.async.wait_group 1;" ::: "memory");
        __syncthreads();
        if (c < 10) {
            load_stage(c + 2, (c + 2) % 3);
            asm volatile("cp.async.commit_group;" ::: "memory");
        } else {
            // keep group count consistent for wait_group 1 semantics
            asm volatile("cp.async.commit_group;" ::: "memory");
        }
        uint32_t sA = sb + (c % 3) * STAGE_SZ;
        uint32_t sAl = sA + 16384, sB = sA + 32768;
#pragma unroll
        for (int ks = 0; ks < 4; ks++) {
            uint32_t ah[2][4], al[2][4], bh[2][4];
            uint32_t ac = ((uint32_t)(ks * 2 + alc) ^ arx) << 4;
            uint32_t bc = ((uint32_t)(ks * 2 + blc) ^ brx) << 4;
#pragma unroll
            for (int mi = 0; mi < 2; mi++) {
                ldsm4(ah[mi], sA  + aoff[mi] + ac);
                ldsm4(al[mi], sAl + aoff[mi] + ac);
            }
#pragma unroll
            for (int ni = 0; ni < 2; ni++) ldsm4(bh[ni], sB + boff[ni] + bc);
#pragma unroll
            for (int mi = 0; mi < 2; mi++)
#pragma unroll
                for (int nj = 0; nj < 4; nj++) {
                    int ni = nj >> 1, hf = (nj & 1) * 2;
                    mma16816(acc[mi][nj], ah[mi], bh[ni][hf], bh[ni][hf + 1]);
                    mma16816(acc[mi][nj], al[mi], bh[ni][hf], bh[ni][hf + 1]);
                }
        }
    }

    __syncthreads();
    int g = lane >> 2, t4 = lane & 3;
#pragma unroll
    for (int mi = 0; mi < 2; mi++) {
        int r0 = m0 + wm * 32 + mi * 16 + g;
#pragma unroll
        for (int nj = 0; nj < 4; nj++) {
            int cc = n0 + wn * 32 + nj * 8 + t4 * 2;
#pragma unroll
            for (int half = 0; half < 2; half++) {
                int m = r0 + half * 8;
                float v0 = acc[mi][nj][half * 2 + 0];
                float v1 = acc[mi][nj][half * 2 + 1];
                if (OUT) {
                    float2 o = make_float2(v0 + bias_o[cc], v1 + bias_o[cc + 1]);
                    *(float2*)(outp + (size_t)m * Dd + cc) = o;
                } else {
                    const float* bias = bp.b[z];
                    float scale = (z == 0) ? 0.125f : 1.0f;
                    v0 = (v0 + bias[cc]) * scale;
                    v1 = (v1 + bias[cc + 1]) * scale;
                    int b = m >> 12, s = m & 4095;
                    int h = cc >> 6, d0 = cc & 63;
                    size_t base = (((size_t)(b * Hh + h)) * Ss + s) * DHd + d0;
                    if (z >= 3) {
                        float* dstz = (z == 3) ? g_kg : g_vg;
                        *(float2*)(dstz + base) = make_float2(v0, v1);
                    } else if (z == 0) {
                        uint32_t hi, lo;
                        pack_hilo_h(v0, v1, hi, lo);
                        *(uint32_t*)(g_qhi + base) = hi;
                        *(uint32_t*)(g_qlo + base) = lo;
                    } else {
                        __half* dst = (z == 1) ? g_kf : g_vf;
                        *(uint32_t*)(dst + base) = pack_h2(v0, v1);
                    }
                }
            }
        }
    }
}

// ================= local attention: fp16 2/1-product FA2 =================
// smem: kok[128]f @0 (pad 1024) | Qhi 16K | Qlo 16K | K 16K | V 16K
#define LA_KOK   0
#define LA_Q     1024
#define LA_QL    (LA_Q  + 16384)
#define LA_K     (LA_QL + 16384)
#define LA_V     (LA_K  + 16384)
#define LA_SMEM  (LA_V  + 16384)

__global__ __launch_bounds__(256) void local_attn(const int* __restrict__ mask)
{
    extern __shared__ char smem[];
    uint32_t sb = smem_u32(smem);
    float* kok = (float*)(smem + LA_KOK);

    int n = blockIdx.x, h = blockIdx.y, b = blockIdx.z;
    int tid = threadIdx.x;
    int wid = tid >> 5, lane = tid & 31;
    int g = lane >> 2, t4 = lane & 3;
    int qr = wid * 16;

    size_t bhbase = ((size_t)(b * Hh + h)) * Ss * DHd;
    const __half* qh_g = g_qhi + bhbase + (size_t)n * Ww * DHd;
    const __half* ql_g = g_qlo + bhbase + (size_t)n * Ww * DHd;
    const __half* k_g  = g_kf + bhbase;
    const __half* v_g  = g_vf + bhbase;
    const int* mk = mask + b * Ss;

#pragma unroll
    for (int it = 0; it < 4; it++) {
        int idx = tid + it * 256;
        int row = idx >> 3, cu = idx & 7;
        uint32_t sw = row * 128 + ((cu ^ (row & 7)) << 4);
        *(uint4*)(smem + LA_Q  + sw) = *(const uint4*)(qh_g + (size_t)row * DHd + cu * 8);
        *(uint4*)(smem + LA_QL + sw) = *(const uint4*)(ql_g + (size_t)row * DHd + cu * 8);
    }

    float sacc[16][4];
    float O[8][4];
#pragma unroll
    for (int j = 0; j < 8; j++)
#pragma unroll
        for (int q = 0; q < 4; q++) O[j][q] = 0.f;
    float m0 = -3.0e38f, m1 = -3.0e38f, l0 = 0.f, l1 = 0.f;

    uint32_t aboff = (qr + (lane & 15)) * 128;
    int arx = lane & 7;
    int alc = lane >> 4;
    int krow_in = (lane & 7) + 8 * ((lane >> 4) & 1);
    int kcc = (lane >> 3) & 1;
    int tkrow = (lane & 7) + 8 * ((lane >> 3) & 1);
    int tdu = lane >> 4;

    for (int c = 0; c < 4; c++) {
        int p0 = (n - 1) * Ww + c * Ww;
        __syncthreads();
        if (tid < 128) {
            bool ok;
            if (c == 3) ok = (tid < Gg) && (mk[tid] > 0);
            else { int p = p0 + tid; ok = (p >= Gg) && (p < Ss) && (mk[p] > 0); }
            kok[tid] = ok ? 1.f : 0.f;
        }
#pragma unroll
        for (int it = 0; it < 4; it++) {
            int idx = tid + it * 256;
            int j = idx >> 3, cu = idx & 7;
            int p = (c == 3) ? j : (p0 + j);
            bool inr = (c == 3) ? (j < Gg) : (p >= 0 && p < Ss);
            uint4 kv = make_uint4(0, 0, 0, 0), vv = make_uint4(0, 0, 0, 0);
            if (inr) {
                size_t gb = (size_t)p * DHd + cu * 8;
                kv = *(const uint4*)(k_g + gb);
                vv = *(const uint4*)(v_g + gb);
            }
            uint32_t sw = j * 128 + ((cu ^ (j & 7)) << 4);
            *(uint4*)(smem + LA_K + sw) = kv;
            *(uint4*)(smem + LA_V + sw) = vv;
        }
        __syncthreads();

        // ---- S = Q.K^T (2-product) ----
#pragma unroll
        for (int j = 0; j < 16; j++)
#pragma unroll
            for (int q = 0; q < 4; q++) sacc[j][q] = 0.f;
#pragma unroll
        for (int ks = 0; ks < 4; ks++) {
            uint32_t qh4[4], ql4[4];
            uint32_t ac = ((uint32_t)(ks * 2 + alc) ^ arx) << 4;
            ldsm4(qh4, sb + LA_Q  + aboff + ac);
            ldsm4(ql4, sb + LA_QL + aboff + ac);
#pragma unroll
            for (int jj = 0; jj < 8; jj++) {
                uint32_t kh4[4];
                uint32_t kb = (16 * jj + krow_in) * 128 + (((uint32_t)(ks * 2 + kcc) ^ arx) << 4);
                ldsm4(kh4, sb + LA_K + kb);
                mma16816(sacc[2 * jj],     qh4, kh4[0], kh4[1]);
                mma16816(sacc[2 * jj],     ql4, kh4[0], kh4[1]);
                mma16816(sacc[2 * jj + 1], qh4, kh4[2], kh4[3]);
                mma16816(sacc[2 * jj + 1], ql4, kh4[2], kh4[3]);
            }
        }

        // ---- mask ----
        int row0 = n * Ww + qr + g;
        int row1 = row0 + 8;
#pragma unroll
        for (int j = 0; j < 16; j++) {
#pragma unroll
            for (int q = 0; q < 4; q++) {
                int col = 8 * j + t4 * 2 + (q & 1);
                int row = (q >= 2) ? row1 : row0;
                bool ok = kok[col] > 0.f;
                if (c != 3) {
                    int rel = (p0 + col) - row;
                    ok = ok && (rel <= Ww) && (rel >= -Ww);
                }
                if (!ok) sacc[j][q] = NEGF;
            }
        }

        // ---- online softmax ----
        float mx0 = -3.0e38f, mx1 = -3.0e38f;
#pragma unroll
        for (int j = 0; j < 16; j++) {
            mx0 = fmaxf(mx0, fmaxf(sacc[j][0], sacc[j][1]));
            mx1 = fmaxf(mx1, fmaxf(sacc[j][2], sacc[j][3]));
        }
        mx0 = fmaxf(mx0, __shfl_xor_sync(0xffffffff, mx0, 1));
        mx0 = fmaxf(mx0, __shfl_xor_sync(0xffffffff, mx0, 2));
        mx1 = fmaxf(mx1, __shfl_xor_sync(0xffffffff, mx1, 1));
        mx1 = fmaxf(mx1, __shfl_xor_sync(0xffffffff, mx1, 2));
        float mn0 = fmaxf(m0, mx0), mn1 = fmaxf(m1, mx1);
        float f0 = __expf(m0 - mn0), f1 = __expf(m1 - mn1);
        float s0 = 0.f, s1 = 0.f;
#pragma unroll
        for (int j = 0; j < 16; j++) {
            float p0v = __expf(sacc[j][0] - mn0);
            float p1v = __expf(sacc[j][1] - mn0);
            float p2v = __expf(sacc[j][2] - mn1);
            float p3v = __expf(sacc[j][3] - mn1);
            sacc[j][0] = p0v; sacc[j][1] = p1v; sacc[j][2] = p2v; sacc[j][3] = p3v;
            s0 += p0v + p1v; s1 += p2v + p3v;
        }
        s0 += __shfl_xor_sync(0xffffffff, s0, 1);
        s0 += __shfl_xor_sync(0xffffffff, s0, 2);
        s1 += __shfl_xor_sync(0xffffffff, s1, 1);
        s1 += __shfl_xor_sync(0xffffffff, s1, 2);
        l0 = l0 * f0 + s0; l1 = l1 * f1 + s1;
        m0 = mn0; m1 = mn1;
#pragma unroll
        for (int j = 0; j < 8; j++) {
            O[j][0] *= f0; O[j][1] *= f0; O[j][2] *= f1; O[j][3] *= f1;
        }

        // ---- O += P.V (P single fp16, 1 product) ----
#pragma unroll
        for (int ks = 0; ks < 8; ks++) {
            uint32_t pa[4];
            pa[0] = pack_h2(sacc[2 * ks][0],     sacc[2 * ks][1]);
            pa[1] = pack_h2(sacc[2 * ks][2],     sacc[2 * ks][3]);
            pa[2] = pack_h2(sacc[2 * ks + 1][0], sacc[2 * ks + 1][1]);
            pa[3] = pack_h2(sacc[2 * ks + 1][2], sacc[2 * ks + 1][3]);
#pragma unroll
            for (int jd = 0; jd < 4; jd++) {
                uint32_t vh4[4];
                uint32_t vb = (uint32_t)(16 * ks + tkrow) * 128 +
                              (((uint32_t)(jd * 2 + tdu) ^ (uint32_t)(lane & 7)) << 4);
                ldsm4t(vh4, sb + LA_V + vb);
                mma16816(O[2 * jd],     pa, vh4[0], vh4[1]);
                mma16816(O[2 * jd + 1], pa, vh4[2], vh4[3]);
            }
        }
    }

    // ---- write out as fp16 hi/lo (feeds out-proj) ----
    float inv0 = 1.0f / l0, inv1 = 1.0f / l1;
    int s0r = n * Ww + qr + g;
    int s1r = s0r + 8;
    size_t b0 = ((size_t)b * Ss + s0r) * Dd + h * DHd;
    size_t b1 = ((size_t)b * Ss + s1r) * Dd + h * DHd;
#pragma unroll
    for (int jd = 0; jd < 8; jd++) {
        int cc = 8 * jd + t4 * 2;
        uint32_t hi, lo;
        pack_hilo_h(O[jd][0] * inv0, O[jd][1] * inv0, hi, lo);
        *(uint32_t*)(g_ahi + b0 + cc) = hi;
        *(uint32_t*)(g_alo + b0 + cc) = lo;
        pack_hilo_h(O[jd][2] * inv1, O[jd][3] * inv1, hi, lo);
        *(uint32_t*)(g_ahi + b1 + cc) = hi;
        *(uint32_t*)(g_alo + b1 + cc) = lo;
    }
}

// ---------------- qg projection ----------------
__global__ __launch_bounds__(256) void qg_proj(const float* __restrict__ x,
                                               const float* __restrict__ Wqg,
                                               const float* __restrict__ bqg)
{
    __shared__ float xr[768];
    __shared__ float sred[256];
    int bg = blockIdx.x, cc = blockIdx.y;
    int b = bg >> 4, g = bg & 15;
    int tid = threadIdx.x;
    for (int i = tid; i < 768; i += 256) xr[i] = x[((size_t)b * Ss + g) * Dd + i];
    __syncthreads();
    int col = cc * 32 + (tid & 31);
    int ks = tid >> 5;
    int k0 = ks * 96;
    float acc = 0.f;
#pragma unroll 8
    for (int k = 0; k < 96; k++)
        acc += xr[k0 + k] * Wqg[(size_t)(k0 + k) * 768 + col];
    sred[tid] = acc;
    __syncthreads();
    if (tid < 32) {
        float tot = 0.f;
#pragma unroll
        for (int j = 0; j < 8; j++) tot += sred[tid + 32 * j];
        int c = cc * 32 + tid;
        float vv = (tot + bqg[c]) * 0.125f;
        g_qg[(((size_t)b * Hh + (c >> 6)) * Gg + g) * DHd + (c & 63)] = vv;
    }
}

// ---------------- global-row attention: 32-way split ----------------
__global__ __launch_bounds__(256) void gattn_part(const int* __restrict__ mask)
{
    extern __shared__ float sm[];
    float* Qgs  = sm;
    float* Kts  = Qgs + 16 * 68;
    float* Vs   = Kts + 64 * 132;
    float* Ps   = Vs + 128 * 68;
    float* rowm = Ps + 16 * 129;
    float* rowl = rowm + 16;

    int si = blockIdx.x, h = blockIdx.y, b = blockIdx.z;
    int tid = threadIdx.x;
    const float* kgb = g_kg + ((size_t)(b * Hh + h)) * Ss * DHd;
    const float* vgb = g_vg + ((size_t)(b * Hh + h)) * Ss * DHd;
    const int* mk = mask + b * Ss;

    for (int i = tid; i < 16 * 64; i += 256) {
        int r = i >> 6, d = i & 63;
        Qgs[r * 68 + d] = g_qg[(((size_t)b * Hh + h) * Gg + r) * DHd + d];
    }

    int p0 = si * 128;
    int r = tid >> 4, cg = tid & 15;
#pragma unroll
    for (int it = 0; it < 8; it++) {
        int idx = tid + it * 256;
        int j = idx >> 4, cv = idx & 15;
        int p = p0 + j;
        float4 kv = *(const float4*)(kgb + (size_t)p * 64 + cv * 4);
        float4 vv = *(const float4*)(vgb + (size_t)p * 64 + cv * 4);
        Kts[(cv * 4 + 0) * 132 + j] = kv.x;
        Kts[(cv * 4 + 1) * 132 + j] = kv.y;
        Kts[(cv * 4 + 2) * 132 + j] = kv.z;
        Kts[(cv * 4 + 3) * 132 + j] = kv.w;
        *(float4*)&Vs[j * 68 + cv * 4] = vv;
    }
    __syncthreads();

    float sc8[8] = {0.f, 0.f, 0.f, 0.f, 0.f, 0.f, 0.f, 0.f};
#pragma unroll 8
    for (int d = 0; d < 64; d++) {
        float a = Qgs[r * 68 + d];
#pragma unroll
        for (int j = 0; j < 8; j++) sc8[j] += a * Kts[d * 132 + cg * 8 + j];
    }
#pragma unroll
    for (int j = 0; j < 8; j++) {
        int p = p0 + cg * 8 + j;
        Ps[r * 129 + cg * 8 + j] = (mk[p] > 0) ? sc8[j] : NEGF;
    }
    __syncthreads();

    if (tid < 16) {
        float cm = -3.0e38f;
        for (int j2 = 0; j2 < 128; j2++) cm = fmaxf(cm, Ps[tid * 129 + j2]);
        float ls = 0.f;
        for (int j2 = 0; j2 < 128; j2++) {
            float pv = __expf(Ps[tid * 129 + j2] - cm);
            Ps[tid * 129 + j2] = pv;
            ls += pv;
        }
        rowm[tid] = cm;
        rowl[tid] = ls;
    }
    __syncthreads();

    float oacc[4] = {0.f, 0.f, 0.f, 0.f};
    for (int kk = 0; kk < 128; kk++) {
        float a = Ps[r * 129 + kk];
#pragma unroll
        for (int j = 0; j < 4; j++) oacc[j] += a * Vs[kk * 68 + cg * 4 + j];
    }
    int part = (b * Hh + h) * NSPLIT + si;
#pragma unroll
    for (int j = 0; j < 4; j++)
        g_pacc[((size_t)part * 16 + r) * 64 + cg * 4 + j] = oacc[j];
    if (cg == 0) {
        g_pm[part * 16 + r] = rowm[r];
        g_pl[part * 16 + r] = rowl[r];
    }
}

__global__ __launch_bounds__(32) void gattn_combine()
{
    int bh = blockIdx.x;
    int b = bh / Hh, h = bh % Hh;
    int t = threadIdx.x;
    for (int r = 0; r < Gg; r++) {
        float M = -3.0e38f;
        for (int si = 0; si < NSPLIT; si++)
            M = fmaxf(M, g_pm[((b * Hh + h) * NSPLIT + si) * 16 + r]);
        float L = 0.f, a0 = 0.f, a1 = 0.f;
        for (int si = 0; si < NSPLIT; si++) {
            int part = (b * Hh + h) * NSPLIT + si;
            float w = __expf(g_pm[part * 16 + r] - M);
            L += w * g_pl[part * 16 + r];
            a0 += w * g_pacc[((size_t)part * 16 + r) * 64 + 2 * t];
            a1 += w * g_pacc[((size_t)part * 16 + r) * 64 + 2 * t + 1];
        }
        uint32_t hi, lo;
        pack_hilo_h(a0 / L, a1 / L, hi, lo);
        size_t base = ((size_t)b * Ss + r) * Dd + h * DHd + 2 * t;
        *(uint32_t*)(g_ahi + base) = hi;
        *(uint32_t*)(g_alo + base) = lo;
    }
}

// ---------------- launch ----------------
extern "C" void kernel_launch(void* const* d_in, const int* in_sizes, int n_in,
                              void* d_out, int out_size)
{
    (void)in_sizes; (void)n_in; (void)out_size;
    const float* x    = (const float*)d_in[0];
    const int*   mask = (const int*)d_in[1];
    W6 w6;
    w6.w[0] = (const float*)d_in[2];
    w6.w[1] = (const float*)d_in[4];
    w6.w[2] = (const float*)d_in[6];
    w6.w[3] = (const float*)d_in[10];
    w6.w[4] = (const float*)d_in[12];
    w6.w[5] = (const float*)d_in[14];
    Bia5 b5;
    b5.b[0] = (const float*)d_in[3];
    b5.b[1] = (const float*)d_in[5];
    b5.b[2] = (const float*)d_in[7];
    b5.b[3] = (const float*)d_in[11];
    b5.b[4] = (const float*)d_in[13];
    const float* Wqg = (const float*)d_in[8];
    const float* bqg = (const float*)d_in[9];
    const float* bo  = (const float*)d_in[15];
    float* out = (float*)d_out;

    int gsm = (16 * 68 + 64 * 132 + 128 * 68 + 16 * 129 + 2 * 16) * 4;
    cudaFuncSetAttribute(gattn_part, cudaFuncAttributeMaxDynamicSharedMemorySize, gsm);
    cudaFuncSetAttribute(mma_gemm<false>, cudaFuncAttributeMaxDynamicSharedMemorySize, GEMM_SMEM);
    cudaFuncSetAttribute(mma_gemm<true>,  cudaFuncAttributeMaxDynamicSharedMemorySize, GEMM_SMEM);
    cudaFuncSetAttribute(local_attn, cudaFuncAttributeMaxDynamicSharedMemorySize, LA_SMEM);

    __half *xhi, *xlo, *ahi, *alo;
    cudaGetSymbolAddress((void**)&xhi, g_xhi);
    cudaGetSymbolAddress((void**)&xlo, g_xlo);
    cudaGetSymbolAddress((void**)&ahi, g_ahi);
    cudaGetSymbolAddress((void**)&alo, g_alo);

    int n4 = Bb * Ss * Dd / 4;
    to_f16_split<<<(n4 + 255) / 256, 256>>>(x, xhi, xlo, n4);              // 1
    prep_w<<<dim3(24, 24, 6), dim3(32, 8)>>>(w6);                          // 2
    qg_proj<<<dim3(Bb * Gg, 24), 256>>>(x, Wqg, bqg);                      // 3
    mma_gemm<false><<<dim3(6, 64, 5), 512, GEMM_SMEM>>>(xhi, xlo, b5, nullptr, nullptr); // 4 (profiled)
    local_attn<<<dim3(NBb, Hh, Bb), 256, LA_SMEM>>>(mask);                 // 5
    gattn_part<<<dim3(NSPLIT, Hh, Bb), 256, gsm>>>(mask);                  // 6
    gattn_combine<<<Bb * Hh, 32>>>();                                      // 7
    mma_gemm<true><<<dim3(6, 64), 512, GEMM_SMEM>>>(ahi, alo, b5, bo, out); // 8
}

// round 10
// speedup vs baseline: 3.3065x; 1.0174x over previous
#include <cuda_runtime.h>
#include <cuda_fp16.h>
#include <cstdint>

#define Bb 2
#define Ss 4096
#define Dd 768
#define Hh 12
#define DHd 64
#define Ww 128
#define Gg 16
#define NBb 32
#define NSPLIT 32
#define NEGF (-1.0e9f)

// ---------------- scratch (device globals; no allocation) ----------------
__device__ float g_kg[Bb*Hh*Ss*DHd];
__device__ float g_vg[Bb*Hh*Ss*DHd];
__device__ float g_qg[Bb*Hh*Gg*DHd];
__device__ float g_pm  [Bb*Hh*NSPLIT*Gg];
__device__ float g_pl  [Bb*Hh*NSPLIT*Gg];
__device__ float g_pacc[Bb*Hh*NSPLIT*Gg*DHd];

__device__ __half g_xhi[Bb*Ss*Dd];
__device__ __half g_xlo[Bb*Ss*Dd];
__device__ __half g_ahi[Bb*Ss*Dd];
__device__ __half g_alo[Bb*Ss*Dd];
__device__ __half g_wt [6*Dd*Dd];
__device__ __half g_qhi[Bb*Hh*Ss*DHd];
__device__ __half g_qlo[Bb*Hh*Ss*DHd];
__device__ __half g_kf [Bb*Hh*Ss*DHd];
__device__ __half g_vf [Bb*Hh*Ss*DHd];

struct W6   { const float* w[6]; };
struct Bia5 { const float* b[5]; };

// ================= warp-MMA helpers =================
#define SWZ(o) ((o) ^ (((o) >> 3) & 0x70))

__device__ __forceinline__ uint32_t smem_u32(const void* p) {
    uint32_t a;
    asm("{ .reg .u64 t; cvta.to.shared.u64 t, %1; cvt.u32.u64 %0, t; }" : "=r"(a) : "l"(p));
    return a;
}
__device__ __forceinline__ void ldsm4(uint32_t* r, uint32_t addr) {
    asm volatile("ldmatrix.sync.aligned.m8n8.x4.shared.b16 {%0,%1,%2,%3}, [%4];"
                 : "=r"(r[0]), "=r"(r[1]), "=r"(r[2]), "=r"(r[3]) : "r"(addr));
}
__device__ __forceinline__ void ldsm4t(uint32_t* r, uint32_t addr) {
    asm volatile("ldmatrix.sync.aligned.m8n8.x4.trans.shared.b16 {%0,%1,%2,%3}, [%4];"
                 : "=r"(r[0]), "=r"(r[1]), "=r"(r[2]), "=r"(r[3]) : "r"(addr));
}
__device__ __forceinline__ void mma16816(float* d, const uint32_t* a, uint32_t b0, uint32_t b1) {
    asm volatile(
        "mma.sync.aligned.m16n8k16.row.col.f32.f16.f16.f32 "
        "{%0,%1,%2,%3}, {%4,%5,%6,%7}, {%8,%9}, {%0,%1,%2,%3};"
        : "+f"(d[0]), "+f"(d[1]), "+f"(d[2]), "+f"(d[3])
        : "r"(a[0]), "r"(a[1]), "r"(a[2]), "r"(a[3]), "r"(b0), "r"(b1));
}
__device__ __forceinline__ void pack_hilo_h(float e0, float e1, uint32_t& hi, uint32_t& lo) {
    __half2 h = __floats2half2_rn(e0, e1);
    float r0 = e0 - __half2float(h.x);
    float r1 = e1 - __half2float(h.y);
    __half2 l2 = __floats2half2_rn(r0, r1);
    hi = *(uint32_t*)&h;
    lo = *(uint32_t*)&l2;
}
__device__ __forceinline__ uint32_t pack_h2(float e0, float e1) {
    __half2 h = __floats2half2_rn(e0, e1);
    return *(uint32_t*)&h;
}
__device__ __forceinline__ void cpasync16(uint32_t dst, const void* src) {
    asm volatile("cp.async.cg.shared.global [%0], [%1], 16;" :: "r"(dst), "l"(src) : "memory");
}

// ================= prep kernels =================
__global__ __launch_bounds__(256) void to_f16_split(const float* __restrict__ in,
                                                    __half* __restrict__ hi,
                                                    __half* __restrict__ lo, int n4)
{
    int i = blockIdx.x * 256 + threadIdx.x;
    if (i >= n4) return;
    float4 v = ((const float4*)in)[i];
    float vv[4] = {v.x, v.y, v.z, v.w};
    union { __half h[4]; uint2 u; } uh, ul;
#pragma unroll
    for (int j = 0; j < 4; j++) {
        __half h = __float2half_rn(vv[j]);
        uh.h[j] = h;
        ul.h[j] = __float2half_rn(vv[j] - __half2float(h));
    }
    *(uint2*)(hi + (size_t)i * 4) = uh.u;
    *(uint2*)(lo + (size_t)i * 4) = ul.u;
}

__global__ __launch_bounds__(256) void prep_w(W6 ws)
{
    __shared__ float t[32][33];
    int z = blockIdx.z;
    const float* W = ws.w[z];
    __half* oh = g_wt + (size_t)z * Dd * Dd;
    int k0 = blockIdx.x * 32, n0 = blockIdx.y * 32;
    int tx = threadIdx.x, ty = threadIdx.y;
#pragma unroll
    for (int r = 0; r < 4; r++)
        t[ty + r * 8][tx] = W[(size_t)(k0 + ty + r * 8) * Dd + n0 + tx];
    __syncthreads();
#pragma unroll
    for (int r = 0; r < 4; r++)
        oh[(size_t)(n0 + ty + r * 8) * Dd + k0 + tx] = __float2half_rn(t[tx][ty + r * 8]);
}

// ===== fp16 2-product GEMM v3: BM128 x BN256, 512 thr, 3-stage cp.async =====
// stage: Ah 16K | Al 16K | B 32K = 64KB
#define STAGE_SZ 65536
#define GEMM_SMEM (3 * STAGE_SZ)

template<bool OUT>
__global__ __launch_bounds__(512)
void mma_gemm(const __half* __restrict__ Ahi, const __half* __restrict__ Alo,
              Bia5 bp, const float* __restrict__ bias_o, float* __restrict__ outp)
{
    extern __shared__ char smem[];
    uint32_t sb = smem_u32(smem);
    int tid = threadIdx.x;
    int wid = tid >> 5, lane = tid & 31;
    int wm = wid >> 2, wn = wid & 3;          // warp tile 32m x 64n
    int z = OUT ? 5 : blockIdx.z;
    int n0 = blockIdx.x * 256, m0 = blockIdx.y * 128;

    const __half* Bw = g_wt + (size_t)z * Dd * Dd + (size_t)n0 * Dd;
    const __half* Ah = Ahi + (size_t)m0 * Dd;
    const __half* Al = Alo + (size_t)m0 * Dd;

    float acc[2][8][4];
#pragma unroll
    for (int i = 0; i < 2; i++)
#pragma unroll
        for (int j = 0; j < 8; j++)
#pragma unroll
            for (int q = 0; q < 4; q++) acc[i][j][q] = 0.f;

    int alr = lane & 15, alc = lane >> 4, arx = lane & 7;
    uint32_t aoff[2];
#pragma unroll
    for (int mi = 0; mi < 2; mi++) aoff[mi] = (wm * 32 + mi * 16 + alr) * 128;
    int blr = (lane & 7) + ((lane >> 4) & 1) * 8;
    int blc = (lane >> 3) & 1, brx = lane & 7;
    uint32_t boff[4];
#pragma unroll
    for (int ni = 0; ni < 4; ni++) boff[ni] = (wn * 64 + ni * 16 + blr) * 128;

    // loader: idx 0-1023 Ah, 1024-2047 Al, 2048-4095 B (row,cu = 128B rows)
    auto load_stage = [&](int c, int s) {
        int k0 = c * 64;
        uint32_t base = sb + s * STAGE_SZ;
#pragma unroll
        for (int it = 0; it < 8; it++) {
            int idx = tid + it * 512;
            int cu = idx & 7;
            if (idx < 2048) {
                int reg = idx >> 10;                 // 0=Ah 1=Al
                int row = (idx & 1023) >> 3;
                const __half* sp = (reg == 0 ? Ah : Al) + k0;
                cpasync16(base + reg * 16384 + SWZ(row * 128 + cu * 16),
                          sp + (size_t)row * Dd + cu * 8);
            } else {
                int row = (idx - 2048) >> 3;         // 0..255
                cpasync16(base + 32768 + SWZ(row * 128 + cu * 16),
                          Bw + k0 + (size_t)row * Dd + cu * 8);
            }
        }
    };

    load_stage(0, 0);
    asm volatile("cp.async.commit_group;" ::: "memory");
    load_stage(1, 1);
    asm volatile("cp.async.commit_group;" ::: "memory");

    for (int c = 0; c < 12; c++) {
        asm volatile("cp.async.wait_group 1;" ::: "memory");
        __syncthreads();
        if (c < 10) {
            load_stage(c + 2, (c + 2) % 3);
            asm volatile("cp.async.commit_group;" ::: "memory");
        } else {
            asm volatile("cp.async.commit_group;" ::: "memory");
        }
        uint32_t sA = sb + (c % 3) * STAGE_SZ;
        uint32_t sAl = sA + 16384, sB = sA + 32768;
#pragma unroll
        for (int ks = 0; ks < 4; ks++) {
            uint32_t ah[2][4], al[2][4], bh[4][4];
            uint32_t ac = ((uint32_t)(ks * 2 + alc) ^ arx) << 4;
            uint32_t bc = ((uint32_t)(ks * 2 + blc) ^ brx) << 4;
#pragma unroll
            for (int mi = 0; mi < 2; mi++) {
                ldsm4(ah[mi], sA  + aoff[mi] + ac);
                ldsm4(al[mi], sAl + aoff[mi] + ac);
            }
#pragma unroll
            for (int ni = 0; ni < 4; ni++) ldsm4(bh[ni], sB + boff[ni] + bc);
#pragma unroll
            for (int mi = 0; mi < 2; mi++)
#pragma unroll
                for (int nj = 0; nj < 8; nj++) {
                    int ni = nj >> 1, hf = (nj & 1) * 2;
                    mma16816(acc[mi][nj], ah[mi], bh[ni][hf], bh[ni][hf + 1]);
                    mma16816(acc[mi][nj], al[mi], bh[ni][hf], bh[ni][hf + 1]);
                }
        }
    }

    __syncthreads();
    int g = lane >> 2, t4 = lane & 3;
#pragma unroll
    for (int mi = 0; mi < 2; mi++) {
        int r0 = m0 + wm * 32 + mi * 16 + g;
#pragma unroll
        for (int nj = 0; nj < 8; nj++) {
            int cc = n0 + wn * 64 + nj * 8 + t4 * 2;
#pragma unroll
            for (int half = 0; half < 2; half++) {
                int m = r0 + half * 8;
                float v0 = acc[mi][nj][half * 2 + 0];
                float v1 = acc[mi][nj][half * 2 + 1];
                if (OUT) {
                    float2 o = make_float2(v0 + bias_o[cc], v1 + bias_o[cc + 1]);
                    *(float2*)(outp + (size_t)m * Dd + cc) = o;
                } else {
                    const float* bias = bp.b[z];
                    float scale = (z == 0) ? 0.125f : 1.0f;
                    v0 = (v0 + bias[cc]) * scale;
                    v1 = (v1 + bias[cc + 1]) * scale;
                    int b = m >> 12, s = m & 4095;
                    int h = cc >> 6, d0 = cc & 63;
                    size_t base = (((size_t)(b * Hh + h)) * Ss + s) * DHd + d0;
                    if (z >= 3) {
                        float* dstz = (z == 3) ? g_kg : g_vg;
                        *(float2*)(dstz + base) = make_float2(v0, v1);
                    } else if (z == 0) {
                        uint32_t hi, lo;
                        pack_hilo_h(v0, v1, hi, lo);
                        *(uint32_t*)(g_qhi + base) = hi;
                        *(uint32_t*)(g_qlo + base) = lo;
                    } else {
                        __half* dst = (z == 1) ? g_kf : g_vf;
                        *(uint32_t*)(dst + base) = pack_h2(v0, v1);
                    }
                }
            }
        }
    }
}

// ================= local attention: fp16 2/1-product FA2 =================
#define LA_KOK   0
#define LA_Q     1024
#define LA_QL    (LA_Q  + 16384)
#define LA_K     (LA_QL + 16384)
#define LA_V     (LA_K  + 16384)
#define LA_SMEM  (LA_V  + 16384)

__global__ __launch_bounds__(256) void local_attn(const int* __restrict__ mask)
{
    extern __shared__ char smem[];
    uint32_t sb = smem_u32(smem);
    float* kok = (float*)(smem + LA_KOK);

    int n = blockIdx.x, h = blockIdx.y, b = blockIdx.z;
    int tid = threadIdx.x;
    int wid = tid >> 5, lane = tid & 31;
    int g = lane >> 2, t4 = lane & 3;
    int qr = wid * 16;

    size_t bhbase = ((size_t)(b * Hh + h)) * Ss * DHd;
    const __half* qh_g = g_qhi + bhbase + (size_t)n * Ww * DHd;
    const __half* ql_g = g_qlo + bhbase + (size_t)n * Ww * DHd;
    const __half* k_g  = g_kf + bhbase;
    const __half* v_g  = g_vf + bhbase;
    const int* mk = mask + b * Ss;

#pragma unroll
    for (int it = 0; it < 4; it++) {
        int idx = tid + it * 256;
        int row = idx >> 3, cu = idx & 7;
        uint32_t sw = row * 128 + ((cu ^ (row & 7)) << 4);
        *(uint4*)(smem + LA_Q  + sw) = *(const uint4*)(qh_g + (size_t)row * DHd + cu * 8);
        *(uint4*)(smem + LA_QL + sw) = *(const uint4*)(ql_g + (size_t)row * DHd + cu * 8);
    }

    float sacc[16][4];
    float O[8][4];
#pragma unroll
    for (int j = 0; j < 8; j++)
#pragma unroll
        for (int q = 0; q < 4; q++) O[j][q] = 0.f;
    float m0 = -3.0e38f, m1 = -3.0e38f, l0 = 0.f, l1 = 0.f;

    uint32_t aboff = (qr + (lane & 15)) * 128;
    int arx = lane & 7;
    int alc = lane >> 4;
    int krow_in = (lane & 7) + 8 * ((lane >> 4) & 1);
    int kcc = (lane >> 3) & 1;
    int tkrow = (lane & 7) + 8 * ((lane >> 3) & 1);
    int tdu = lane >> 4;

    for (int c = 0; c < 4; c++) {
        int p0 = (n - 1) * Ww + c * Ww;
        __syncthreads();
        if (tid < 128) {
            bool ok;
            if (c == 3) ok = (tid < Gg) && (mk[tid] > 0);
            else { int p = p0 + tid; ok = (p >= Gg) && (p < Ss) && (mk[p] > 0); }
            kok[tid] = ok ? 1.f : 0.f;
        }
#pragma unroll
        for (int it = 0; it < 4; it++) {
            int idx = tid + it * 256;
            int j = idx >> 3, cu = idx & 7;
            int p = (c == 3) ? j : (p0 + j);
            bool inr = (c == 3) ? (j < Gg) : (p >= 0 && p < Ss);
            uint4 kv = make_uint4(0, 0, 0, 0), vv = make_uint4(0, 0, 0, 0);
            if (inr) {
                size_t gb = (size_t)p * DHd + cu * 8;
                kv = *(const uint4*)(k_g + gb);
                vv = *(const uint4*)(v_g + gb);
            }
            uint32_t sw = j * 128 + ((cu ^ (j & 7)) << 4);
            *(uint4*)(smem + LA_K + sw) = kv;
            *(uint4*)(smem + LA_V + sw) = vv;
        }
        __syncthreads();

#pragma unroll
        for (int j = 0; j < 16; j++)
#pragma unroll
            for (int q = 0; q < 4; q++) sacc[j][q] = 0.f;
#pragma unroll
        for (int ks = 0; ks < 4; ks++) {
            uint32_t qh4[4], ql4[4];
            uint32_t ac = ((uint32_t)(ks * 2 + alc) ^ arx) << 4;
            ldsm4(qh4, sb + LA_Q  + aboff + ac);
            ldsm4(ql4, sb + LA_QL + aboff + ac);
#pragma unroll
            for (int jj = 0; jj < 8; jj++) {
                uint32_t kh4[4];
                uint32_t kb = (16 * jj + krow_in) * 128 + (((uint32_t)(ks * 2 + kcc) ^ arx) << 4);
                ldsm4(kh4, sb + LA_K + kb);
                mma16816(sacc[2 * jj],     qh4, kh4[0], kh4[1]);
                mma16816(sacc[2 * jj],     ql4, kh4[0], kh4[1]);
                mma16816(sacc[2 * jj + 1], qh4, kh4[2], kh4[3]);
                mma16816(sacc[2 * jj + 1], ql4, kh4[2], kh4[3]);
            }
        }

        int row0 = n * Ww + qr + g;
        int row1 = row0 + 8;
#pragma unroll
        for (int j = 0; j < 16; j++) {
#pragma unroll
            for (int q = 0; q < 4; q++) {
                int col = 8 * j + t4 * 2 + (q & 1);
                int row = (q >= 2) ? row1 : row0;
                bool ok = kok[col] > 0.f;
                if (c != 3) {
                    int rel = (p0 + col) - row;
                    ok = ok && (rel <= Ww) && (rel >= -Ww);
                }
                if (!ok) sacc[j][q] = NEGF;
            }
        }

        float mx0 = -3.0e38f, mx1 = -3.0e38f;
#pragma unroll
        for (int j = 0; j < 16; j++) {
            mx0 = fmaxf(mx0, fmaxf(sacc[j][0], sacc[j][1]));
            mx1 = fmaxf(mx1, fmaxf(sacc[j][2], sacc[j][3]));
        }
        mx0 = fmaxf(mx0, __shfl_xor_sync(0xffffffff, mx0, 1));
        mx0 = fmaxf(mx0, __shfl_xor_sync(0xffffffff, mx0, 2));
        mx1 = fmaxf(mx1, __shfl_xor_sync(0xffffffff, mx1, 1));
        mx1 = fmaxf(mx1, __shfl_xor_sync(0xffffffff, mx1, 2));
        float mn0 = fmaxf(m0, mx0), mn1 = fmaxf(m1, mx1);
        float f0 = __expf(m0 - mn0), f1 = __expf(m1 - mn1);
        float s0 = 0.f, s1 = 0.f;
#pragma unroll
        for (int j = 0; j < 16; j++) {
            float p0v = __expf(sacc[j][0] - mn0);
            float p1v = __expf(sacc[j][1] - mn0);
            float p2v = __expf(sacc[j][2] - mn1);
            float p3v = __expf(sacc[j][3] - mn1);
            sacc[j][0] = p0v; sacc[j][1] = p1v; sacc[j][2] = p2v; sacc[j][3] = p3v;
            s0 += p0v + p1v; s1 += p2v + p3v;
        }
        s0 += __shfl_xor_sync(0xffffffff, s0, 1);
        s0 += __shfl_xor_sync(0xffffffff, s0, 2);
        s1 += __shfl_xor_sync(0xffffffff, s1, 1);
        s1 += __shfl_xor_sync(0xffffffff, s1, 2);
        l0 = l0 * f0 + s0; l1 = l1 * f1 + s1;
        m0 = mn0; m1 = mn1;
#pragma unroll
        for (int j = 0; j < 8; j++) {
            O[j][0] *= f0; O[j][1] *= f0; O[j][2] *= f1; O[j][3] *= f1;
        }

#pragma unroll
        for (int ks = 0; ks < 8; ks++) {
            uint32_t pa[4];
            pa[0] = pack_h2(sacc[2 * ks][0],     sacc[2 * ks][1]);
            pa[1] = pack_h2(sacc[2 * ks][2],     sacc[2 * ks][3]);
            pa[2] = pack_h2(sacc[2 * ks + 1][0], sacc[2 * ks + 1][1]);
            pa[3] = pack_h2(sacc[2 * ks + 1][2], sacc[2 * ks + 1][3]);
#pragma unroll
            for (int jd = 0; jd < 4; jd++) {
                uint32_t vh4[4];
                uint32_t vb = (uint32_t)(16 * ks + tkrow) * 128 +
                              (((uint32_t)(jd * 2 + tdu) ^ (uint32_t)(lane & 7)) << 4);
                ldsm4t(vh4, sb + LA_V + vb);
                mma16816(O[2 * jd],     pa, vh4[0], vh4[1]);
                mma16816(O[2 * jd + 1], pa, vh4[2], vh4[3]);
            }
        }
    }

    float inv0 = 1.0f / l0, inv1 = 1.0f / l1;
    int s0r = n * Ww + qr + g;
    int s1r = s0r + 8;
    size_t b0 = ((size_t)b * Ss + s0r) * Dd + h * DHd;
    size_t b1 = ((size_t)b * Ss + s1r) * Dd + h * DHd;
#pragma unroll
    for (int jd = 0; jd < 8; jd++) {
        int cc = 8 * jd + t4 * 2;
        uint32_t hi, lo;
        pack_hilo_h(O[jd][0] * inv0, O[jd][1] * inv0, hi, lo);
        *(uint32_t*)(g_ahi + b0 + cc) = hi;
        *(uint32_t*)(g_alo + b0 + cc) = lo;
        pack_hilo_h(O[jd][2] * inv1, O[jd][3] * inv1, hi, lo);
        *(uint32_t*)(g_ahi + b1 + cc) = hi;
        *(uint32_t*)(g_alo + b1 + cc) = lo;
    }
}

// ---------------- qg projection ----------------
__global__ __launch_bounds__(256) void qg_proj(const float* __restrict__ x,
                                               const float* __restrict__ Wqg,
                                               const float* __restrict__ bqg)
{
    __shared__ float xr[768];
    __shared__ float sred[256];
    int bg = blockIdx.x, cc = blockIdx.y;
    int b = bg >> 4, g = bg & 15;
    int tid = threadIdx.x;
    for (int i = tid; i < 768; i += 256) xr[i] = x[((size_t)b * Ss + g) * Dd + i];
    __syncthreads();
    int col = cc * 32 + (tid & 31);
    int ks = tid >> 5;
    int k0 = ks * 96;
    float acc = 0.f;
#pragma unroll 8
    for (int k = 0; k < 96; k++)
        acc += xr[k0 + k] * Wqg[(size_t)(k0 + k) * 768 + col];
    sred[tid] = acc;
    __syncthreads();
    if (tid < 32) {
        float tot = 0.f;
#pragma unroll
        for (int j = 0; j < 8; j++) tot += sred[tid + 32 * j];
        int c = cc * 32 + tid;
        float vv = (tot + bqg[c]) * 0.125f;
        g_qg[(((size_t)b * Hh + (c >> 6)) * Gg + g) * DHd + (c & 63)] = vv;
    }
}

// ---------------- global-row attention: 32-way split ----------------
__global__ __launch_bounds__(256) void gattn_part(const int* __restrict__ mask)
{
    extern __shared__ float sm[];
    float* Qgs  = sm;
    float* Kts  = Qgs + 16 * 68;
    float* Vs   = Kts + 64 * 132;
    float* Ps   = Vs + 128 * 68;
    float* rowm = Ps + 16 * 129;
    float* rowl = rowm + 16;

    int si = blockIdx.x, h = blockIdx.y, b = blockIdx.z;
    int tid = threadIdx.x;
    const float* kgb = g_kg + ((size_t)(b * Hh + h)) * Ss * DHd;
    const float* vgb = g_vg + ((size_t)(b * Hh + h)) * Ss * DHd;
    const int* mk = mask + b * Ss;

    for (int i = tid; i < 16 * 64; i += 256) {
        int r = i >> 6, d = i & 63;
        Qgs[r * 68 + d] = g_qg[(((size_t)b * Hh + h) * Gg + r) * DHd + d];
    }

    int p0 = si * 128;
    int r = tid >> 4, cg = tid & 15;
#pragma unroll
    for (int it = 0; it < 8; it++) {
        int idx = tid + it * 256;
        int j = idx >> 4, cv = idx & 15;
        int p = p0 + j;
        float4 kv = *(const float4*)(kgb + (size_t)p * 64 + cv * 4);
        float4 vv = *(const float4*)(vgb + (size_t)p * 64 + cv * 4);
        Kts[(cv * 4 + 0) * 132 + j] = kv.x;
        Kts[(cv * 4 + 1) * 132 + j] = kv.y;
        Kts[(cv * 4 + 2) * 132 + j] = kv.z;
        Kts[(cv * 4 + 3) * 132 + j] = kv.w;
        *(float4*)&Vs[j * 68 + cv * 4] = vv;
    }
    __syncthreads();

    float sc8[8] = {0.f, 0.f, 0.f, 0.f, 0.f, 0.f, 0.f, 0.f};
#pragma unroll 8
    for (int d = 0; d < 64; d++) {
        float a = Qgs[r * 68 + d];
#pragma unroll
        for (int j = 0; j < 8; j++) sc8[j] += a * Kts[d * 132 + cg * 8 + j];
    }
#pragma unroll
    for (int j = 0; j < 8; j++) {
        int p = p0 + cg * 8 + j;
        Ps[r * 129 + cg * 8 + j] = (mk[p] > 0) ? sc8[j] : NEGF;
    }
    __syncthreads();

    if (tid < 16) {
        float cm = -3.0e38f;
        for (int j2 = 0; j2 < 128; j2++) cm = fmaxf(cm, Ps[tid * 129 + j2]);
        float ls = 0.f;
        for (int j2 = 0; j2 < 128; j2++) {
            float pv = __expf(Ps[tid * 129 + j2] - cm);
            Ps[tid * 129 + j2] = pv;
            ls += pv;
        }
        rowm[tid] = cm;
        rowl[tid] = ls;
    }
    __syncthreads();

    float oacc[4] = {0.f, 0.f, 0.f, 0.f};
    for (int kk = 0; kk < 128; kk++) {
        float a = Ps[r * 129 + kk];
#pragma unroll
        for (int j = 0; j < 4; j++) oacc[j] += a * Vs[kk * 68 + cg * 4 + j];
    }
    int part = (b * Hh + h) * NSPLIT + si;
#pragma unroll
    for (int j = 0; j < 4; j++)
        g_pacc[((size_t)part * 16 + r) * 64 + cg * 4 + j] = oacc[j];
    if (cg == 0) {
        g_pm[part * 16 + r] = rowm[r];
        g_pl[part * 16 + r] = rowl[r];
    }
}

__global__ __launch_bounds__(32) void gattn_combine()
{
    int bh = blockIdx.x;
    int b = bh / Hh, h = bh % Hh;
    int t = threadIdx.x;
    for (int r = 0; r < Gg; r++) {
        float M = -3.0e38f;
        for (int si = 0; si < NSPLIT; si++)
            M = fmaxf(M, g_pm[((b * Hh + h) * NSPLIT + si) * 16 + r]);
        float L = 0.f, a0 = 0.f, a1 = 0.f;
        for (int si = 0; si < NSPLIT; si++) {
            int part = (b * Hh + h) * NSPLIT + si;
            float w = __expf(g_pm[part * 16 + r] - M);
            L += w * g_pl[part * 16 + r];
            a0 += w * g_pacc[((size_t)part * 16 + r) * 64 + 2 * t];
            a1 += w * g_pacc[((size_t)part * 16 + r) * 64 + 2 * t + 1];
        }
        uint32_t hi, lo;
        pack_hilo_h(a0 / L, a1 / L, hi, lo);
        size_t base = ((size_t)b * Ss + r) * Dd + h * DHd + 2 * t;
        *(uint32_t*)(g_ahi + base) = hi;
        *(uint32_t*)(g_alo + base) = lo;
    }
}

// ---------------- launch ----------------
extern "C" void kernel_launch(void* const* d_in, const int* in_sizes, int n_in,
                              void* d_out, int out_size)
{
    (void)in_sizes; (void)n_in; (void)out_size;
    const float* x    = (const float*)d_in[0];
    const int*   mask = (const int*)d_in[1];
    W6 w6;
    w6.w[0] = (const float*)d_in[2];
    w6.w[1] = (const float*)d_in[4];
    w6.w[2] = (const float*)d_in[6];
    w6.w[3] = (const float*)d_in[10];
    w6.w[4] = (const float*)d_in[12];
    w6.w[5] = (const float*)d_in[14];
    Bia5 b5;
    b5.b[0] = (const float*)d_in[3];
    b5.b[1] = (const float*)d_in[5];
    b5.b[2] = (const float*)d_in[7];
    b5.b[3] = (const float*)d_in[11];
    b5.b[4] = (const float*)d_in[13];
    const float* Wqg = (const float*)d_in[8];
    const float* bqg = (const float*)d_in[9];
    const float* bo  = (const float*)d_in[15];
    float* out = (float*)d_out;

    int gsm = (16 * 68 + 64 * 132 + 128 * 68 + 16 * 129 + 2 * 16) * 4;
    cudaFuncSetAttribute(gattn_part, cudaFuncAttributeMaxDynamicSharedMemorySize, gsm);
    cudaFuncSetAttribute(mma_gemm<false>, cudaFuncAttributeMaxDynamicSharedMemorySize, GEMM_SMEM);
    cudaFuncSetAttribute(mma_gemm<true>,  cudaFuncAttributeMaxDynamicSharedMemorySize, GEMM_SMEM);
    cudaFuncSetAttribute(local_attn, cudaFuncAttributeMaxDynamicSharedMemorySize, LA_SMEM);

    __half *xhi, *xlo, *ahi, *alo;
    cudaGetSymbolAddress((void**)&xhi, g_xhi);
    cudaGetSymbolAddress((void**)&xlo, g_xlo);
    cudaGetSymbolAddress((void**)&ahi, g_ahi);
    cudaGetSymbolAddress((void**)&alo, g_alo);

    int n4 = Bb * Ss * Dd / 4;
    to_f16_split<<<(n4 + 255) / 256, 256>>>(x, xhi, xlo, n4);              // 1
    prep_w<<<dim3(24, 24, 6), dim3(32, 8)>>>(w6);                          // 2
    qg_proj<<<dim3(Bb * Gg, 24), 256>>>(x, Wqg, bqg);                      // 3
    mma_gemm<false><<<dim3(3, 64, 5), 512, GEMM_SMEM>>>(xhi, xlo, b5, nullptr, nullptr); // 4 (profiled)
    local_attn<<<dim3(NBb, Hh, Bb), 256, LA_SMEM>>>(mask);                 // 5
    gattn_part<<<dim3(NSPLIT, Hh, Bb), 256, gsm>>>(mask);                  // 6
    gattn_combine<<<Bb * Hh, 32>>>();                                      // 7
    mma_gemm<true><<<dim3(3, 64), 512, GEMM_SMEM>>>(ahi, alo, b5, bo, out); // 8
}

// round 11
// speedup vs baseline: 4.3940x; 1.3289x over previous
#include <cuda_runtime.h>
#include <cuda_fp16.h>
#include <cstdint>

#define Bb 2
#define Ss 4096
#define Dd 768
#define Hh 12
#define DHd 64
#define Ww 128
#define Gg 16
#define NBb 32
#define NSPLIT 32
#define NEGF (-1.0e9f)

// ---------------- scratch (device globals; no allocation) ----------------
__device__ float g_kg[Bb*Hh*Ss*DHd];
__device__ float g_vg[Bb*Hh*Ss*DHd];
__device__ float g_qg[Bb*Hh*Gg*DHd];
__device__ float g_pm  [Bb*Hh*NSPLIT*Gg];
__device__ float g_pl  [Bb*Hh*NSPLIT*Gg];
__device__ float g_pacc[Bb*Hh*NSPLIT*Gg*DHd];

__device__ __half g_x  [Bb*Ss*Dd];
__device__ __half g_a  [Bb*Ss*Dd];
__device__ __half g_wt [6*Dd*Dd];
__device__ __half g_qf [Bb*Hh*Ss*DHd];
__device__ __half g_kf [Bb*Hh*Ss*DHd];
__device__ __half g_vf [Bb*Hh*Ss*DHd];

struct W6   { const float* w[6]; };
struct Bia5 { const float* b[5]; };

// ================= warp-MMA helpers =================
#define SWZ(o) ((o) ^ (((o) >> 3) & 0x70))

__device__ __forceinline__ uint32_t smem_u32(const void* p) {
    uint32_t a;
    asm("{ .reg .u64 t; cvta.to.shared.u64 t, %1; cvt.u32.u64 %0, t; }" : "=r"(a) : "l"(p));
    return a;
}
__device__ __forceinline__ void ldsm4(uint32_t* r, uint32_t addr) {
    asm volatile("ldmatrix.sync.aligned.m8n8.x4.shared.b16 {%0,%1,%2,%3}, [%4];"
                 : "=r"(r[0]), "=r"(r[1]), "=r"(r[2]), "=r"(r[3]) : "r"(addr));
}
__device__ __forceinline__ void ldsm4t(uint32_t* r, uint32_t addr) {
    asm volatile("ldmatrix.sync.aligned.m8n8.x4.trans.shared.b16 {%0,%1,%2,%3}, [%4];"
                 : "=r"(r[0]), "=r"(r[1]), "=r"(r[2]), "=r"(r[3]) : "r"(addr));
}
__device__ __forceinline__ void mma16816(float* d, const uint32_t* a, uint32_t b0, uint32_t b1) {
    asm volatile(
        "mma.sync.aligned.m16n8k16.row.col.f32.f16.f16.f32 "
        "{%0,%1,%2,%3}, {%4,%5,%6,%7}, {%8,%9}, {%0,%1,%2,%3};"
        : "+f"(d[0]), "+f"(d[1]), "+f"(d[2]), "+f"(d[3])
        : "r"(a[0]), "r"(a[1]), "r"(a[2]), "r"(a[3]), "r"(b0), "r"(b1));
}
__device__ __forceinline__ uint32_t pack_h2(float e0, float e1) {
    __half2 h = __floats2half2_rn(e0, e1);
    return *(uint32_t*)&h;
}
__device__ __forceinline__ void cpasync16(uint32_t dst, const void* src) {
    asm volatile("cp.async.cg.shared.global [%0], [%1], 16;" :: "r"(dst), "l"(src) : "memory");
}

// ================= prep kernels =================
__global__ __launch_bounds__(256) void to_f16(const float* __restrict__ in,
                                              __half* __restrict__ out16, int n4)
{
    int i = blockIdx.x * 256 + threadIdx.x;
    if (i >= n4) return;
    float4 v = ((const float4*)in)[i];
    union { __half h[4]; uint2 u; } uh;
    uh.h[0] = __float2half_rn(v.x);
    uh.h[1] = __float2half_rn(v.y);
    uh.h[2] = __float2half_rn(v.z);
    uh.h[3] = __float2half_rn(v.w);
    *(uint2*)(out16 + (size_t)i * 4) = uh.u;
}

__global__ __launch_bounds__(256) void prep_w(W6 ws)
{
    __shared__ float t[32][33];
    int z = blockIdx.z;
    const float* W = ws.w[z];
    __half* oh = g_wt + (size_t)z * Dd * Dd;
    int k0 = blockIdx.x * 32, n0 = blockIdx.y * 32;
    int tx = threadIdx.x, ty = threadIdx.y;
#pragma unroll
    for (int r = 0; r < 4; r++)
        t[ty + r * 8][tx] = W[(size_t)(k0 + ty + r * 8) * Dd + n0 + tx];
    __syncthreads();
#pragma unroll
    for (int r = 0; r < 4; r++)
        oh[(size_t)(n0 + ty + r * 8) * Dd + k0 + tx] = __float2half_rn(t[tx][ty + r * 8]);
}

// ===== fp16 single-product GEMM: BM128 x BN256, 512 thr, 3-stage cp.async =====
// stage: A 16K | B 32K = 48KB
#define STAGE_SZ 49152
#define GEMM_SMEM (3 * STAGE_SZ)

template<bool OUT>
__global__ __launch_bounds__(512)
void mma_gemm(const __half* __restrict__ Af,
              Bia5 bp, const float* __restrict__ bias_o, float* __restrict__ outp)
{
    extern __shared__ char smem[];
    uint32_t sb = smem_u32(smem);
    int tid = threadIdx.x;
    int wid = tid >> 5, lane = tid & 31;
    int wm = wid >> 2, wn = wid & 3;          // warp tile 32m x 64n
    int z = OUT ? 5 : blockIdx.z;
    int n0 = blockIdx.x * 256, m0 = blockIdx.y * 128;

    const __half* Bw = g_wt + (size_t)z * Dd * Dd + (size_t)n0 * Dd;
    const __half* Ah = Af + (size_t)m0 * Dd;

    float acc[2][8][4];
#pragma unroll
    for (int i = 0; i < 2; i++)
#pragma unroll
        for (int j = 0; j < 8; j++)
#pragma unroll
            for (int q = 0; q < 4; q++) acc[i][j][q] = 0.f;

    int alr = lane & 15, alc = lane >> 4, arx = lane & 7;
    uint32_t aoff[2];
#pragma unroll
    for (int mi = 0; mi < 2; mi++) aoff[mi] = (wm * 32 + mi * 16 + alr) * 128;
    int blr = (lane & 7) + ((lane >> 4) & 1) * 8;
    int blc = (lane >> 3) & 1, brx = lane & 7;
    uint32_t boff[4];
#pragma unroll
    for (int ni = 0; ni < 4; ni++) boff[ni] = (wn * 64 + ni * 16 + blr) * 128;

    // loader: idx 0-1023 A (128 rows), 1024-3071 B (256 rows)
    auto load_stage = [&](int c, int s) {
        int k0 = c * 64;
        uint32_t base = sb + s * STAGE_SZ;
#pragma unroll
        for (int it = 0; it < 6; it++) {
            int idx = tid + it * 512;
            int cu = idx & 7;
            if (idx < 1024) {
                int row = idx >> 3;
                cpasync16(base + SWZ(row * 128 + cu * 16),
                          Ah + k0 + (size_t)row * Dd + cu * 8);
            } else {
                int row = (idx - 1024) >> 3;
                cpasync16(base + 16384 + SWZ(row * 128 + cu * 16),
                          Bw + k0 + (size_t)row * Dd + cu * 8);
            }
        }
    };

    load_stage(0, 0);
    asm volatile("cp.async.commit_group;" ::: "memory");
    load_stage(1, 1);
    asm volatile("cp.async.commit_group;" ::: "memory");

    for (int c = 0; c < 12; c++) {
        asm volatile("cp.async.wait_group 1;" ::: "memory");
        __syncthreads();
        if (c < 10) {
            load_stage(c + 2, (c + 2) % 3);
            asm volatile("cp.async.commit_group;" ::: "memory");
        } else {
            asm volatile("cp.async.commit_group;" ::: "memory");
        }
        uint32_t sA = sb + (c % 3) * STAGE_SZ;
        uint32_t sB = sA + 16384;
#pragma unroll
        for (int ks = 0; ks < 4; ks++) {
            uint32_t ah[2][4], bh[4][4];
            uint32_t ac = ((uint32_t)(ks * 2 + alc) ^ arx) << 4;
            uint32_t bc = ((uint32_t)(ks * 2 + blc) ^ brx) << 4;
#pragma unroll
            for (int mi = 0; mi < 2; mi++) ldsm4(ah[mi], sA + aoff[mi] + ac);
#pragma unroll
            for (int ni = 0; ni < 4; ni++) ldsm4(bh[ni], sB + boff[ni] + bc);
#pragma unroll
            for (int mi = 0; mi < 2; mi++)
#pragma unroll
                for (int nj = 0; nj < 8; nj++) {
                    int ni = nj >> 1, hf = (nj & 1) * 2;
                    mma16816(acc[mi][nj], ah[mi], bh[ni][hf], bh[ni][hf + 1]);
                }
        }
    }

    __syncthreads();
    int g = lane >> 2, t4 = lane & 3;
#pragma unroll
    for (int mi = 0; mi < 2; mi++) {
        int r0 = m0 + wm * 32 + mi * 16 + g;
#pragma unroll
        for (int nj = 0; nj < 8; nj++) {
            int cc = n0 + wn * 64 + nj * 8 + t4 * 2;
#pragma unroll
            for (int half = 0; half < 2; half++) {
                int m = r0 + half * 8;
                float v0 = acc[mi][nj][half * 2 + 0];
                float v1 = acc[mi][nj][half * 2 + 1];
                if (OUT) {
                    float2 o = make_float2(v0 + bias_o[cc], v1 + bias_o[cc + 1]);
                    *(float2*)(outp + (size_t)m * Dd + cc) = o;
                } else {
                    const float* bias = bp.b[z];
                    float scale = (z == 0) ? 0.125f : 1.0f;
                    v0 = (v0 + bias[cc]) * scale;
                    v1 = (v1 + bias[cc + 1]) * scale;
                    int b = m >> 12, s = m & 4095;
                    int h = cc >> 6, d0 = cc & 63;
                    size_t base = (((size_t)(b * Hh + h)) * Ss + s) * DHd + d0;
                    if (z >= 3) {
                        float* dstz = (z == 3) ? g_kg : g_vg;
                        *(float2*)(dstz + base) = make_float2(v0, v1);
                    } else {
                        __half* dst = (z == 0) ? g_qf : ((z == 1) ? g_kf : g_vf);
                        *(uint32_t*)(dst + base) = pack_h2(v0, v1);
                    }
                }
            }
        }
    }
}

// ================= local attention: fp16 single-product FA2 =================
// smem: kok[128]f @0 (pad 1024) | Q 16K | K 16K | V 16K
#define LA_KOK   0
#define LA_Q     1024
#define LA_K     (LA_Q + 16384)
#define LA_V     (LA_K + 16384)
#define LA_SMEM  (LA_V + 16384)

__global__ __launch_bounds__(256) void local_attn(const int* __restrict__ mask)
{
    extern __shared__ char smem[];
    uint32_t sb = smem_u32(smem);
    float* kok = (float*)(smem + LA_KOK);

    int n = blockIdx.x, h = blockIdx.y, b = blockIdx.z;
    int tid = threadIdx.x;
    int wid = tid >> 5, lane = tid & 31;
    int g = lane >> 2, t4 = lane & 3;
    int qr = wid * 16;

    size_t bhbase = ((size_t)(b * Hh + h)) * Ss * DHd;
    const __half* q_g = g_qf + bhbase + (size_t)n * Ww * DHd;
    const __half* k_g = g_kf + bhbase;
    const __half* v_g = g_vf + bhbase;
    const int* mk = mask + b * Ss;

#pragma unroll
    for (int it = 0; it < 4; it++) {
        int idx = tid + it * 256;
        int row = idx >> 3, cu = idx & 7;
        uint32_t sw = row * 128 + ((cu ^ (row & 7)) << 4);
        *(uint4*)(smem + LA_Q + sw) = *(const uint4*)(q_g + (size_t)row * DHd + cu * 8);
    }

    float sacc[16][4];
    float O[8][4];
#pragma unroll
    for (int j = 0; j < 8; j++)
#pragma unroll
        for (int q = 0; q < 4; q++) O[j][q] = 0.f;
    float m0 = -3.0e38f, m1 = -3.0e38f, l0 = 0.f, l1 = 0.f;

    uint32_t aboff = (qr + (lane & 15)) * 128;
    int arx = lane & 7;
    int alc = lane >> 4;
    int krow_in = (lane & 7) + 8 * ((lane >> 4) & 1);
    int kcc = (lane >> 3) & 1;
    int tkrow = (lane & 7) + 8 * ((lane >> 3) & 1);
    int tdu = lane >> 4;

    for (int c = 0; c < 4; c++) {
        int p0 = (n - 1) * Ww + c * Ww;
        __syncthreads();
        if (tid < 128) {
            bool ok;
            if (c == 3) ok = (tid < Gg) && (mk[tid] > 0);
            else { int p = p0 + tid; ok = (p >= Gg) && (p < Ss) && (mk[p] > 0); }
            kok[tid] = ok ? 1.f : 0.f;
        }
#pragma unroll
        for (int it = 0; it < 4; it++) {
            int idx = tid + it * 256;
            int j = idx >> 3, cu = idx & 7;
            int p = (c == 3) ? j : (p0 + j);
            bool inr = (c == 3) ? (j < Gg) : (p >= 0 && p < Ss);
            uint4 kv = make_uint4(0, 0, 0, 0), vv = make_uint4(0, 0, 0, 0);
            if (inr) {
                size_t gb = (size_t)p * DHd + cu * 8;
                kv = *(const uint4*)(k_g + gb);
                vv = *(const uint4*)(v_g + gb);
            }
            uint32_t sw = j * 128 + ((cu ^ (j & 7)) << 4);
            *(uint4*)(smem + LA_K + sw) = kv;
            *(uint4*)(smem + LA_V + sw) = vv;
        }
        __syncthreads();

        // ---- S = Q.K^T (single product) ----
#pragma unroll
        for (int j = 0; j < 16; j++)
#pragma unroll
            for (int q = 0; q < 4; q++) sacc[j][q] = 0.f;
#pragma unroll
        for (int ks = 0; ks < 4; ks++) {
            uint32_t qh4[4];
            uint32_t ac = ((uint32_t)(ks * 2 + alc) ^ arx) << 4;
            ldsm4(qh4, sb + LA_Q + aboff + ac);
#pragma unroll
            for (int jj = 0; jj < 8; jj++) {
                uint32_t kh4[4];
                uint32_t kb = (16 * jj + krow_in) * 128 + (((uint32_t)(ks * 2 + kcc) ^ arx) << 4);
                ldsm4(kh4, sb + LA_K + kb);
                mma16816(sacc[2 * jj],     qh4, kh4[0], kh4[1]);
                mma16816(sacc[2 * jj + 1], qh4, kh4[2], kh4[3]);
            }
        }

        // ---- mask ----
        int row0 = n * Ww + qr + g;
        int row1 = row0 + 8;
#pragma unroll
        for (int j = 0; j < 16; j++) {
#pragma unroll
            for (int q = 0; q < 4; q++) {
                int col = 8 * j + t4 * 2 + (q & 1);
                int row = (q >= 2) ? row1 : row0;
                bool ok = kok[col] > 0.f;
                if (c != 3) {
                    int rel = (p0 + col) - row;
                    ok = ok && (rel <= Ww) && (rel >= -Ww);
                }
                if (!ok) sacc[j][q] = NEGF;
            }
        }

        // ---- online softmax ----
        float mx0 = -3.0e38f, mx1 = -3.0e38f;
#pragma unroll
        for (int j = 0; j < 16; j++) {
            mx0 = fmaxf(mx0, fmaxf(sacc[j][0], sacc[j][1]));
            mx1 = fmaxf(mx1, fmaxf(sacc[j][2], sacc[j][3]));
        }
        mx0 = fmaxf(mx0, __shfl_xor_sync(0xffffffff, mx0, 1));
        mx0 = fmaxf(mx0, __shfl_xor_sync(0xffffffff, mx0, 2));
        mx1 = fmaxf(mx1, __shfl_xor_sync(0xffffffff, mx1, 1));
        mx1 = fmaxf(mx1, __shfl_xor_sync(0xffffffff, mx1, 2));
        float mn0 = fmaxf(m0, mx0), mn1 = fmaxf(m1, mx1);
        float f0 = __expf(m0 - mn0), f1 = __expf(m1 - mn1);
        float s0 = 0.f, s1 = 0.f;
#pragma unroll
        for (int j = 0; j < 16; j++) {
            float p0v = __expf(sacc[j][0] - mn0);
            float p1v = __expf(sacc[j][1] - mn0);
            float p2v = __expf(sacc[j][2] - mn1);
            float p3v = __expf(sacc[j][3] - mn1);
            sacc[j][0] = p0v; sacc[j][1] = p1v; sacc[j][2] = p2v; sacc[j][3] = p3v;
            s0 += p0v + p1v; s1 += p2v + p3v;
        }
        s0 += __shfl_xor_sync(0xffffffff, s0, 1);
        s0 += __shfl_xor_sync(0xffffffff, s0, 2);
        s1 += __shfl_xor_sync(0xffffffff, s1, 1);
        s1 += __shfl_xor_sync(0xffffffff, s1, 2);
        l0 = l0 * f0 + s0; l1 = l1 * f1 + s1;
        m0 = mn0; m1 = mn1;
#pragma unroll
        for (int j = 0; j < 8; j++) {
            O[j][0] *= f0; O[j][1] *= f0; O[j][2] *= f1; O[j][3] *= f1;
        }

        // ---- O += P.V ----
#pragma unroll
        for (int ks = 0; ks < 8; ks++) {
            uint32_t pa[4];
            pa[0] = pack_h2(sacc[2 * ks][0],     sacc[2 * ks][1]);
            pa[1] = pack_h2(sacc[2 * ks][2],     sacc[2 * ks][3]);
            pa[2] = pack_h2(sacc[2 * ks + 1][0], sacc[2 * ks + 1][1]);
            pa[3] = pack_h2(sacc[2 * ks + 1][2], sacc[2 * ks + 1][3]);
#pragma unroll
            for (int jd = 0; jd < 4; jd++) {
                uint32_t vh4[4];
                uint32_t vb = (uint32_t)(16 * ks + tkrow) * 128 +
                              (((uint32_t)(jd * 2 + tdu) ^ (uint32_t)(lane & 7)) << 4);
                ldsm4t(vh4, sb + LA_V + vb);
                mma16816(O[2 * jd],     pa, vh4[0], vh4[1]);
                mma16816(O[2 * jd + 1], pa, vh4[2], vh4[3]);
            }
        }
    }

    // ---- write out as fp16 (feeds out-proj) ----
    float inv0 = 1.0f / l0, inv1 = 1.0f / l1;
    int s0r = n * Ww + qr + g;
    int s1r = s0r + 8;
    size_t b0 = ((size_t)b * Ss + s0r) * Dd + h * DHd;
    size_t b1 = ((size_t)b * Ss + s1r) * Dd + h * DHd;
#pragma unroll
    for (int jd = 0; jd < 8; jd++) {
        int cc = 8 * jd + t4 * 2;
        *(uint32_t*)(g_a + b0 + cc) = pack_h2(O[jd][0] * inv0, O[jd][1] * inv0);
        *(uint32_t*)(g_a + b1 + cc) = pack_h2(O[jd][2] * inv1, O[jd][3] * inv1);
    }
}

// ---------------- qg projection ----------------
__global__ __launch_bounds__(256) void qg_proj(const float* __restrict__ x,
                                               const float* __restrict__ Wqg,
                                               const float* __restrict__ bqg)
{
    __shared__ float xr[768];
    __shared__ float sred[256];
    int bg = blockIdx.x, cc = blockIdx.y;
    int b = bg >> 4, g = bg & 15;
    int tid = threadIdx.x;
    for (int i = tid; i < 768; i += 256) xr[i] = x[((size_t)b * Ss + g) * Dd + i];
    __syncthreads();
    int col = cc * 32 + (tid & 31);
    int ks = tid >> 5;
    int k0 = ks * 96;
    float acc = 0.f;
#pragma unroll 8
    for (int k = 0; k < 96; k++)
        acc += xr[k0 + k] * Wqg[(size_t)(k0 + k) * 768 + col];
    sred[tid] = acc;
    __syncthreads();
    if (tid < 32) {
        float tot = 0.f;
#pragma unroll
        for (int j = 0; j < 8; j++) tot += sred[tid + 32 * j];
        int c = cc * 32 + tid;
        float vv = (tot + bqg[c]) * 0.125f;
        g_qg[(((size_t)b * Hh + (c >> 6)) * Gg + g) * DHd + (c & 63)] = vv;
    }
}

// ---------------- global-row attention: 32-way split ----------------
__global__ __launch_bounds__(256) void gattn_part(const int* __restrict__ mask)
{
    extern __shared__ float sm[];
    float* Qgs  = sm;
    float* Kts  = Qgs + 16 * 68;
    float* Vs   = Kts + 64 * 132;
    float* Ps   = Vs + 128 * 68;
    float* rowm = Ps + 16 * 129;
    float* rowl = rowm + 16;

    int si = blockIdx.x, h = blockIdx.y, b = blockIdx.z;
    int tid = threadIdx.x;
    const float* kgb = g_kg + ((size_t)(b * Hh + h)) * Ss * DHd;
    const float* vgb = g_vg + ((size_t)(b * Hh + h)) * Ss * DHd;
    const int* mk = mask + b * Ss;

    for (int i = tid; i < 16 * 64; i += 256) {
        int r = i >> 6, d = i & 63;
        Qgs[r * 68 + d] = g_qg[(((size_t)b * Hh + h) * Gg + r) * DHd + d];
    }

    int p0 = si * 128;
    int r = tid >> 4, cg = tid & 15;
#pragma unroll
    for (int it = 0; it < 8; it++) {
        int idx = tid + it * 256;
        int j = idx >> 4, cv = idx & 15;
        int p = p0 + j;
        float4 kv = *(const float4*)(kgb + (size_t)p * 64 + cv * 4);
        float4 vv = *(const float4*)(vgb + (size_t)p * 64 + cv * 4);
        Kts[(cv * 4 + 0) * 132 + j] = kv.x;
        Kts[(cv * 4 + 1) * 132 + j] = kv.y;
        Kts[(cv * 4 + 2) * 132 + j] = kv.z;
        Kts[(cv * 4 + 3) * 132 + j] = kv.w;
        *(float4*)&Vs[j * 68 + cv * 4] = vv;
    }
    __syncthreads();

    float sc8[8] = {0.f, 0.f, 0.f, 0.f, 0.f, 0.f, 0.f, 0.f};
#pragma unroll 8
    for (int d = 0; d < 64; d++) {
        float a = Qgs[r * 68 + d];
#pragma unroll
        for (int j = 0; j < 8; j++) sc8[j] += a * Kts[d * 132 + cg * 8 + j];
    }
#pragma unroll
    for (int j = 0; j < 8; j++) {
        int p = p0 + cg * 8 + j;
        Ps[r * 129 + cg * 8 + j] = (mk[p] > 0) ? sc8[j] : NEGF;
    }
    __syncthreads();

    if (tid < 16) {
        float cm = -3.0e38f;
        for (int j2 = 0; j2 < 128; j2++) cm = fmaxf(cm, Ps[tid * 129 + j2]);
        float ls = 0.f;
        for (int j2 = 0; j2 < 128; j2++) {
            float pv = __expf(Ps[tid * 129 + j2] - cm);
            Ps[tid * 129 + j2] = pv;
            ls += pv;
        }
        rowm[tid] = cm;
        rowl[tid] = ls;
    }
    __syncthreads();

    float oacc[4] = {0.f, 0.f, 0.f, 0.f};
    for (int kk = 0; kk < 128; kk++) {
        float a = Ps[r * 129 + kk];
#pragma unroll
        for (int j = 0; j < 4; j++) oacc[j] += a * Vs[kk * 68 + cg * 4 + j];
    }
    int part = (b * Hh + h) * NSPLIT + si;
#pragma unroll
    for (int j = 0; j < 4; j++)
        g_pacc[((size_t)part * 16 + r) * 64 + cg * 4 + j] = oacc[j];
    if (cg == 0) {
        g_pm[part * 16 + r] = rowm[r];
        g_pl[part * 16 + r] = rowl[r];
    }
}

__global__ __launch_bounds__(32) void gattn_combine()
{
    int bh = blockIdx.x;
    int b = bh / Hh, h = bh % Hh;
    int t = threadIdx.x;
    for (int r = 0; r < Gg; r++) {
        float M = -3.0e38f;
        for (int si = 0; si < NSPLIT; si++)
            M = fmaxf(M, g_pm[((b * Hh + h) * NSPLIT + si) * 16 + r]);
        float L = 0.f, a0 = 0.f, a1 = 0.f;
        for (int si = 0; si < NSPLIT; si++) {
            int part = (b * Hh + h) * NSPLIT + si;
            float w = __expf(g_pm[part * 16 + r] - M);
            L += w * g_pl[part * 16 + r];
            a0 += w * g_pacc[((size_t)part * 16 + r) * 64 + 2 * t];
            a1 += w * g_pacc[((size_t)part * 16 + r) * 64 + 2 * t + 1];
        }
        size_t base = ((size_t)b * Ss + r) * Dd + h * DHd + 2 * t;
        *(uint32_t*)(g_a + base) = pack_h2(a0 / L, a1 / L);
    }
}

// ---------------- launch ----------------
extern "C" void kernel_launch(void* const* d_in, const int* in_sizes, int n_in,
                              void* d_out, int out_size)
{
    (void)in_sizes; (void)n_in; (void)out_size;
    const float* x    = (const float*)d_in[0];
    const int*   mask = (const int*)d_in[1];
    W6 w6;
    w6.w[0] = (const float*)d_in[2];
    w6.w[1] = (const float*)d_in[4];
    w6.w[2] = (const float*)d_in[6];
    w6.w[3] = (const float*)d_in[10];
    w6.w[4] = (const float*)d_in[12];
    w6.w[5] = (const float*)d_in[14];
    Bia5 b5;
    b5.b[0] = (const float*)d_in[3];
    b5.b[1] = (const float*)d_in[5];
    b5.b[2] = (const float*)d_in[7];
    b5.b[3] = (const float*)d_in[11];
    b5.b[4] = (const float*)d_in[13];
    const float* Wqg = (const float*)d_in[8];
    const float* bqg = (const float*)d_in[9];
    const float* bo  = (const float*)d_in[15];
    float* out = (float*)d_out;

    int gsm = (16 * 68 + 64 * 132 + 128 * 68 + 16 * 129 + 2 * 16) * 4;
    cudaFuncSetAttribute(gattn_part, cudaFuncAttributeMaxDynamicSharedMemorySize, gsm);
    cudaFuncSetAttribute(mma_gemm<false>, cudaFuncAttributeMaxDynamicSharedMemorySize, GEMM_SMEM);
    cudaFuncSetAttribute(mma_gemm<true>,  cudaFuncAttributeMaxDynamicSharedMemorySize, GEMM_SMEM);
    cudaFuncSetAttribute(local_attn, cudaFuncAttributeMaxDynamicSharedMemorySize, LA_SMEM);

    __half *xf, *af;
    cudaGetSymbolAddress((void**)&xf, g_x);
    cudaGetSymbolAddress((void**)&af, g_a);

    int n4 = Bb * Ss * Dd / 4;
    to_f16<<<(n4 + 255) / 256, 256>>>(x, xf, n4);                          // 1
    prep_w<<<dim3(24, 24, 6), dim3(32, 8)>>>(w6);                          // 2
    qg_proj<<<dim3(Bb * Gg, 24), 256>>>(x, Wqg, bqg);                      // 3
    mma_gemm<false><<<dim3(3, 64, 5), 512, GEMM_SMEM>>>(xf, b5, nullptr, nullptr); // 4 (profiled)
    local_attn<<<dim3(NBb, Hh, Bb), 256, LA_SMEM>>>(mask);                 // 5
    gattn_part<<<dim3(NSPLIT, Hh, Bb), 256, gsm>>>(mask);                  // 6
    gattn_combine<<<Bb * Hh, 32>>>();                                      // 7
    mma_gemm<true><<<dim3(3, 64), 512, GEMM_SMEM>>>(af, b5, bo, out);      // 8
}

// round 12
// speedup vs baseline: 4.4510x; 1.0130x over previous
#include <cuda_runtime.h>
#include <cuda_fp16.h>
#include <cstdint>

#define Bb 2
#define Ss 4096
#define Dd 768
#define Hh 12
#define DHd 64
#define Ww 128
#define Gg 16
#define NBb 32
#define NSPLIT 32
#define NEGF (-1.0e9f)

// ---------------- scratch (device globals; no allocation) ----------------
__device__ float g_kg[Bb*Hh*Ss*DHd];
__device__ float g_vg[Bb*Hh*Ss*DHd];
__device__ float g_qg[Bb*Hh*Gg*DHd];
__device__ float g_pm  [Bb*Hh*NSPLIT*Gg];
__device__ float g_pl  [Bb*Hh*NSPLIT*Gg];
__device__ float g_pacc[Bb*Hh*NSPLIT*Gg*DHd];

__device__ __half g_x  [Bb*Ss*Dd];
__device__ __half g_a  [Bb*Ss*Dd];
__device__ __half g_wt [6*Dd*Dd];
__device__ __half g_qf [Bb*Hh*Ss*DHd];
__device__ __half g_kf [Bb*Hh*Ss*DHd];
__device__ __half g_vf [Bb*Hh*Ss*DHd];

struct W6   { const float* w[6]; };
struct Bia5 { const float* b[5]; };

// ================= warp-MMA helpers =================
#define SWZ(o) ((o) ^ (((o) >> 3) & 0x70))

__device__ __forceinline__ uint32_t smem_u32(const void* p) {
    uint32_t a;
    asm("{ .reg .u64 t; cvta.to.shared.u64 t, %1; cvt.u32.u64 %0, t; }" : "=r"(a) : "l"(p));
    return a;
}
__device__ __forceinline__ void ldsm4(uint32_t* r, uint32_t addr) {
    asm volatile("ldmatrix.sync.aligned.m8n8.x4.shared.b16 {%0,%1,%2,%3}, [%4];"
                 : "=r"(r[0]), "=r"(r[1]), "=r"(r[2]), "=r"(r[3]) : "r"(addr));
}
__device__ __forceinline__ void ldsm4t(uint32_t* r, uint32_t addr) {
    asm volatile("ldmatrix.sync.aligned.m8n8.x4.trans.shared.b16 {%0,%1,%2,%3}, [%4];"
                 : "=r"(r[0]), "=r"(r[1]), "=r"(r[2]), "=r"(r[3]) : "r"(addr));
}
__device__ __forceinline__ void mma16816(float* d, const uint32_t* a, uint32_t b0, uint32_t b1) {
    asm volatile(
        "mma.sync.aligned.m16n8k16.row.col.f32.f16.f16.f32 "
        "{%0,%1,%2,%3}, {%4,%5,%6,%7}, {%8,%9}, {%0,%1,%2,%3};"
        : "+f"(d[0]), "+f"(d[1]), "+f"(d[2]), "+f"(d[3])
        : "r"(a[0]), "r"(a[1]), "r"(a[2]), "r"(a[3]), "r"(b0), "r"(b1));
}
__device__ __forceinline__ uint32_t pack_h2(float e0, float e1) {
    __half2 h = __floats2half2_rn(e0, e1);
    return *(uint32_t*)&h;
}
__device__ __forceinline__ void cpasync16(uint32_t dst, const void* src) {
    asm volatile("cp.async.cg.shared.global [%0], [%1], 16;" :: "r"(dst), "l"(src) : "memory");
}

// ================= prep kernels =================
__global__ __launch_bounds__(256) void to_f16(const float* __restrict__ in,
                                              __half* __restrict__ out16, int n4)
{
    int i = blockIdx.x * 256 + threadIdx.x;
    if (i >= n4) return;
    float4 v = ((const float4*)in)[i];
    union { __half h[4]; uint2 u; } uh;
    uh.h[0] = __float2half_rn(v.x);
    uh.h[1] = __float2half_rn(v.y);
    uh.h[2] = __float2half_rn(v.z);
    uh.h[3] = __float2half_rn(v.w);
    *(uint2*)(out16 + (size_t)i * 4) = uh.u;
}

__global__ __launch_bounds__(256) void prep_w(W6 ws)
{
    __shared__ float t[32][33];
    int z = blockIdx.z;
    const float* W = ws.w[z];
    __half* oh = g_wt + (size_t)z * Dd * Dd;
    int k0 = blockIdx.x * 32, n0 = blockIdx.y * 32;
    int tx = threadIdx.x, ty = threadIdx.y;
#pragma unroll
    for (int r = 0; r < 4; r++)
        t[ty + r * 8][tx] = W[(size_t)(k0 + ty + r * 8) * Dd + n0 + tx];
    __syncthreads();
#pragma unroll
    for (int r = 0; r < 4; r++)
        oh[(size_t)(n0 + ty + r * 8) * Dd + k0 + tx] = __float2half_rn(t[tx][ty + r * 8]);
}

// ===== fp16 GEMM v4: BM128 x BN256, BK=128, 512 thr, 2-stage cp.async =====
// stage layout: A0 16K | A1 16K | B0 32K | B1 32K = 96KB   (Ax = K-half x)
#define STAGE_SZ 98304
#define GEMM_SMEM (2 * STAGE_SZ)

template<bool OUT>
__global__ __launch_bounds__(512)
void mma_gemm(const __half* __restrict__ Af,
              Bia5 bp, const float* __restrict__ bias_o, float* __restrict__ outp)
{
    extern __shared__ char smem[];
    uint32_t sb = smem_u32(smem);
    int tid = threadIdx.x;
    int wid = tid >> 5, lane = tid & 31;
    int wm = wid >> 2, wn = wid & 3;          // warp tile 32m x 64n
    int z = OUT ? 5 : blockIdx.z;
    int n0 = blockIdx.x * 256, m0 = blockIdx.y * 128;

    const __half* Bw = g_wt + (size_t)z * Dd * Dd + (size_t)n0 * Dd;
    const __half* Ah = Af + (size_t)m0 * Dd;

    float acc[2][8][4];
#pragma unroll
    for (int i = 0; i < 2; i++)
#pragma unroll
        for (int j = 0; j < 8; j++)
#pragma unroll
            for (int q = 0; q < 4; q++) acc[i][j][q] = 0.f;

    int alr = lane & 15, alc = lane >> 4, arx = lane & 7;
    uint32_t aoff[2];
#pragma unroll
    for (int mi = 0; mi < 2; mi++) aoff[mi] = (wm * 32 + mi * 16 + alr) * 128;
    int blr = (lane & 7) + ((lane >> 4) & 1) * 8;
    int blc = (lane >> 3) & 1, brx = lane & 7;
    uint32_t boff[4];
#pragma unroll
    for (int ni = 0; ni < 4; ni++) boff[ni] = (wn * 64 + ni * 16 + blr) * 128;

    // loader: 6144 x 16B units per stage, 12 per thread
    auto load_stage = [&](int c, int s) {
        int k0 = c * 128;
        uint32_t base = sb + s * STAGE_SZ;
#pragma unroll
        for (int it = 0; it < 12; it++) {
            int idx = tid + it * 512;
            int cu = idx & 7;
            if (idx < 1024) {              // A half 0: cols k0..k0+63
                int row = idx >> 3;
                cpasync16(base + SWZ(row * 128 + cu * 16),
                          Ah + k0 + (size_t)row * Dd + cu * 8);
            } else if (idx < 2048) {       // A half 1: cols k0+64..k0+127
                int row = (idx - 1024) >> 3;
                cpasync16(base + 16384 + SWZ(row * 128 + cu * 16),
                          Ah + k0 + 64 + (size_t)row * Dd + cu * 8);
            } else if (idx < 4096) {       // B half 0
                int row = (idx - 2048) >> 3;
                cpasync16(base + 32768 + SWZ(row * 128 + cu * 16),
                          Bw + k0 + (size_t)row * Dd + cu * 8);
            } else {                       // B half 1
                int row = (idx - 4096) >> 3;
                cpasync16(base + 65536 + SWZ(row * 128 + cu * 16),
                          Bw + k0 + 64 + (size_t)row * Dd + cu * 8);
            }
        }
    };

    load_stage(0, 0);
    asm volatile("cp.async.commit_group;" ::: "memory");

    for (int c = 0; c < 6; c++) {
        asm volatile("cp.async.wait_group 0;" ::: "memory");
        __syncthreads();
        if (c < 5) {
            load_stage(c + 1, (c + 1) & 1);
            asm volatile("cp.async.commit_group;" ::: "memory");
        }
        uint32_t sA = sb + (c & 1) * STAGE_SZ;
        uint32_t sBb0 = sA + 32768;
#pragma unroll
        for (int ks = 0; ks < 8; ks++) {
            int ksl = ks & 3, kh = ks >> 2;
            uint32_t aBase = sA + kh * 16384;
            uint32_t bBase = sBb0 + kh * 32768;
            uint32_t ah[2][4], bh[4][4];
            uint32_t ac = ((uint32_t)(ksl * 2 + alc) ^ arx) << 4;
            uint32_t bc = ((uint32_t)(ksl * 2 + blc) ^ brx) << 4;
#pragma unroll
            for (int mi = 0; mi < 2; mi++) ldsm4(ah[mi], aBase + aoff[mi] + ac);
#pragma unroll
            for (int ni = 0; ni < 4; ni++) ldsm4(bh[ni], bBase + boff[ni] + bc);
#pragma unroll
            for (int mi = 0; mi < 2; mi++)
#pragma unroll
                for (int nj = 0; nj < 8; nj++) {
                    int ni = nj >> 1, hf = (nj & 1) * 2;
                    mma16816(acc[mi][nj], ah[mi], bh[ni][hf], bh[ni][hf + 1]);
                }
        }
    }

    int g = lane >> 2, t4 = lane & 3;
#pragma unroll
    for (int mi = 0; mi < 2; mi++) {
        int r0 = m0 + wm * 32 + mi * 16 + g;
#pragma unroll
        for (int nj = 0; nj < 8; nj++) {
            int cc = n0 + wn * 64 + nj * 8 + t4 * 2;
#pragma unroll
            for (int half = 0; half < 2; half++) {
                int m = r0 + half * 8;
                float v0 = acc[mi][nj][half * 2 + 0];
                float v1 = acc[mi][nj][half * 2 + 1];
                if (OUT) {
                    float2 o = make_float2(v0 + bias_o[cc], v1 + bias_o[cc + 1]);
                    *(float2*)(outp + (size_t)m * Dd + cc) = o;
                } else {
                    const float* bias = bp.b[z];
                    float scale = (z == 0) ? 0.125f : 1.0f;
                    v0 = (v0 + bias[cc]) * scale;
                    v1 = (v1 + bias[cc + 1]) * scale;
                    int b = m >> 12, s = m & 4095;
                    int h = cc >> 6, d0 = cc & 63;
                    size_t base = (((size_t)(b * Hh + h)) * Ss + s) * DHd + d0;
                    if (z >= 3) {
                        float* dstz = (z == 3) ? g_kg : g_vg;
                        *(float2*)(dstz + base) = make_float2(v0, v1);
                    } else {
                        __half* dst = (z == 0) ? g_qf : ((z == 1) ? g_kf : g_vf);
                        *(uint32_t*)(dst + base) = pack_h2(v0, v1);
                    }
                }
            }
        }
    }
}

// ================= local attention: fp16 single-product FA2 =================
#define LA_KOK   0
#define LA_Q     1024
#define LA_K     (LA_Q + 16384)
#define LA_V     (LA_K + 16384)
#define LA_SMEM  (LA_V + 16384)

__global__ __launch_bounds__(256) void local_attn(const int* __restrict__ mask)
{
    extern __shared__ char smem[];
    uint32_t sb = smem_u32(smem);
    float* kok = (float*)(smem + LA_KOK);

    int n = blockIdx.x, h = blockIdx.y, b = blockIdx.z;
    int tid = threadIdx.x;
    int wid = tid >> 5, lane = tid & 31;
    int g = lane >> 2, t4 = lane & 3;
    int qr = wid * 16;

    size_t bhbase = ((size_t)(b * Hh + h)) * Ss * DHd;
    const __half* q_g = g_qf + bhbase + (size_t)n * Ww * DHd;
    const __half* k_g = g_kf + bhbase;
    const __half* v_g = g_vf + bhbase;
    const int* mk = mask + b * Ss;

#pragma unroll
    for (int it = 0; it < 4; it++) {
        int idx = tid + it * 256;
        int row = idx >> 3, cu = idx & 7;
        uint32_t sw = row * 128 + ((cu ^ (row & 7)) << 4);
        *(uint4*)(smem + LA_Q + sw) = *(const uint4*)(q_g + (size_t)row * DHd + cu * 8);
    }

    float sacc[16][4];
    float O[8][4];
#pragma unroll
    for (int j = 0; j < 8; j++)
#pragma unroll
        for (int q = 0; q < 4; q++) O[j][q] = 0.f;
    float m0 = -3.0e38f, m1 = -3.0e38f, l0 = 0.f, l1 = 0.f;

    uint32_t aboff = (qr + (lane & 15)) * 128;
    int arx = lane & 7;
    int alc = lane >> 4;
    int krow_in = (lane & 7) + 8 * ((lane >> 4) & 1);
    int kcc = (lane >> 3) & 1;
    int tkrow = (lane & 7) + 8 * ((lane >> 3) & 1);
    int tdu = lane >> 4;

    for (int c = 0; c < 4; c++) {
        int p0 = (n - 1) * Ww + c * Ww;
        __syncthreads();
        if (tid < 128) {
            bool ok;
            if (c == 3) ok = (tid < Gg) && (mk[tid] > 0);
            else { int p = p0 + tid; ok = (p >= Gg) && (p < Ss) && (mk[p] > 0); }
            kok[tid] = ok ? 1.f : 0.f;
        }
#pragma unroll
        for (int it = 0; it < 4; it++) {
            int idx = tid + it * 256;
            int j = idx >> 3, cu = idx & 7;
            int p = (c == 3) ? j : (p0 + j);
            bool inr = (c == 3) ? (j < Gg) : (p >= 0 && p < Ss);
            uint4 kv = make_uint4(0, 0, 0, 0), vv = make_uint4(0, 0, 0, 0);
            if (inr) {
                size_t gb = (size_t)p * DHd + cu * 8;
                kv = *(const uint4*)(k_g + gb);
                vv = *(const uint4*)(v_g + gb);
            }
            uint32_t sw = j * 128 + ((cu ^ (j & 7)) << 4);
            *(uint4*)(smem + LA_K + sw) = kv;
            *(uint4*)(smem + LA_V + sw) = vv;
        }
        __syncthreads();

#pragma unroll
        for (int j = 0; j < 16; j++)
#pragma unroll
            for (int q = 0; q < 4; q++) sacc[j][q] = 0.f;
#pragma unroll
        for (int ks = 0; ks < 4; ks++) {
            uint32_t qh4[4];
            uint32_t ac = ((uint32_t)(ks * 2 + alc) ^ arx) << 4;
            ldsm4(qh4, sb + LA_Q + aboff + ac);
#pragma unroll
            for (int jj = 0; jj < 8; jj++) {
                uint32_t kh4[4];
                uint32_t kb = (16 * jj + krow_in) * 128 + (((uint32_t)(ks * 2 + kcc) ^ arx) << 4);
                ldsm4(kh4, sb + LA_K + kb);
                mma16816(sacc[2 * jj],     qh4, kh4[0], kh4[1]);
                mma16816(sacc[2 * jj + 1], qh4, kh4[2], kh4[3]);
            }
        }

        int row0 = n * Ww + qr + g;
        int row1 = row0 + 8;
#pragma unroll
        for (int j = 0; j < 16; j++) {
#pragma unroll
            for (int q = 0; q < 4; q++) {
                int col = 8 * j + t4 * 2 + (q & 1);
                int row = (q >= 2) ? row1 : row0;
                bool ok = kok[col] > 0.f;
                if (c != 3) {
                    int rel = (p0 + col) - row;
                    ok = ok && (rel <= Ww) && (rel >= -Ww);
                }
                if (!ok) sacc[j][q] = NEGF;
            }
        }

        float mx0 = -3.0e38f, mx1 = -3.0e38f;
#pragma unroll
        for (int j = 0; j < 16; j++) {
            mx0 = fmaxf(mx0, fmaxf(sacc[j][0], sacc[j][1]));
            mx1 = fmaxf(mx1, fmaxf(sacc[j][2], sacc[j][3]));
        }
        mx0 = fmaxf(mx0, __shfl_xor_sync(0xffffffff, mx0, 1));
        mx0 = fmaxf(mx0, __shfl_xor_sync(0xffffffff, mx0, 2));
        mx1 = fmaxf(mx1, __shfl_xor_sync(0xffffffff, mx1, 1));
        mx1 = fmaxf(mx1, __shfl_xor_sync(0xffffffff, mx1, 2));
        float mn0 = fmaxf(m0, mx0), mn1 = fmaxf(m1, mx1);
        float f0 = __expf(m0 - mn0), f1 = __expf(m1 - mn1);
        float s0 = 0.f, s1 = 0.f;
#pragma unroll
        for (int j = 0; j < 16; j++) {
            float p0v = __expf(sacc[j][0] - mn0);
            float p1v = __expf(sacc[j][1] - mn0);
            float p2v = __expf(sacc[j][2] - mn1);
            float p3v = __expf(sacc[j][3] - mn1);
            sacc[j][0] = p0v; sacc[j][1] = p1v; sacc[j][2] = p2v; sacc[j][3] = p3v;
            s0 += p0v + p1v; s1 += p2v + p3v;
        }
        s0 += __shfl_xor_sync(0xffffffff, s0, 1);
        s0 += __shfl_xor_sync(0xffffffff, s0, 2);
        s1 += __shfl_xor_sync(0xffffffff, s1, 1);
        s1 += __shfl_xor_sync(0xffffffff, s1, 2);
        l0 = l0 * f0 + s0; l1 = l1 * f1 + s1;
        m0 = mn0; m1 = mn1;
#pragma unroll
        for (int j = 0; j < 8; j++) {
            O[j][0] *= f0; O[j][1] *= f0; O[j][2] *= f1; O[j][3] *= f1;
        }

#pragma unroll
        for (int ks = 0; ks < 8; ks++) {
            uint32_t pa[4];
            pa[0] = pack_h2(sacc[2 * ks][0],     sacc[2 * ks][1]);
            pa[1] = pack_h2(sacc[2 * ks][2],     sacc[2 * ks][3]);
            pa[2] = pack_h2(sacc[2 * ks + 1][0], sacc[2 * ks + 1][1]);
            pa[3] = pack_h2(sacc[2 * ks + 1][2], sacc[2 * ks + 1][3]);
#pragma unroll
            for (int jd = 0; jd < 4; jd++) {
                uint32_t vh4[4];
                uint32_t vb = (uint32_t)(16 * ks + tkrow) * 128 +
                              (((uint32_t)(jd * 2 + tdu) ^ (uint32_t)(lane & 7)) << 4);
                ldsm4t(vh4, sb + LA_V + vb);
                mma16816(O[2 * jd],     pa, vh4[0], vh4[1]);
                mma16816(O[2 * jd + 1], pa, vh4[2], vh4[3]);
            }
        }
    }

    float inv0 = 1.0f / l0, inv1 = 1.0f / l1;
    int s0r = n * Ww + qr + g;
    int s1r = s0r + 8;
    size_t b0 = ((size_t)b * Ss + s0r) * Dd + h * DHd;
    size_t b1 = ((size_t)b * Ss + s1r) * Dd + h * DHd;
#pragma unroll
    for (int jd = 0; jd < 8; jd++) {
        int cc = 8 * jd + t4 * 2;
        *(uint32_t*)(g_a + b0 + cc) = pack_h2(O[jd][0] * inv0, O[jd][1] * inv0);
        *(uint32_t*)(g_a + b1 + cc) = pack_h2(O[jd][2] * inv1, O[jd][3] * inv1);
    }
}

// ---------------- qg projection ----------------
__global__ __launch_bounds__(256) void qg_proj(const float* __restrict__ x,
                                               const float* __restrict__ Wqg,
                                               const float* __restrict__ bqg)
{
    __shared__ float xr[768];
    __shared__ float sred[256];
    int bg = blockIdx.x, cc = blockIdx.y;
    int b = bg >> 4, g = bg & 15;
    int tid = threadIdx.x;
    for (int i = tid; i < 768; i += 256) xr[i] = x[((size_t)b * Ss + g) * Dd + i];
    __syncthreads();
    int col = cc * 32 + (tid & 31);
    int ks = tid >> 5;
    int k0 = ks * 96;
    float acc = 0.f;
#pragma unroll 8
    for (int k = 0; k < 96; k++)
        acc += xr[k0 + k] * Wqg[(size_t)(k0 + k) * 768 + col];
    sred[tid] = acc;
    __syncthreads();
    if (tid < 32) {
        float tot = 0.f;
#pragma unroll
        for (int j = 0; j < 8; j++) tot += sred[tid + 32 * j];
        int c = cc * 32 + tid;
        float vv = (tot + bqg[c]) * 0.125f;
        g_qg[(((size_t)b * Hh + (c >> 6)) * Gg + g) * DHd + (c & 63)] = vv;
    }
}

// ---------------- global-row attention: 32-way split ----------------
__global__ __launch_bounds__(256) void gattn_part(const int* __restrict__ mask)
{
    extern __shared__ float sm[];
    float* Qgs  = sm;
    float* Kts  = Qgs + 16 * 68;
    float* Vs   = Kts + 64 * 132;
    float* Ps   = Vs + 128 * 68;
    float* rowm = Ps + 16 * 129;
    float* rowl = rowm + 16;

    int si = blockIdx.x, h = blockIdx.y, b = blockIdx.z;
    int tid = threadIdx.x;
    const float* kgb = g_kg + ((size_t)(b * Hh + h)) * Ss * DHd;
    const float* vgb = g_vg + ((size_t)(b * Hh + h)) * Ss * DHd;
    const int* mk = mask + b * Ss;

    for (int i = tid; i < 16 * 64; i += 256) {
        int r = i >> 6, d = i & 63;
        Qgs[r * 68 + d] = g_qg[(((size_t)b * Hh + h) * Gg + r) * DHd + d];
    }

    int p0 = si * 128;
    int r = tid >> 4, cg = tid & 15;
#pragma unroll
    for (int it = 0; it < 8; it++) {
        int idx = tid + it * 256;
        int j = idx >> 4, cv = idx & 15;
        int p = p0 + j;
        float4 kv = *(const float4*)(kgb + (size_t)p * 64 + cv * 4);
        float4 vv = *(const float4*)(vgb + (size_t)p * 64 + cv * 4);
        Kts[(cv * 4 + 0) * 132 + j] = kv.x;
        Kts[(cv * 4 + 1) * 132 + j] = kv.y;
        Kts[(cv * 4 + 2) * 132 + j] = kv.z;
        Kts[(cv * 4 + 3) * 132 + j] = kv.w;
        *(float4*)&Vs[j * 68 + cv * 4] = vv;
    }
    __syncthreads();

    float sc8[8] = {0.f, 0.f, 0.f, 0.f, 0.f, 0.f, 0.f, 0.f};
#pragma unroll 8
    for (int d = 0; d < 64; d++) {
        float a = Qgs[r * 68 + d];
#pragma unroll
        for (int j = 0; j < 8; j++) sc8[j] += a * Kts[d * 132 + cg * 8 + j];
    }
#pragma unroll
    for (int j = 0; j < 8; j++) {
        int p = p0 + cg * 8 + j;
        Ps[r * 129 + cg * 8 + j] = (mk[p] > 0) ? sc8[j] : NEGF;
    }
    __syncthreads();

    if (tid < 16) {
        float cm = -3.0e38f;
        for (int j2 = 0; j2 < 128; j2++) cm = fmaxf(cm, Ps[tid * 129 + j2]);
        float ls = 0.f;
        for (int j2 = 0; j2 < 128; j2++) {
            float pv = __expf(Ps[tid * 129 + j2] - cm);
            Ps[tid * 129 + j2] = pv;
            ls += pv;
        }
        rowm[tid] = cm;
        rowl[tid] = ls;
    }
    __syncthreads();

    float oacc[4] = {0.f, 0.f, 0.f, 0.f};
    for (int kk = 0; kk < 128; kk++) {
        float a = Ps[r * 129 + kk];
#pragma unroll
        for (int j = 0; j < 4; j++) oacc[j] += a * Vs[kk * 68 + cg * 4 + j];
    }
    int part = (b * Hh + h) * NSPLIT + si;
#pragma unroll
    for (int j = 0; j < 4; j++)
        g_pacc[((size_t)part * 16 + r) * 64 + cg * 4 + j] = oacc[j];
    if (cg == 0) {
        g_pm[part * 16 + r] = rowm[r];
        g_pl[part * 16 + r] = rowl[r];
    }
}

__global__ __launch_bounds__(32) void gattn_combine()
{
    int bh = blockIdx.x;
    int b = bh / Hh, h = bh % Hh;
    int t = threadIdx.x;
    for (int r = 0; r < Gg; r++) {
        float M = -3.0e38f;
        for (int si = 0; si < NSPLIT; si++)
            M = fmaxf(M, g_pm[((b * Hh + h) * NSPLIT + si) * 16 + r]);
        float L = 0.f, a0 = 0.f, a1 = 0.f;
        for (int si = 0; si < NSPLIT; si++) {
            int part = (b * Hh + h) * NSPLIT + si;
            float w = __expf(g_pm[part * 16 + r] - M);
            L += w * g_pl[part * 16 + r];
            a0 += w * g_pacc[((size_t)part * 16 + r) * 64 + 2 * t];
            a1 += w * g_pacc[((size_t)part * 16 + r) * 64 + 2 * t + 1];
        }
        size_t base = ((size_t)b * Ss + r) * Dd + h * DHd + 2 * t;
        *(uint32_t*)(g_a + base) = pack_h2(a0 / L, a1 / L);
    }
}

// ---------------- launch ----------------
extern "C" void kernel_launch(void* const* d_in, const int* in_sizes, int n_in,
                              void* d_out, int out_size)
{
    (void)in_sizes; (void)n_in; (void)out_size;
    const float* x    = (const float*)d_in[0];
    const int*   mask = (const int*)d_in[1];
    W6 w6;
    w6.w[0] = (const float*)d_in[2];
    w6.w[1] = (const float*)d_in[4];
    w6.w[2] = (const float*)d_in[6];
    w6.w[3] = (const float*)d_in[10];
    w6.w[4] = (const float*)d_in[12];
    w6.w[5] = (const float*)d_in[14];
    Bia5 b5;
    b5.b[0] = (const float*)d_in[3];
    b5.b[1] = (const float*)d_in[5];
    b5.b[2] = (const float*)d_in[7];
    b5.b[3] = (const float*)d_in[11];
    b5.b[4] = (const float*)d_in[13];
    const float* Wqg = (const float*)d_in[8];
    const float* bqg = (const float*)d_in[9];
    const float* bo  = (const float*)d_in[15];
    float* out = (float*)d_out;

    int gsm = (16 * 68 + 64 * 132 + 128 * 68 + 16 * 129 + 2 * 16) * 4;
    cudaFuncSetAttribute(gattn_part, cudaFuncAttributeMaxDynamicSharedMemorySize, gsm);
    cudaFuncSetAttribute(mma_gemm<false>, cudaFuncAttributeMaxDynamicSharedMemorySize, GEMM_SMEM);
    cudaFuncSetAttribute(mma_gemm<true>,  cudaFuncAttributeMaxDynamicSharedMemorySize, GEMM_SMEM);
    cudaFuncSetAttribute(local_attn, cudaFuncAttributeMaxDynamicSharedMemorySize, LA_SMEM);

    __half *xf, *af;
    cudaGetSymbolAddress((void**)&xf, g_x);
    cudaGetSymbolAddress((void**)&af, g_a);

    int n4 = Bb * Ss * Dd / 4;
    to_f16<<<(n4 + 255) / 256, 256>>>(x, xf, n4);                          // 1
    prep_w<<<dim3(24, 24, 6), dim3(32, 8)>>>(w6);                          // 2
    mma_gemm<false><<<dim3(3, 64, 5), 512, GEMM_SMEM>>>(xf, b5, nullptr, nullptr); // 3
    local_attn<<<dim3(NBb, Hh, Bb), 256, LA_SMEM>>>(mask);                 // 4 (profiled)
    qg_proj<<<dim3(Bb * Gg, 24), 256>>>(x, Wqg, bqg);                      // 5
    gattn_part<<<dim3(NSPLIT, Hh, Bb), 256, gsm>>>(mask);                  // 6
    gattn_combine<<<Bb * Hh, 32>>>();                                      // 7
    mma_gemm<true><<<dim3(3, 64), 512, GEMM_SMEM>>>(af, b5, bo, out);      // 8
}

// round 13
// speedup vs baseline: 4.6746x; 1.0502x over previous
#include <cuda_runtime.h>
#include <cuda_fp16.h>
#include <cstdint>

#define Bb 2
#define Ss 4096
#define Dd 768
#define Hh 12
#define DHd 64
#define Ww 128
#define Gg 16
#define NBb 32
#define NSPLIT 32
#define NEGF (-1.0e9f)

// ---------------- scratch (device globals; no allocation) ----------------
__device__ float g_kg[Bb*Hh*Ss*DHd];
__device__ float g_vg[Bb*Hh*Ss*DHd];
__device__ float g_qg[Bb*Hh*Gg*DHd];
__device__ float g_pm  [Bb*Hh*NSPLIT*Gg];
__device__ float g_pl  [Bb*Hh*NSPLIT*Gg];
__device__ float g_pacc[Bb*Hh*NSPLIT*Gg*DHd];

__device__ __half g_x  [Bb*Ss*Dd];
__device__ __half g_a  [Bb*Ss*Dd];
__device__ __half g_wt [6*Dd*Dd];
__device__ __half g_qf [Bb*Hh*Ss*DHd];
__device__ __half g_kf [Bb*Hh*Ss*DHd];
__device__ __half g_vf [Bb*Hh*Ss*DHd];

struct W6   { const float* w[6]; };
struct Bia5 { const float* b[5]; };

// ================= warp-MMA helpers =================
#define SWZ(o) ((o) ^ (((o) >> 3) & 0x70))

__device__ __forceinline__ uint32_t smem_u32(const void* p) {
    uint32_t a;
    asm("{ .reg .u64 t; cvta.to.shared.u64 t, %1; cvt.u32.u64 %0, t; }" : "=r"(a) : "l"(p));
    return a;
}
__device__ __forceinline__ void ldsm4(uint32_t* r, uint32_t addr) {
    asm volatile("ldmatrix.sync.aligned.m8n8.x4.shared.b16 {%0,%1,%2,%3}, [%4];"
                 : "=r"(r[0]), "=r"(r[1]), "=r"(r[2]), "=r"(r[3]) : "r"(addr));
}
__device__ __forceinline__ void ldsm4t(uint32_t* r, uint32_t addr) {
    asm volatile("ldmatrix.sync.aligned.m8n8.x4.trans.shared.b16 {%0,%1,%2,%3}, [%4];"
                 : "=r"(r[0]), "=r"(r[1]), "=r"(r[2]), "=r"(r[3]) : "r"(addr));
}
__device__ __forceinline__ void mma16816(float* d, const uint32_t* a, uint32_t b0, uint32_t b1) {
    asm volatile(
        "mma.sync.aligned.m16n8k16.row.col.f32.f16.f16.f32 "
        "{%0,%1,%2,%3}, {%4,%5,%6,%7}, {%8,%9}, {%0,%1,%2,%3};"
        : "+f"(d[0]), "+f"(d[1]), "+f"(d[2]), "+f"(d[3])
        : "r"(a[0]), "r"(a[1]), "r"(a[2]), "r"(a[3]), "r"(b0), "r"(b1));
}
__device__ __forceinline__ uint32_t pack_h2(float e0, float e1) {
    __half2 h = __floats2half2_rn(e0, e1);
    return *(uint32_t*)&h;
}
__device__ __forceinline__ void cpasync16(uint32_t dst, const void* src) {
    asm volatile("cp.async.cg.shared.global [%0], [%1], 16;" :: "r"(dst), "l"(src) : "memory");
}

// ================= prep kernels =================
__global__ __launch_bounds__(256) void to_f16(const float* __restrict__ in,
                                              __half* __restrict__ out16, int n4)
{
    int i = blockIdx.x * 256 + threadIdx.x;
    if (i >= n4) return;
    float4 v = ((const float4*)in)[i];
    union { __half h[4]; uint2 u; } uh;
    uh.h[0] = __float2half_rn(v.x);
    uh.h[1] = __float2half_rn(v.y);
    uh.h[2] = __float2half_rn(v.z);
    uh.h[3] = __float2half_rn(v.w);
    *(uint2*)(out16 + (size_t)i * 4) = uh.u;
}

__global__ __launch_bounds__(256) void prep_w(W6 ws)
{
    __shared__ float t[32][33];
    int z = blockIdx.z;
    const float* W = ws.w[z];
    __half* oh = g_wt + (size_t)z * Dd * Dd;
    int k0 = blockIdx.x * 32, n0 = blockIdx.y * 32;
    int tx = threadIdx.x, ty = threadIdx.y;
#pragma unroll
    for (int r = 0; r < 4; r++)
        t[ty + r * 8][tx] = W[(size_t)(k0 + ty + r * 8) * Dd + n0 + tx];
    __syncthreads();
#pragma unroll
    for (int r = 0; r < 4; r++)
        oh[(size_t)(n0 + ty + r * 8) * Dd + k0 + tx] = __float2half_rn(t[tx][ty + r * 8]);
}

// ===== fp16 GEMM: BM128 x BN256, BK=128, 512 thr, 2-stage cp.async =====
#define STAGE_SZ 98304
#define GEMM_SMEM (2 * STAGE_SZ)

template<bool OUT>
__global__ __launch_bounds__(512)
void mma_gemm(const __half* __restrict__ Af,
              Bia5 bp, const float* __restrict__ bias_o, float* __restrict__ outp)
{
    extern __shared__ char smem[];
    uint32_t sb = smem_u32(smem);
    int tid = threadIdx.x;
    int wid = tid >> 5, lane = tid & 31;
    int wm = wid >> 2, wn = wid & 3;
    int z = OUT ? 5 : blockIdx.z;
    int n0 = blockIdx.x * 256, m0 = blockIdx.y * 128;

    const __half* Bw = g_wt + (size_t)z * Dd * Dd + (size_t)n0 * Dd;
    const __half* Ah = Af + (size_t)m0 * Dd;

    float acc[2][8][4];
#pragma unroll
    for (int i = 0; i < 2; i++)
#pragma unroll
        for (int j = 0; j < 8; j++)
#pragma unroll
            for (int q = 0; q < 4; q++) acc[i][j][q] = 0.f;

    int alr = lane & 15, alc = lane >> 4, arx = lane & 7;
    uint32_t aoff[2];
#pragma unroll
    for (int mi = 0; mi < 2; mi++) aoff[mi] = (wm * 32 + mi * 16 + alr) * 128;
    int blr = (lane & 7) + ((lane >> 4) & 1) * 8;
    int blc = (lane >> 3) & 1, brx = lane & 7;
    uint32_t boff[4];
#pragma unroll
    for (int ni = 0; ni < 4; ni++) boff[ni] = (wn * 64 + ni * 16 + blr) * 128;

    auto load_stage = [&](int c, int s) {
        int k0 = c * 128;
        uint32_t base = sb + s * STAGE_SZ;
#pragma unroll
        for (int it = 0; it < 12; it++) {
            int idx = tid + it * 512;
            int cu = idx & 7;
            if (idx < 1024) {
                int row = idx >> 3;
                cpasync16(base + SWZ(row * 128 + cu * 16),
                          Ah + k0 + (size_t)row * Dd + cu * 8);
            } else if (idx < 2048) {
                int row = (idx - 1024) >> 3;
                cpasync16(base + 16384 + SWZ(row * 128 + cu * 16),
                          Ah + k0 + 64 + (size_t)row * Dd + cu * 8);
            } else if (idx < 4096) {
                int row = (idx - 2048) >> 3;
                cpasync16(base + 32768 + SWZ(row * 128 + cu * 16),
                          Bw + k0 + (size_t)row * Dd + cu * 8);
            } else {
                int row = (idx - 4096) >> 3;
                cpasync16(base + 65536 + SWZ(row * 128 + cu * 16),
                          Bw + k0 + 64 + (size_t)row * Dd + cu * 8);
            }
        }
    };

    load_stage(0, 0);
    asm volatile("cp.async.commit_group;" ::: "memory");

    for (int c = 0; c < 6; c++) {
        asm volatile("cp.async.wait_group 0;" ::: "memory");
        __syncthreads();
        if (c < 5) {
            load_stage(c + 1, (c + 1) & 1);
            asm volatile("cp.async.commit_group;" ::: "memory");
        }
        uint32_t sA = sb + (c & 1) * STAGE_SZ;
        uint32_t sBb0 = sA + 32768;
#pragma unroll
        for (int ks = 0; ks < 8; ks++) {
            int ksl = ks & 3, kh = ks >> 2;
            uint32_t aBase = sA + kh * 16384;
            uint32_t bBase = sBb0 + kh * 32768;
            uint32_t ah[2][4], bh[4][4];
            uint32_t ac = ((uint32_t)(ksl * 2 + alc) ^ arx) << 4;
            uint32_t bc = ((uint32_t)(ksl * 2 + blc) ^ brx) << 4;
#pragma unroll
            for (int mi = 0; mi < 2; mi++) ldsm4(ah[mi], aBase + aoff[mi] + ac);
#pragma unroll
            for (int ni = 0; ni < 4; ni++) ldsm4(bh[ni], bBase + boff[ni] + bc);
#pragma unroll
            for (int mi = 0; mi < 2; mi++)
#pragma unroll
                for (int nj = 0; nj < 8; nj++) {
                    int ni = nj >> 1, hf = (nj & 1) * 2;
                    mma16816(acc[mi][nj], ah[mi], bh[ni][hf], bh[ni][hf + 1]);
                }
        }
    }

    int g = lane >> 2, t4 = lane & 3;
#pragma unroll
    for (int mi = 0; mi < 2; mi++) {
        int r0 = m0 + wm * 32 + mi * 16 + g;
#pragma unroll
        for (int nj = 0; nj < 8; nj++) {
            int cc = n0 + wn * 64 + nj * 8 + t4 * 2;
#pragma unroll
            for (int half = 0; half < 2; half++) {
                int m = r0 + half * 8;
                float v0 = acc[mi][nj][half * 2 + 0];
                float v1 = acc[mi][nj][half * 2 + 1];
                if (OUT) {
                    float2 o = make_float2(v0 + bias_o[cc], v1 + bias_o[cc + 1]);
                    *(float2*)(outp + (size_t)m * Dd + cc) = o;
                } else {
                    const float* bias = bp.b[z];
                    float scale = (z == 0) ? 0.125f : 1.0f;
                    v0 = (v0 + bias[cc]) * scale;
                    v1 = (v1 + bias[cc + 1]) * scale;
                    int b = m >> 12, s = m & 4095;
                    int h = cc >> 6, d0 = cc & 63;
                    size_t base = (((size_t)(b * Hh + h)) * Ss + s) * DHd + d0;
                    if (z >= 3) {
                        float* dstz = (z == 3) ? g_kg : g_vg;
                        *(float2*)(dstz + base) = make_float2(v0, v1);
                    } else {
                        __half* dst = (z == 0) ? g_qf : ((z == 1) ? g_kf : g_vf);
                        *(uint32_t*)(dst + base) = pack_h2(v0, v1);
                    }
                }
            }
        }
    }
}

// ===== local attention: 64-query CTAs, 128 thr, 3 CTAs/SM =====
// smem: kok[128]f @0 (pad 1024) | Q 8K | K 16K | V 16K = 41K
#define LA_KOK   0
#define LA_Q     1024
#define LA_K     (LA_Q + 8192)
#define LA_V     (LA_K + 16384)
#define LA_SMEM  (LA_V + 16384)

__global__ __launch_bounds__(128, 3) void local_attn(const int* __restrict__ mask)
{
    extern __shared__ char smem[];
    uint32_t sb = smem_u32(smem);
    float* kok = (float*)(smem + LA_KOK);

    int nh = blockIdx.x, h = blockIdx.y, b = blockIdx.z;
    int n = nh >> 1, half64 = nh & 1;
    int tid = threadIdx.x;
    int wid = tid >> 5, lane = tid & 31;
    int g = lane >> 2, t4 = lane & 3;
    int qr = wid * 16;
    int qbase = n * Ww + half64 * 64;

    size_t bhbase = ((size_t)(b * Hh + h)) * Ss * DHd;
    const __half* q_g = g_qf + bhbase + (size_t)qbase * DHd;
    const __half* k_g = g_kf + bhbase;
    const __half* v_g = g_vf + bhbase;
    const int* mk = mask + b * Ss;

    // load Q (64 rows): 512 uint4
#pragma unroll
    for (int it = 0; it < 4; it++) {
        int idx = tid + it * 128;
        int row = idx >> 3, cu = idx & 7;
        uint32_t sw = row * 128 + ((cu ^ (row & 7)) << 4);
        *(uint4*)(smem + LA_Q + sw) = *(const uint4*)(q_g + (size_t)row * DHd + cu * 8);
    }

    float sacc[16][4];
    float O[8][4];
#pragma unroll
    for (int j = 0; j < 8; j++)
#pragma unroll
        for (int q = 0; q < 4; q++) O[j][q] = 0.f;
    float m0 = -3.0e38f, m1 = -3.0e38f, l0 = 0.f, l1 = 0.f;

    uint32_t aboff = (qr + (lane & 15)) * 128;
    int arx = lane & 7;
    int alc = lane >> 4;
    int krow_in = (lane & 7) + 8 * ((lane >> 4) & 1);
    int kcc = (lane >> 3) & 1;
    int tkrow = (lane & 7) + 8 * ((lane >> 3) & 1);
    int tdu = lane >> 4;

    for (int c = 0; c < 4; c++) {
        int p0 = (n - 1) * Ww + c * Ww;
        __syncthreads();
        {
            bool ok;
            if (c == 3) ok = (tid < Gg) && (mk[tid] > 0);
            else { int p = p0 + tid; ok = (p >= Gg) && (p < Ss) && (mk[p] > 0); }
            kok[tid] = ok ? 1.f : 0.f;
        }
        // load K and V (128 keys): 1024 idx, 8 iters x 128 thr
#pragma unroll
        for (int it = 0; it < 8; it++) {
            int idx = tid + it * 128;
            int j = idx >> 3, cu = idx & 7;
            int p = (c == 3) ? j : (p0 + j);
            bool inr = (c == 3) ? (j < Gg) : (p >= 0 && p < Ss);
            uint4 kv = make_uint4(0, 0, 0, 0), vv = make_uint4(0, 0, 0, 0);
            if (inr) {
                size_t gb = (size_t)p * DHd + cu * 8;
                kv = *(const uint4*)(k_g + gb);
                vv = *(const uint4*)(v_g + gb);
            }
            uint32_t sw = j * 128 + ((cu ^ (j & 7)) << 4);
            *(uint4*)(smem + LA_K + sw) = kv;
            *(uint4*)(smem + LA_V + sw) = vv;
        }
        __syncthreads();

        // ---- S = Q.K^T ----
#pragma unroll
        for (int j = 0; j < 16; j++)
#pragma unroll
            for (int q = 0; q < 4; q++) sacc[j][q] = 0.f;
#pragma unroll
        for (int ks = 0; ks < 4; ks++) {
            uint32_t qh4[4];
            uint32_t ac = ((uint32_t)(ks * 2 + alc) ^ arx) << 4;
            ldsm4(qh4, sb + LA_Q + aboff + ac);
#pragma unroll
            for (int jj = 0; jj < 8; jj++) {
                uint32_t kh4[4];
                uint32_t kb = (16 * jj + krow_in) * 128 + (((uint32_t)(ks * 2 + kcc) ^ arx) << 4);
                ldsm4(kh4, sb + LA_K + kb);
                mma16816(sacc[2 * jj],     qh4, kh4[0], kh4[1]);
                mma16816(sacc[2 * jj + 1], qh4, kh4[2], kh4[3]);
            }
        }

        // ---- mask ----
        int row0 = qbase + qr + g;
        int row1 = row0 + 8;
#pragma unroll
        for (int j = 0; j < 16; j++) {
#pragma unroll
            for (int q = 0; q < 4; q++) {
                int col = 8 * j + t4 * 2 + (q & 1);
                int row = (q >= 2) ? row1 : row0;
                bool ok = kok[col] > 0.f;
                if (c != 3) {
                    int rel = (p0 + col) - row;
                    ok = ok && (rel <= Ww) && (rel >= -Ww);
                }
                if (!ok) sacc[j][q] = NEGF;
            }
        }

        // ---- online softmax ----
        float mx0 = -3.0e38f, mx1 = -3.0e38f;
#pragma unroll
        for (int j = 0; j < 16; j++) {
            mx0 = fmaxf(mx0, fmaxf(sacc[j][0], sacc[j][1]));
            mx1 = fmaxf(mx1, fmaxf(sacc[j][2], sacc[j][3]));
        }
        mx0 = fmaxf(mx0, __shfl_xor_sync(0xffffffff, mx0, 1));
        mx0 = fmaxf(mx0, __shfl_xor_sync(0xffffffff, mx0, 2));
        mx1 = fmaxf(mx1, __shfl_xor_sync(0xffffffff, mx1, 1));
        mx1 = fmaxf(mx1, __shfl_xor_sync(0xffffffff, mx1, 2));
        float mn0 = fmaxf(m0, mx0), mn1 = fmaxf(m1, mx1);
        float f0 = __expf(m0 - mn0), f1 = __expf(m1 - mn1);
        float s0 = 0.f, s1 = 0.f;
#pragma unroll
        for (int j = 0; j < 16; j++) {
            float p0v = __expf(sacc[j][0] - mn0);
            float p1v = __expf(sacc[j][1] - mn0);
            float p2v = __expf(sacc[j][2] - mn1);
            float p3v = __expf(sacc[j][3] - mn1);
            sacc[j][0] = p0v; sacc[j][1] = p1v; sacc[j][2] = p2v; sacc[j][3] = p3v;
            s0 += p0v + p1v; s1 += p2v + p3v;
        }
        s0 += __shfl_xor_sync(0xffffffff, s0, 1);
        s0 += __shfl_xor_sync(0xffffffff, s0, 2);
        s1 += __shfl_xor_sync(0xffffffff, s1, 1);
        s1 += __shfl_xor_sync(0xffffffff, s1, 2);
        l0 = l0 * f0 + s0; l1 = l1 * f1 + s1;
        m0 = mn0; m1 = mn1;
#pragma unroll
        for (int j = 0; j < 8; j++) {
            O[j][0] *= f0; O[j][1] *= f0; O[j][2] *= f1; O[j][3] *= f1;
        }

        // ---- O += P.V ----
#pragma unroll
        for (int ks = 0; ks < 8; ks++) {
            uint32_t pa[4];
            pa[0] = pack_h2(sacc[2 * ks][0],     sacc[2 * ks][1]);
            pa[1] = pack_h2(sacc[2 * ks][2],     sacc[2 * ks][3]);
            pa[2] = pack_h2(sacc[2 * ks + 1][0], sacc[2 * ks + 1][1]);
            pa[3] = pack_h2(sacc[2 * ks + 1][2], sacc[2 * ks + 1][3]);
#pragma unroll
            for (int jd = 0; jd < 4; jd++) {
                uint32_t vh4[4];
                uint32_t vb = (uint32_t)(16 * ks + tkrow) * 128 +
                              (((uint32_t)(jd * 2 + tdu) ^ (uint32_t)(lane & 7)) << 4);
                ldsm4t(vh4, sb + LA_V + vb);
                mma16816(O[2 * jd],     pa, vh4[0], vh4[1]);
                mma16816(O[2 * jd + 1], pa, vh4[2], vh4[3]);
            }
        }
    }

    float inv0 = 1.0f / l0, inv1 = 1.0f / l1;
    int s0r = qbase + qr + g;
    int s1r = s0r + 8;
    size_t b0 = ((size_t)b * Ss + s0r) * Dd + h * DHd;
    size_t b1 = ((size_t)b * Ss + s1r) * Dd + h * DHd;
#pragma unroll
    for (int jd = 0; jd < 8; jd++) {
        int cc = 8 * jd + t4 * 2;
        *(uint32_t*)(g_a + b0 + cc) = pack_h2(O[jd][0] * inv0, O[jd][1] * inv0);
        *(uint32_t*)(g_a + b1 + cc) = pack_h2(O[jd][2] * inv1, O[jd][3] * inv1);
    }
}

// ---------------- qg projection ----------------
__global__ __launch_bounds__(256) void qg_proj(const float* __restrict__ x,
                                               const float* __restrict__ Wqg,
                                               const float* __restrict__ bqg)
{
    __shared__ float xr[768];
    __shared__ float sred[256];
    int bg = blockIdx.x, cc = blockIdx.y;
    int b = bg >> 4, g = bg & 15;
    int tid = threadIdx.x;
    for (int i = tid; i < 768; i += 256) xr[i] = x[((size_t)b * Ss + g) * Dd + i];
    __syncthreads();
    int col = cc * 32 + (tid & 31);
    int ks = tid >> 5;
    int k0 = ks * 96;
    float acc = 0.f;
#pragma unroll 8
    for (int k = 0; k < 96; k++)
        acc += xr[k0 + k] * Wqg[(size_t)(k0 + k) * 768 + col];
    sred[tid] = acc;
    __syncthreads();
    if (tid < 32) {
        float tot = 0.f;
#pragma unroll
        for (int j = 0; j < 8; j++) tot += sred[tid + 32 * j];
        int c = cc * 32 + tid;
        float vv = (tot + bqg[c]) * 0.125f;
        g_qg[(((size_t)b * Hh + (c >> 6)) * Gg + g) * DHd + (c & 63)] = vv;
    }
}

// ---------------- global-row attention: 32-way split ----------------
__global__ __launch_bounds__(256) void gattn_part(const int* __restrict__ mask)
{
    extern __shared__ float sm[];
    float* Qgs  = sm;
    float* Kts  = Qgs + 16 * 68;
    float* Vs   = Kts + 64 * 132;
    float* Ps   = Vs + 128 * 68;
    float* rowm = Ps + 16 * 129;
    float* rowl = rowm + 16;

    int si = blockIdx.x, h = blockIdx.y, b = blockIdx.z;
    int tid = threadIdx.x;
    const float* kgb = g_kg + ((size_t)(b * Hh + h)) * Ss * DHd;
    const float* vgb = g_vg + ((size_t)(b * Hh + h)) * Ss * DHd;
    const int* mk = mask + b * Ss;

    for (int i = tid; i < 16 * 64; i += 256) {
        int r = i >> 6, d = i & 63;
        Qgs[r * 68 + d] = g_qg[(((size_t)b * Hh + h) * Gg + r) * DHd + d];
    }

    int p0 = si * 128;
    int r = tid >> 4, cg = tid & 15;
#pragma unroll
    for (int it = 0; it < 8; it++) {
        int idx = tid + it * 256;
        int j = idx >> 4, cv = idx & 15;
        int p = p0 + j;
        float4 kv = *(const float4*)(kgb + (size_t)p * 64 + cv * 4);
        float4 vv = *(const float4*)(vgb + (size_t)p * 64 + cv * 4);
        Kts[(cv * 4 + 0) * 132 + j] = kv.x;
        Kts[(cv * 4 + 1) * 132 + j] = kv.y;
        Kts[(cv * 4 + 2) * 132 + j] = kv.z;
        Kts[(cv * 4 + 3) * 132 + j] = kv.w;
        *(float4*)&Vs[j * 68 + cv * 4] = vv;
    }
    __syncthreads();

    float sc8[8] = {0.f, 0.f, 0.f, 0.f, 0.f, 0.f, 0.f, 0.f};
#pragma unroll 8
    for (int d = 0; d < 64; d++) {
        float a = Qgs[r * 68 + d];
#pragma unroll
        for (int j = 0; j < 8; j++) sc8[j] += a * Kts[d * 132 + cg * 8 + j];
    }
#pragma unroll
    for (int j = 0; j < 8; j++) {
        int p = p0 + cg * 8 + j;
        Ps[r * 129 + cg * 8 + j] = (mk[p] > 0) ? sc8[j] : NEGF;
    }
    __syncthreads();

    if (tid < 16) {
        float cm = -3.0e38f;
        for (int j2 = 0; j2 < 128; j2++) cm = fmaxf(cm, Ps[tid * 129 + j2]);
        float ls = 0.f;
        for (int j2 = 0; j2 < 128; j2++) {
            float pv = __expf(Ps[tid * 129 + j2] - cm);
            Ps[tid * 129 + j2] = pv;
            ls += pv;
        }
        rowm[tid] = cm;
        rowl[tid] = ls;
    }
    __syncthreads();

    float oacc[4] = {0.f, 0.f, 0.f, 0.f};
    for (int kk = 0; kk < 128; kk++) {
        float a = Ps[r * 129 + kk];
#pragma unroll
        for (int j = 0; j < 4; j++) oacc[j] += a * Vs[kk * 68 + cg * 4 + j];
    }
    int part = (b * Hh + h) * NSPLIT + si;
#pragma unroll
    for (int j = 0; j < 4; j++)
        g_pacc[((size_t)part * 16 + r) * 64 + cg * 4 + j] = oacc[j];
    if (cg == 0) {
        g_pm[part * 16 + r] = rowm[r];
        g_pl[part * 16 + r] = rowl[r];
    }
}

__global__ __launch_bounds__(32) void gattn_combine()
{
    int bh = blockIdx.x;
    int b = bh / Hh, h = bh % Hh;
    int t = threadIdx.x;
    for (int r = 0; r < Gg; r++) {
        float M = -3.0e38f;
        for (int si = 0; si < NSPLIT; si++)
            M = fmaxf(M, g_pm[((b * Hh + h) * NSPLIT + si) * 16 + r]);
        float L = 0.f, a0 = 0.f, a1 = 0.f;
        for (int si = 0; si < NSPLIT; si++) {
            int part = (b * Hh + h) * NSPLIT + si;
            float w = __expf(g_pm[part * 16 + r] - M);
            L += w * g_pl[part * 16 + r];
            a0 += w * g_pacc[((size_t)part * 16 + r) * 64 + 2 * t];
            a1 += w * g_pacc[((size_t)part * 16 + r) * 64 + 2 * t + 1];
        }
        size_t base = ((size_t)b * Ss + r) * Dd + h * DHd + 2 * t;
        *(uint32_t*)(g_a + base) = pack_h2(a0 / L, a1 / L);
    }
}

// ---------------- launch ----------------
extern "C" void kernel_launch(void* const* d_in, const int* in_sizes, int n_in,
                              void* d_out, int out_size)
{
    (void)in_sizes; (void)n_in; (void)out_size;
    const float* x    = (const float*)d_in[0];
    const int*   mask = (const int*)d_in[1];
    W6 w6;
    w6.w[0] = (const float*)d_in[2];
    w6.w[1] = (const float*)d_in[4];
    w6.w[2] = (const float*)d_in[6];
    w6.w[3] = (const float*)d_in[10];
    w6.w[4] = (const float*)d_in[12];
    w6.w[5] = (const float*)d_in[14];
    Bia5 b5;
    b5.b[0] = (const float*)d_in[3];
    b5.b[1] = (const float*)d_in[5];
    b5.b[2] = (const float*)d_in[7];
    b5.b[3] = (const float*)d_in[11];
    b5.b[4] = (const float*)d_in[13];
    const float* Wqg = (const float*)d_in[8];
    const float* bqg = (const float*)d_in[9];
    const float* bo  = (const float*)d_in[15];
    float* out = (float*)d_out;

    int gsm = (16 * 68 + 64 * 132 + 128 * 68 + 16 * 129 + 2 * 16) * 4;
    cudaFuncSetAttribute(gattn_part, cudaFuncAttributeMaxDynamicSharedMemorySize, gsm);
    cudaFuncSetAttribute(mma_gemm<false>, cudaFuncAttributeMaxDynamicSharedMemorySize, GEMM_SMEM);
    cudaFuncSetAttribute(mma_gemm<true>,  cudaFuncAttributeMaxDynamicSharedMemorySize, GEMM_SMEM);
    cudaFuncSetAttribute(local_attn, cudaFuncAttributeMaxDynamicSharedMemorySize, LA_SMEM);

    __half *xf, *af;
    cudaGetSymbolAddress((void**)&xf, g_x);
    cudaGetSymbolAddress((void**)&af, g_a);

    int n4 = Bb * Ss * Dd / 4;
    to_f16<<<(n4 + 255) / 256, 256>>>(x, xf, n4);                          // 1
    prep_w<<<dim3(24, 24, 6), dim3(32, 8)>>>(w6);                          // 2
    qg_proj<<<dim3(Bb * Gg, 24), 256>>>(x, Wqg, bqg);                      // 3
    mma_gemm<false><<<dim3(3, 64, 5), 512, GEMM_SMEM>>>(xf, b5, nullptr, nullptr); // 4 (profiled)
    local_attn<<<dim3(NBb * 2, Hh, Bb), 128, LA_SMEM>>>(mask);             // 5
    gattn_part<<<dim3(NSPLIT, Hh, Bb), 256, gsm>>>(mask);                  // 6
    gattn_combine<<<Bb * Hh, 32>>>();                                      // 7
    mma_gemm<true><<<dim3(3, 64), 512, GEMM_SMEM>>>(af, b5, bo, out);      // 8
}

// round 15
// speedup vs baseline: 4.9786x; 1.0650x over previous
#include <cuda_runtime.h>
#include <cuda_fp16.h>
#include <cstdint>

#define Bb 2
#define Ss 4096
#define Dd 768
#define Hh 12
#define DHd 64
#define Ww 128
#define Gg 16
#define NBb 32
#define NSPLIT 32
#define NEGF (-1.0e9f)

// ---------------- scratch (device globals; no allocation) ----------------
__device__ float g_kg[Bb*Hh*Ss*DHd];
__device__ float g_vg[Bb*Hh*Ss*DHd];
__device__ float g_qg[Bb*Hh*Gg*DHd];
__device__ float g_pm  [Bb*Hh*NSPLIT*Gg];
__device__ float g_pl  [Bb*Hh*NSPLIT*Gg];
__device__ float g_pacc[Bb*Hh*NSPLIT*Gg*DHd];

__device__ __half g_x  [Bb*Ss*Dd];
__device__ __half g_a  [Bb*Ss*Dd];
__device__ __half g_wt [6*Dd*Dd];
__device__ __half g_qf [Bb*Hh*Ss*DHd];
__device__ __half g_kf [Bb*Hh*Ss*DHd];
__device__ __half g_vf [Bb*Hh*Ss*DHd];

struct W6   { const float* w[6]; };
struct Bia5 { const float* b[5]; };

// ================= warp-MMA helpers =================
#define SWZ(o) ((o) ^ (((o) >> 3) & 0x70))

__device__ __forceinline__ uint32_t smem_u32(const void* p) {
    uint32_t a;
    asm("{ .reg .u64 t; cvta.to.shared.u64 t, %1; cvt.u32.u64 %0, t; }" : "=r"(a) : "l"(p));
    return a;
}
__device__ __forceinline__ void ldsm4(uint32_t* r, uint32_t addr) {
    asm volatile("ldmatrix.sync.aligned.m8n8.x4.shared.b16 {%0,%1,%2,%3}, [%4];"
                 : "=r"(r[0]), "=r"(r[1]), "=r"(r[2]), "=r"(r[3]) : "r"(addr));
}
__device__ __forceinline__ void ldsm4t(uint32_t* r, uint32_t addr) {
    asm volatile("ldmatrix.sync.aligned.m8n8.x4.trans.shared.b16 {%0,%1,%2,%3}, [%4];"
                 : "=r"(r[0]), "=r"(r[1]), "=r"(r[2]), "=r"(r[3]) : "r"(addr));
}
__device__ __forceinline__ void mma16816(float* d, const uint32_t* a, uint32_t b0, uint32_t b1) {
    asm volatile(
        "mma.sync.aligned.m16n8k16.row.col.f32.f16.f16.f32 "
        "{%0,%1,%2,%3}, {%4,%5,%6,%7}, {%8,%9}, {%0,%1,%2,%3};"
        : "+f"(d[0]), "+f"(d[1]), "+f"(d[2]), "+f"(d[3])
        : "r"(a[0]), "r"(a[1]), "r"(a[2]), "r"(a[3]), "r"(b0), "r"(b1));
}
__device__ __forceinline__ uint32_t pack_h2(float e0, float e1) {
    __half2 h = __floats2half2_rn(e0, e1);
    return *(uint32_t*)&h;
}
__device__ __forceinline__ void cpasync16(uint32_t dst, const void* src) {
    asm volatile("cp.async.cg.shared.global [%0], [%1], 16;" :: "r"(dst), "l"(src) : "memory");
}

// ================= prep kernels =================
__global__ __launch_bounds__(256) void to_f16(const float* __restrict__ in,
                                              __half* __restrict__ out16, int n4)
{
    int i = blockIdx.x * 256 + threadIdx.x;
    if (i >= n4) return;
    float4 v = ((const float4*)in)[i];
    union { __half h[4]; uint2 u; } uh;
    uh.h[0] = __float2half_rn(v.x);
    uh.h[1] = __float2half_rn(v.y);
    uh.h[2] = __float2half_rn(v.z);
    uh.h[3] = __float2half_rn(v.w);
    *(uint2*)(out16 + (size_t)i * 4) = uh.u;
}

__global__ __launch_bounds__(256) void prep_w(W6 ws)
{
    __shared__ float t[32][33];
    int z = blockIdx.z;
    const float* W = ws.w[z];
    __half* oh = g_wt + (size_t)z * Dd * Dd;
    int k0 = blockIdx.x * 32, n0 = blockIdx.y * 32;
    int tx = threadIdx.x, ty = threadIdx.y;
#pragma unroll
    for (int r = 0; r < 4; r++)
        t[ty + r * 8][tx] = W[(size_t)(k0 + ty + r * 8) * Dd + n0 + tx];
    __syncthreads();
#pragma unroll
    for (int r = 0; r < 4; r++)
        oh[(size_t)(n0 + ty + r * 8) * Dd + k0 + tx] = __float2half_rn(t[tx][ty + r * 8]);
}

// ===== fp16 GEMM v5: BM64 x BN256, BK=64, 256 thr, 2 CTAs/SM, 2-stage =====
// stage: A 8K | B 32K = 40K
#define STAGE_SZ 40960
#define GEMM_SMEM (2 * STAGE_SZ)

template<bool OUT>
__global__ __launch_bounds__(256, 2)
void mma_gemm(const __half* __restrict__ Af,
              Bia5 bp, const float* __restrict__ bias_o, float* __restrict__ outp)
{
    extern __shared__ char smem[];
    uint32_t sb = smem_u32(smem);
    int tid = threadIdx.x;
    int wid = tid >> 5, lane = tid & 31;
    int wm = wid >> 2, wn = wid & 3;          // 2m x 4n warps; warp tile 32m x 64n
    int z = OUT ? 5 : blockIdx.z;
    int n0 = blockIdx.x * 256, m0 = blockIdx.y * 64;

    const __half* Bw = g_wt + (size_t)z * Dd * Dd + (size_t)n0 * Dd;
    const __half* Ah = Af + (size_t)m0 * Dd;

    float acc[2][8][4];
#pragma unroll
    for (int i = 0; i < 2; i++)
#pragma unroll
        for (int j = 0; j < 8; j++)
#pragma unroll
            for (int q = 0; q < 4; q++) acc[i][j][q] = 0.f;

    int alr = lane & 15, alc = lane >> 4, arx = lane & 7;
    uint32_t aoff[2];
#pragma unroll
    for (int mi = 0; mi < 2; mi++) aoff[mi] = (wm * 32 + mi * 16 + alr) * 128;
    int blr = (lane & 7) + ((lane >> 4) & 1) * 8;
    int blc = (lane >> 3) & 1, brx = lane & 7;
    uint32_t boff[4];
#pragma unroll
    for (int ni = 0; ni < 4; ni++) boff[ni] = (wn * 64 + ni * 16 + blr) * 128;

    // loader: 2560 x 16B units per stage (A 512, B 2048), 256 thr -> 10 each
    auto load_stage = [&](int c, int s) {
        int k0 = c * 64;
        uint32_t base = sb + s * STAGE_SZ;
#pragma unroll
        for (int it = 0; it < 10; it++) {
            int idx = tid + it * 256;
            int cu = idx & 7;
            if (idx < 512) {               // A: 64 rows
                int row = idx >> 3;
                cpasync16(base + SWZ(row * 128 + cu * 16),
                          Ah + k0 + (size_t)row * Dd + cu * 8);
            } else {                       // B: 256 rows
                int row = (idx - 512) >> 3;
                cpasync16(base + 8192 + SWZ(row * 128 + cu * 16),
                          Bw + k0 + (size_t)row * Dd + cu * 8);
            }
        }
    };

    load_stage(0, 0);
    asm volatile("cp.async.commit_group;" ::: "memory");

    for (int c = 0; c < 12; c++) {
        asm volatile("cp.async.wait_group 0;" ::: "memory");
        __syncthreads();
        if (c < 11) {
            load_stage(c + 1, (c + 1) & 1);
            asm volatile("cp.async.commit_group;" ::: "memory");
        }
        uint32_t sA = sb + (c & 1) * STAGE_SZ;
        uint32_t sB = sA + 8192;
#pragma unroll
        for (int ks = 0; ks < 4; ks++) {
            uint32_t ah[2][4], bh[4][4];
            uint32_t ac = ((uint32_t)(ks * 2 + alc) ^ arx) << 4;
            uint32_t bc = ((uint32_t)(ks * 2 + blc) ^ brx) << 4;
#pragma unroll
            for (int mi = 0; mi < 2; mi++) ldsm4(ah[mi], sA + aoff[mi] + ac);
#pragma unroll
            for (int ni = 0; ni < 4; ni++) ldsm4(bh[ni], sB + boff[ni] + bc);
#pragma unroll
            for (int mi = 0; mi < 2; mi++)
#pragma unroll
                for (int nj = 0; nj < 8; nj++) {
                    int ni = nj >> 1, hf = (nj & 1) * 2;
                    mma16816(acc[mi][nj], ah[mi], bh[ni][hf], bh[ni][hf + 1]);
                }
        }
    }

    int g = lane >> 2, t4 = lane & 3;
#pragma unroll
    for (int mi = 0; mi < 2; mi++) {
        int r0 = m0 + wm * 32 + mi * 16 + g;
#pragma unroll
        for (int nj = 0; nj < 8; nj++) {
            int cc = n0 + wn * 64 + nj * 8 + t4 * 2;
#pragma unroll
            for (int half = 0; half < 2; half++) {
                int m = r0 + half * 8;
                float v0 = acc[mi][nj][half * 2 + 0];
                float v1 = acc[mi][nj][half * 2 + 1];
                if (OUT) {
                    float2 o = make_float2(v0 + bias_o[cc], v1 + bias_o[cc + 1]);
                    *(float2*)(outp + (size_t)m * Dd + cc) = o;
                } else {
                    const float* bias = bp.b[z];
                    float scale = (z == 0) ? 0.125f : 1.0f;
                    v0 = (v0 + bias[cc]) * scale;
                    v1 = (v1 + bias[cc + 1]) * scale;
                    int b = m >> 12, s = m & 4095;
                    int h = cc >> 6, d0 = cc & 63;
                    size_t base = (((size_t)(b * Hh + h)) * Ss + s) * DHd + d0;
                    if (z >= 3) {
                        float* dstz = (z == 3) ? g_kg : g_vg;
                        *(float2*)(dstz + base) = make_float2(v0, v1);
                    } else {
                        __half* dst = (z == 0) ? g_qf : ((z == 1) ? g_kf : g_vf);
                        *(uint32_t*)(dst + base) = pack_h2(v0, v1);
                    }
                }
            }
        }
    }
}

// ===== local attention: 64-query CTAs, 128 thr, 3 CTAs/SM =====
#define LA_KOK   0
#define LA_Q     1024
#define LA_K     (LA_Q + 8192)
#define LA_V     (LA_K + 16384)
#define LA_SMEM  (LA_V + 16384)

__global__ __launch_bounds__(128, 3) void local_attn(const int* __restrict__ mask)
{
    extern __shared__ char smem[];
    uint32_t sb = smem_u32(smem);
    float* kok = (float*)(smem + LA_KOK);

    int nh = blockIdx.x, h = blockIdx.y, b = blockIdx.z;
    int n = nh >> 1, half64 = nh & 1;
    int tid = threadIdx.x;
    int wid = tid >> 5, lane = tid & 31;
    int g = lane >> 2, t4 = lane & 3;
    int qr = wid * 16;
    int qbase = n * Ww + half64 * 64;

    size_t bhbase = ((size_t)(b * Hh + h)) * Ss * DHd;
    const __half* q_g = g_qf + bhbase + (size_t)qbase * DHd;
    const __half* k_g = g_kf + bhbase;
    const __half* v_g = g_vf + bhbase;
    const int* mk = mask + b * Ss;

#pragma unroll
    for (int it = 0; it < 4; it++) {
        int idx = tid + it * 128;
        int row = idx >> 3, cu = idx & 7;
        uint32_t sw = row * 128 + ((cu ^ (row & 7)) << 4);
        *(uint4*)(smem + LA_Q + sw) = *(const uint4*)(q_g + (size_t)row * DHd + cu * 8);
    }

    float sacc[16][4];
    float O[8][4];
#pragma unroll
    for (int j = 0; j < 8; j++)
#pragma unroll
        for (int q = 0; q < 4; q++) O[j][q] = 0.f;
    float m0 = -3.0e38f, m1 = -3.0e38f, l0 = 0.f, l1 = 0.f;

    uint32_t aboff = (qr + (lane & 15)) * 128;
    int arx = lane & 7;
    int alc = lane >> 4;
    int krow_in = (lane & 7) + 8 * ((lane >> 4) & 1);
    int kcc = (lane >> 3) & 1;
    int tkrow = (lane & 7) + 8 * ((lane >> 3) & 1);
    int tdu = lane >> 4;

    for (int c = 0; c < 4; c++) {
        int p0 = (n - 1) * Ww + c * Ww;
        __syncthreads();
        {
            bool ok;
            if (c == 3) ok = (tid < Gg) && (mk[tid] > 0);
            else { int p = p0 + tid; ok = (p >= Gg) && (p < Ss) && (mk[p] > 0); }
            kok[tid] = ok ? 1.f : 0.f;
        }
#pragma unroll
        for (int it = 0; it < 8; it++) {
            int idx = tid + it * 128;
            int j = idx >> 3, cu = idx & 7;
            int p = (c == 3) ? j : (p0 + j);
            bool inr = (c == 3) ? (j < Gg) : (p >= 0 && p < Ss);
            uint4 kv = make_uint4(0, 0, 0, 0), vv = make_uint4(0, 0, 0, 0);
            if (inr) {
                size_t gb = (size_t)p * DHd + cu * 8;
                kv = *(const uint4*)(k_g + gb);
                vv = *(const uint4*)(v_g + gb);
            }
            uint32_t sw = j * 128 + ((cu ^ (j & 7)) << 4);
            *(uint4*)(smem + LA_K + sw) = kv;
            *(uint4*)(smem + LA_V + sw) = vv;
        }
        __syncthreads();

#pragma unroll
        for (int j = 0; j < 16; j++)
#pragma unroll
            for (int q = 0; q < 4; q++) sacc[j][q] = 0.f;
#pragma unroll
        for (int ks = 0; ks < 4; ks++) {
            uint32_t qh4[4];
            uint32_t ac = ((uint32_t)(ks * 2 + alc) ^ arx) << 4;
            ldsm4(qh4, sb + LA_Q + aboff + ac);
#pragma unroll
            for (int jj = 0; jj < 8; jj++) {
                uint32_t kh4[4];
                uint32_t kb = (16 * jj + krow_in) * 128 + (((uint32_t)(ks * 2 + kcc) ^ arx) << 4);
                ldsm4(kh4, sb + LA_K + kb);
                mma16816(sacc[2 * jj],     qh4, kh4[0], kh4[1]);
                mma16816(sacc[2 * jj + 1], qh4, kh4[2], kh4[3]);
            }
        }

        int row0 = qbase + qr + g;
        int row1 = row0 + 8;
#pragma unroll
        for (int j = 0; j < 16; j++) {
#pragma unroll
            for (int q = 0; q < 4; q++) {
                int col = 8 * j + t4 * 2 + (q & 1);
                int row = (q >= 2) ? row1 : row0;
                bool ok = kok[col] > 0.f;
                if (c != 3) {
                    int rel = (p0 + col) - row;
                    ok = ok && (rel <= Ww) && (rel >= -Ww);
                }
                if (!ok) sacc[j][q] = NEGF;
            }
        }

        float mx0 = -3.0e38f, mx1 = -3.0e38f;
#pragma unroll
        for (int j = 0; j < 16; j++) {
            mx0 = fmaxf(mx0, fmaxf(sacc[j][0], sacc[j][1]));
            mx1 = fmaxf(mx1, fmaxf(sacc[j][2], sacc[j][3]));
        }
        mx0 = fmaxf(mx0, __shfl_xor_sync(0xffffffff, mx0, 1));
        mx0 = fmaxf(mx0, __shfl_xor_sync(0xffffffff, mx0, 2));
        mx1 = fmaxf(mx1, __shfl_xor_sync(0xffffffff, mx1, 1));
        mx1 = fmaxf(mx1, __shfl_xor_sync(0xffffffff, mx1, 2));
        float mn0 = fmaxf(m0, mx0), mn1 = fmaxf(m1, mx1);
        float f0 = __expf(m0 - mn0), f1 = __expf(m1 - mn1);
        float s0 = 0.f, s1 = 0.f;
#pragma unroll
        for (int j = 0; j < 16; j++) {
            float p0v = __expf(sacc[j][0] - mn0);
            float p1v = __expf(sacc[j][1] - mn0);
            float p2v = __expf(sacc[j][2] - mn1);
            float p3v = __expf(sacc[j][3] - mn1);
            sacc[j][0] = p0v; sacc[j][1] = p1v; sacc[j][2] = p2v; sacc[j][3] = p3v;
            s0 += p0v + p1v; s1 += p2v + p3v;
        }
        s0 += __shfl_xor_sync(0xffffffff, s0, 1);
        s0 += __shfl_xor_sync(0xffffffff, s0, 2);
        s1 += __shfl_xor_sync(0xffffffff, s1, 1);
        s1 += __shfl_xor_sync(0xffffffff, s1, 2);
        l0 = l0 * f0 + s0; l1 = l1 * f1 + s1;
        m0 = mn0; m1 = mn1;
#pragma unroll
        for (int j = 0; j < 8; j++) {
            O[j][0] *= f0; O[j][1] *= f0; O[j][2] *= f1; O[j][3] *= f1;
        }

#pragma unroll
        for (int ks = 0; ks < 8; ks++) {
            uint32_t pa[4];
            pa[0] = pack_h2(sacc[2 * ks][0],     sacc[2 * ks][1]);
            pa[1] = pack_h2(sacc[2 * ks][2],     sacc[2 * ks][3]);
            pa[2] = pack_h2(sacc[2 * ks + 1][0], sacc[2 * ks + 1][1]);
            pa[3] = pack_h2(sacc[2 * ks + 1][2], sacc[2 * ks + 1][3]);
#pragma unroll
            for (int jd = 0; jd < 4; jd++) {
                uint32_t vh4[4];
                uint32_t vb = (uint32_t)(16 * ks + tkrow) * 128 +
                              (((uint32_t)(jd * 2 + tdu) ^ (uint32_t)(lane & 7)) << 4);
                ldsm4t(vh4, sb + LA_V + vb);
                mma16816(O[2 * jd],     pa, vh4[0], vh4[1]);
                mma16816(O[2 * jd + 1], pa, vh4[2], vh4[3]);
            }
        }
    }

    float inv0 = 1.0f / l0, inv1 = 1.0f / l1;
    int s0r = qbase + qr + g;
    int s1r = s0r + 8;
    size_t b0 = ((size_t)b * Ss + s0r) * Dd + h * DHd;
    size_t b1 = ((size_t)b * Ss + s1r) * Dd + h * DHd;
#pragma unroll
    for (int jd = 0; jd < 8; jd++) {
        int cc = 8 * jd + t4 * 2;
        *(uint32_t*)(g_a + b0 + cc) = pack_h2(O[jd][0] * inv0, O[jd][1] * inv0);
        *(uint32_t*)(g_a + b1 + cc) = pack_h2(O[jd][2] * inv1, O[jd][3] * inv1);
    }
}

// ---------------- qg projection ----------------
__global__ __launch_bounds__(256) void qg_proj(const float* __restrict__ x,
                                               const float* __restrict__ Wqg,
                                               const float* __restrict__ bqg)
{
    __shared__ float xr[768];
    __shared__ float sred[256];
    int bg = blockIdx.x, cc = blockIdx.y;
    int b = bg >> 4, g = bg & 15;
    int tid = threadIdx.x;
    for (int i = tid; i < 768; i += 256) xr[i] = x[((size_t)b * Ss + g) * Dd + i];
    __syncthreads();
    int col = cc * 32 + (tid & 31);
    int ks = tid >> 5;
    int k0 = ks * 96;
    float acc = 0.f;
#pragma unroll 8
    for (int k = 0; k < 96; k++)
        acc += xr[k0 + k] * Wqg[(size_t)(k0 + k) * 768 + col];
    sred[tid] = acc;
    __syncthreads();
    if (tid < 32) {
        float tot = 0.f;
#pragma unroll
        for (int j = 0; j < 8; j++) tot += sred[tid + 32 * j];
        int c = cc * 32 + tid;
        float vv = (tot + bqg[c]) * 0.125f;
        g_qg[(((size_t)b * Hh + (c >> 6)) * Gg + g) * DHd + (c & 63)] = vv;
    }
}

// ---------------- global-row attention: 32-way split ----------------
__global__ __launch_bounds__(256) void gattn_part(const int* __restrict__ mask)
{
    extern __shared__ float sm[];
    float* Qgs  = sm;
    float* Kts  = Qgs + 16 * 68;
    float* Vs   = Kts + 64 * 132;
    float* Ps   = Vs + 128 * 68;
    float* rowm = Ps + 16 * 129;
    float* rowl = rowm + 16;

    int si = blockIdx.x, h = blockIdx.y, b = blockIdx.z;
    int tid = threadIdx.x;
    const float* kgb = g_kg + ((size_t)(b * Hh + h)) * Ss * DHd;
    const float* vgb = g_vg + ((size_t)(b * Hh + h)) * Ss * DHd;
    const int* mk = mask + b * Ss;

    for (int i = tid; i < 16 * 64; i += 256) {
        int r = i >> 6, d = i & 63;
        Qgs[r * 68 + d] = g_qg[(((size_t)b * Hh + h) * Gg + r) * DHd + d];
    }

    int p0 = si * 128;
    int r = tid >> 4, cg = tid & 15;
#pragma unroll
    for (int it = 0; it < 8; it++) {
        int idx = tid + it * 256;
        int j = idx >> 4, cv = idx & 15;
        int p = p0 + j;
        float4 kv = *(const float4*)(kgb + (size_t)p * 64 + cv * 4);
        float4 vv = *(const float4*)(vgb + (size_t)p * 64 + cv * 4);
        Kts[(cv * 4 + 0) * 132 + j] = kv.x;
        Kts[(cv * 4 + 1) * 132 + j] = kv.y;
        Kts[(cv * 4 + 2) * 132 + j] = kv.z;
        Kts[(cv * 4 + 3) * 132 + j] = kv.w;
        *(float4*)&Vs[j * 68 + cv * 4] = vv;
    }
    __syncthreads();

    float sc8[8] = {0.f, 0.f, 0.f, 0.f, 0.f, 0.f, 0.f, 0.f};
#pragma unroll 8
    for (int d = 0; d < 64; d++) {
        float a = Qgs[r * 68 + d];
#pragma unroll
        for (int j = 0; j < 8; j++) sc8[j] += a * Kts[d * 132 + cg * 8 + j];
    }
#pragma unroll
    for (int j = 0; j < 8; j++) {
        int p = p0 + cg * 8 + j;
        Ps[r * 129 + cg * 8 + j] = (mk[p] > 0) ? sc8[j] : NEGF;
    }
    __syncthreads();

    if (tid < 16) {
        float cm = -3.0e38f;
        for (int j2 = 0; j2 < 128; j2++) cm = fmaxf(cm, Ps[tid * 129 + j2]);
        float ls = 0.f;
        for (int j2 = 0; j2 < 128; j2++) {
            float pv = __expf(Ps[tid * 129 + j2] - cm);
            Ps[tid * 129 + j2] = pv;
            ls += pv;
        }
        rowm[tid] = cm;
        rowl[tid] = ls;
    }
    __syncthreads();

    float oacc[4] = {0.f, 0.f, 0.f, 0.f};
    for (int kk = 0; kk < 128; kk++) {
        float a = Ps[r * 129 + kk];
#pragma unroll
        for (int j = 0; j < 4; j++) oacc[j] += a * Vs[kk * 68 + cg * 4 + j];
    }
    int part = (b * Hh + h) * NSPLIT + si;
#pragma unroll
    for (int j = 0; j < 4; j++)
        g_pacc[((size_t)part * 16 + r) * 64 + cg * 4 + j] = oacc[j];
    if (cg == 0) {
        g_pm[part * 16 + r] = rowm[r];
        g_pl[part * 16 + r] = rowl[r];
    }
}

__global__ __launch_bounds__(32) void gattn_combine()
{
    int bh = blockIdx.x;
    int b = bh / Hh, h = bh % Hh;
    int t = threadIdx.x;
    for (int r = 0; r < Gg; r++) {
        float M = -3.0e38f;
        for (int si = 0; si < NSPLIT; si++)
            M = fmaxf(M, g_pm[((b * Hh + h) * NSPLIT + si) * 16 + r]);
        float L = 0.f, a0 = 0.f, a1 = 0.f;
        for (int si = 0; si < NSPLIT; si++) {
            int part = (b * Hh + h) * NSPLIT + si;
            float w = __expf(g_pm[part * 16 + r] - M);
            L += w * g_pl[part * 16 + r];
            a0 += w * g_pacc[((size_t)part * 16 + r) * 64 + 2 * t];
            a1 += w * g_pacc[((size_t)part * 16 + r) * 64 + 2 * t + 1];
        }
        size_t base = ((size_t)b * Ss + r) * Dd + h * DHd + 2 * t;
        *(uint32_t*)(g_a + base) = pack_h2(a0 / L, a1 / L);
    }
}

// ---------------- launch ----------------
extern "C" void kernel_launch(void* const* d_in, const int* in_sizes, int n_in,
                              void* d_out, int out_size)
{
    (void)in_sizes; (void)n_in; (void)out_size;
    const float* x    = (const float*)d_in[0];
    const int*   mask = (const int*)d_in[1];
    W6 w6;
    w6.w[0] = (const float*)d_in[2];
    w6.w[1] = (const float*)d_in[4];
    w6.w[2] = (const float*)d_in[6];
    w6.w[3] = (const float*)d_in[10];
    w6.w[4] = (const float*)d_in[12];
    w6.w[5] = (const float*)d_in[14];
    Bia5 b5;
    b5.b[0] = (const float*)d_in[3];
    b5.b[1] = (const float*)d_in[5];
    b5.b[2] = (const float*)d_in[7];
    b5.b[3] = (const float*)d_in[11];
    b5.b[4] = (const float*)d_in[13];
    const float* Wqg = (const float*)d_in[8];
    const float* bqg = (const float*)d_in[9];
    const float* bo  = (const float*)d_in[15];
    float* out = (float*)d_out;

    int gsm = (16 * 68 + 64 * 132 + 128 * 68 + 16 * 129 + 2 * 16) * 4;
    cudaFuncSetAttribute(gattn_part, cudaFuncAttributeMaxDynamicSharedMemorySize, gsm);
    cudaFuncSetAttribute(mma_gemm<false>, cudaFuncAttributeMaxDynamicSharedMemorySize, GEMM_SMEM);
    cudaFuncSetAttribute(mma_gemm<true>,  cudaFuncAttributeMaxDynamicSharedMemorySize, GEMM_SMEM);
    cudaFuncSetAttribute(local_attn, cudaFuncAttributeMaxDynamicSharedMemorySize, LA_SMEM);

    __half *xf, *af;
    cudaGetSymbolAddress((void**)&xf, g_x);
    cudaGetSymbolAddress((void**)&af, g_a);

    int n4 = Bb * Ss * Dd / 4;
    to_f16<<<(n4 + 255) / 256, 256>>>(x, xf, n4);                          // 1
    prep_w<<<dim3(24, 24, 6), dim3(32, 8)>>>(w6);                          // 2
    qg_proj<<<dim3(Bb * Gg, 24), 256>>>(x, Wqg, bqg);                      // 3
    mma_gemm<false><<<dim3(3, 128, 5), 256, GEMM_SMEM>>>(xf, b5, nullptr, nullptr); // 4 (profiled)
    local_attn<<<dim3(NBb * 2, Hh, Bb), 128, LA_SMEM>>>(mask);             // 5
    gattn_part<<<dim3(NSPLIT, Hh, Bb), 256, gsm>>>(mask);                  // 6
    gattn_combine<<<Bb * Hh, 32>>>();                                      // 7
    mma_gemm<true><<<dim3(3, 128), 256, GEMM_SMEM>>>(af, b5, bo, out);     // 8
}